// round 1
// baseline (speedup 1.0000x reference)
#include <cuda_runtime.h>
#include <math.h>

#define ALPHA 0.2f
#define NEGV  -9.0e15f

static const int Bq = 8, Nq = 1024, Fq = 256, Oq = 128, Hq = 8;

// ---------------- scratch (static device globals; no allocation) -------------
__device__ float g_h1[(size_t)8 * 8 * 1024 * 128];     // [B,H,N,O] 32MB
__device__ float g_s1[(size_t)8 * 8 * 1024];
__device__ float g_s2[(size_t)8 * 8 * 1024];
__device__ float g_x1[(size_t)8 * 1024 * 1024];        // [B,N,H*O] 32MB
__device__ float g_h2[(size_t)8 * 1024 * 128];         // [B,N,O]
__device__ float g_linp[(size_t)8 * 1024 * 128];
__device__ float g_s1b[(size_t)8 * 1024];
__device__ float g_s2b[(size_t)8 * 1024];
__device__ float g_att2[(size_t)8 * 1024 * 128];
__device__ float g_lin_wT[(size_t)1024 * 128];
__device__ float g_ln_wT[(size_t)128 * 128];

// ---------------- transpose (in[R][C] -> out[C][R]) --------------------------
__global__ void transpose_k(const float* __restrict__ in, float* __restrict__ out,
                            int R, int C) {
    __shared__ float t[32][33];
    int c0 = blockIdx.x * 32, r0 = blockIdx.y * 32;
    int x = threadIdx.x, y = threadIdx.y;
    for (int i = y; i < 32; i += 8) {
        int r = r0 + i, c = c0 + x;
        if (r < R && c < C) t[i][x] = in[(size_t)r * C + c];
    }
    __syncthreads();
    for (int i = y; i < 32; i += 8) {
        int c = c0 + i, r = r0 + x;
        if (c < C && r < R) out[(size_t)c * R + r] = t[x][i];
    }
}

// ---------------- generic fp32 tiled GEMM, BN fixed to 128 -------------------
// MODE 0: per-z batch (z = b*H + h): A = A0 + b*N*F, Bm = B0 + h*F*O, C = C0 + z*N*O
// MODE 1: flat GEMM
// MODE 2: A := A0 + add + biasA (elementwise), epilogue: relu(acc + biasC)
template <int MODE>
__global__ void __launch_bounds__(256)
gemm_k(const float* __restrict__ A0, const float* __restrict__ B0,
       float* __restrict__ C0, const float* __restrict__ add,
       const float* __restrict__ biasA, const float* __restrict__ biasC,
       int M, int K, int lda) {
    const int BM = 64, BN = 128, BK = 32;
    __shared__ float As[BK][BM + 1];     // transposed: As[k][m]
    __shared__ float Bs[BK][BN + 4];

    const float* A;
    const float* Bm;
    float* C;
    if (MODE == 0) {
        int z = blockIdx.z;
        int b = z / Hq, h = z % Hq;
        A = A0 + (size_t)b * Nq * Fq;
        Bm = B0 + (size_t)h * Fq * Oq;
        C = C0 + (size_t)z * Nq * Oq;
    } else {
        A = A0; Bm = B0; C = C0;
    }
    int mblk = blockIdx.x * BM;
    int tid = threadIdx.x;
    int tx = tid % 16, ty = tid / 16;

    float acc[4][8];
#pragma unroll
    for (int r = 0; r < 4; r++)
#pragma unroll
        for (int c = 0; c < 8; c++) acc[r][c] = 0.f;

    for (int k0 = 0; k0 < K; k0 += BK) {
        // A tile: 64x32 = 512 float4, transposed into As[k][m]
#pragma unroll
        for (int q = 0; q < 2; q++) {
            int f = tid + q * 256;
            int m = f >> 3;
            int kk = (f & 7) * 4;
            const float* ap = A + (size_t)(mblk + m) * lda + (k0 + kk);
            float4 v;
            if (MODE == 2) {
                const float* dp = add + (size_t)(mblk + m) * lda + (k0 + kk);
                const float* bp = biasA + (k0 + kk);
                v.x = ap[0] + dp[0] + bp[0];
                v.y = ap[1] + dp[1] + bp[1];
                v.z = ap[2] + dp[2] + bp[2];
                v.w = ap[3] + dp[3] + bp[3];
            } else {
                v = *(const float4*)ap;
            }
            As[kk + 0][m] = v.x;
            As[kk + 1][m] = v.y;
            As[kk + 2][m] = v.z;
            As[kk + 3][m] = v.w;
        }
        // B tile: 32x128 = 1024 float4
#pragma unroll
        for (int q = 0; q < 4; q++) {
            int f = tid + q * 256;
            int kk = f >> 5;
            int nn = (f & 31) * 4;
            *(float4*)&Bs[kk][nn] = *(const float4*)(Bm + (size_t)(k0 + kk) * 128 + nn);
        }
        __syncthreads();
#pragma unroll
        for (int kk = 0; kk < BK; kk++) {
            float a[4];
#pragma unroll
            for (int r = 0; r < 4; r++) a[r] = As[kk][ty * 4 + r];
            float4 b0 = *(const float4*)&Bs[kk][tx * 4];
            float4 b1 = *(const float4*)&Bs[kk][64 + tx * 4];
            float bb[8] = {b0.x, b0.y, b0.z, b0.w, b1.x, b1.y, b1.z, b1.w};
#pragma unroll
            for (int r = 0; r < 4; r++)
#pragma unroll
                for (int c = 0; c < 8; c++) acc[r][c] += a[r] * bb[c];
        }
        __syncthreads();
    }
    // epilogue
#pragma unroll
    for (int r = 0; r < 4; r++) {
        int gm = mblk + ty * 4 + r;
        float* crow = C + (size_t)gm * 128;
        float v[8];
#pragma unroll
        for (int c = 0; c < 8; c++) v[c] = acc[r][c];
        if (MODE == 2) {
#pragma unroll
            for (int c = 0; c < 4; c++) {
                v[c] = v[c] + biasC[tx * 4 + c];
                v[c] = v[c] > 0.f ? v[c] : 0.f;
                v[c + 4] = v[c + 4] + biasC[64 + tx * 4 + c];
                v[c + 4] = v[c + 4] > 0.f ? v[c + 4] : 0.f;
            }
        }
        float4 o0 = make_float4(v[0], v[1], v[2], v[3]);
        float4 o1 = make_float4(v[4], v[5], v[6], v[7]);
        *(float4*)&crow[tx * 4] = o0;
        *(float4*)&crow[64 + tx * 4] = o1;
    }
}

// ---------------- s1/s2 dot kernel ------------------------------------------
// s1[row] = dot(h[row,:], asrc[hidx]); s2[row] = dot(h[row,:], adst[hidx])
__global__ void __launch_bounds__(256)
sdots_k(const float* __restrict__ h, const float* __restrict__ asrc,
        const float* __restrict__ adst, float* __restrict__ s1,
        float* __restrict__ s2, int HH) {
    int row = blockIdx.x * 8 + (threadIdx.x >> 5);
    int lane = threadIdx.x & 31;
    int hidx = (row / Nq) % HH;
    float4 v = ((const float4*)(h + (size_t)row * Oq))[lane];
    float4 a1 = ((const float4*)(asrc + (size_t)hidx * Oq))[lane];
    float4 a2 = ((const float4*)(adst + (size_t)hidx * Oq))[lane];
    float d1 = v.x * a1.x + v.y * a1.y + v.z * a1.z + v.w * a1.w;
    float d2 = v.x * a2.x + v.y * a2.y + v.z * a2.z + v.w * a2.w;
#pragma unroll
    for (int o = 16; o; o >>= 1) {
        d1 += __shfl_xor_sync(0xffffffffu, d1, o);
        d2 += __shfl_xor_sync(0xffffffffu, d2, o);
    }
    if (lane == 0) {
        s1[row] = d1;
        s2[row] = d2;
    }
}

// ---------------- fused masked-softmax attention -----------------------------
// MODE 0: layer-1 (H heads, elu, writes x1[b,n,h*O+o])
// MODE 1: layer-2 (1 head, plain, writes out[b,n,o])
template <int MODE>
__global__ void __launch_bounds__(256)
attn_k(const float* __restrict__ hmat, const float* __restrict__ s1g,
       const float* __restrict__ s2g, const int* __restrict__ adj,
       float* __restrict__ out) {
    const int HH = (MODE == 0) ? Hq : 1;
    int z = blockIdx.z;
    int b = z / HH, h = z % HH;
    int i0 = blockIdx.x * 64;
    const float* hb = hmat + (size_t)z * Nq * Oq;
    const float* s1 = s1g + (size_t)z * Nq;
    const float* s2 = s2g + (size_t)z * Nq;
    const int* adjb = adj + (size_t)b * Nq * Nq;

    __shared__ float s2s[Nq];
    __shared__ float s1s[64];
    __shared__ float ms[64];
    __shared__ float ds[64];
    __shared__ float hs[32][Oq + 4];
    __shared__ float ps[64][33];

    int tid = threadIdx.x;
    for (int i = tid; i < Nq / 4; i += 256) ((float4*)s2s)[i] = ((const float4*)s2)[i];
    if (tid < 64) s1s[tid] = s1[i0 + tid];
    __syncthreads();

    // Phase A: row max (warp per row, 8 rows per warp)
    int warp = tid >> 5, lane = tid & 31;
    for (int rr = 0; rr < 8; rr++) {
        int i = warp * 8 + rr;
        float s1v = s1s[i];
        float mx = -3.4e38f;
        const int* arow = adjb + (size_t)(i0 + i) * Nq;
        for (int j = lane; j < Nq; j += 32) {
            float e = s1v + s2s[j];
            e = e > 0.f ? e : ALPHA * e;
            float logit = arow[j] > 0 ? e : NEGV;
            mx = fmaxf(mx, logit);
        }
#pragma unroll
        for (int o = 16; o; o >>= 1) mx = fmaxf(mx, __shfl_xor_sync(0xffffffffu, mx, o));
        if (lane == 0) ms[i] = mx;
    }
    __syncthreads();

    // Phase B: generate P tile, accumulate denom + output GEMM
    int tx = tid % 16, ty = tid / 16;
    float acc[4][8];
#pragma unroll
    for (int r = 0; r < 4; r++)
#pragma unroll
        for (int c = 0; c < 8; c++) acc[r][c] = 0.f;
    float dloc = 0.f;

    int jl = tid & 31, il0 = tid >> 5;
    for (int j0 = 0; j0 < Nq; j0 += 32) {
        // hs: 32 x 128
#pragma unroll
        for (int q = 0; q < 4; q++) {
            int f = tid + q * 256;
            int jj = f >> 5;
            int oo = (f & 31) * 4;
            *(float4*)&hs[jj][oo] = *(const float4*)(hb + (size_t)(j0 + jj) * Oq + oo);
        }
        // ps: 64 x 32 probability tile
        float s2v = s2s[j0 + jl];
#pragma unroll
        for (int s = 0; s < 8; s++) {
            int i = il0 + s * 8;
            float e = s1s[i] + s2v;
            e = e > 0.f ? e : ALPHA * e;
            int a = adjb[(size_t)(i0 + i) * Nq + j0 + jl];
            float logit = a > 0 ? e : NEGV;
            ps[i][jl] = __expf(logit - ms[i]);
        }
        __syncthreads();
        if (tid < 64) {
            float sg = 0.f;
#pragma unroll
            for (int j = 0; j < 32; j++) sg += ps[tid][j];
            dloc += sg;
        }
#pragma unroll
        for (int kk = 0; kk < 32; kk++) {
            float a[4];
#pragma unroll
            for (int r = 0; r < 4; r++) a[r] = ps[ty * 4 + r][kk];
            float4 b0 = *(const float4*)&hs[kk][tx * 4];
            float4 b1 = *(const float4*)&hs[kk][64 + tx * 4];
            float bb[8] = {b0.x, b0.y, b0.z, b0.w, b1.x, b1.y, b1.z, b1.w};
#pragma unroll
            for (int r = 0; r < 4; r++)
#pragma unroll
                for (int c = 0; c < 8; c++) acc[r][c] += a[r] * bb[c];
        }
        __syncthreads();
    }
    if (tid < 64) ds[tid] = dloc;
    __syncthreads();

    // epilogue
#pragma unroll
    for (int r = 0; r < 4; r++) {
        int i = ty * 4 + r;
        float inv = 1.f / ds[i];
        int gi = i0 + i;
        float v[8];
#pragma unroll
        for (int c = 0; c < 8; c++) v[c] = acc[r][c] * inv;
        if (MODE == 0) {
#pragma unroll
            for (int c = 0; c < 8; c++) v[c] = v[c] > 0.f ? v[c] : expm1f(v[c]);
            float* orow = out + ((size_t)b * Nq + gi) * (Hq * Oq) + h * Oq;
            *(float4*)&orow[tx * 4] = make_float4(v[0], v[1], v[2], v[3]);
            *(float4*)&orow[64 + tx * 4] = make_float4(v[4], v[5], v[6], v[7]);
        } else {
            float* orow = out + ((size_t)b * Nq + gi) * Oq;
            *(float4*)&orow[tx * 4] = make_float4(v[0], v[1], v[2], v[3]);
            *(float4*)&orow[64 + tx * 4] = make_float4(v[4], v[5], v[6], v[7]);
        }
    }
}

// ---------------- launch ------------------------------------------------------
extern "C" void kernel_launch(void* const* d_in, const int* in_sizes, int n_in,
                              void* d_out, int out_size) {
    (void)in_sizes; (void)n_in; (void)out_size;
    const float* inputs = (const float*)d_in[0];
    const int* adj = (const int*)d_in[1];
    const float* W_att = (const float*)d_in[3];
    const float* a_src = (const float*)d_in[4];
    const float* a_dst = (const float*)d_in[5];
    const float* W_out = (const float*)d_in[6];
    const float* ao_src = (const float*)d_in[7];
    const float* ao_dst = (const float*)d_in[8];
    const float* lin_w = (const float*)d_in[9];
    const float* lin_b = (const float*)d_in[10];
    const float* ln_w = (const float*)d_in[11];
    const float* ln_b = (const float*)d_in[12];

    float *p_h1, *p_s1, *p_s2, *p_x1, *p_h2, *p_linp, *p_s1b, *p_s2b, *p_att2,
        *p_lin_wT, *p_ln_wT;
    cudaGetSymbolAddress((void**)&p_h1, g_h1);
    cudaGetSymbolAddress((void**)&p_s1, g_s1);
    cudaGetSymbolAddress((void**)&p_s2, g_s2);
    cudaGetSymbolAddress((void**)&p_x1, g_x1);
    cudaGetSymbolAddress((void**)&p_h2, g_h2);
    cudaGetSymbolAddress((void**)&p_linp, g_linp);
    cudaGetSymbolAddress((void**)&p_s1b, g_s1b);
    cudaGetSymbolAddress((void**)&p_s2b, g_s2b);
    cudaGetSymbolAddress((void**)&p_att2, g_att2);
    cudaGetSymbolAddress((void**)&p_lin_wT, g_lin_wT);
    cudaGetSymbolAddress((void**)&p_ln_wT, g_ln_wT);

    // weight transposes
    transpose_k<<<dim3(32, 4), dim3(32, 8)>>>(lin_w, p_lin_wT, 128, 1024);
    transpose_k<<<dim3(4, 4), dim3(32, 8)>>>(ln_w, p_ln_wT, 128, 128);

    // layer 1: h1[b,h] = x[b] @ W[h]
    gemm_k<0><<<dim3(16, 1, 64), 256>>>(inputs, W_att, p_h1, nullptr, nullptr,
                                        nullptr, Nq, Fq, Fq);
    // s1/s2
    sdots_k<<<(Bq * Hq * Nq) / 8, 256>>>(p_h1, a_src, a_dst, p_s1, p_s2, Hq);
    // fused attention -> x1 (with elu, interleaved heads)
    attn_k<0><<<dim3(16, 1, Bq * Hq), 256>>>(p_h1, p_s1, p_s2, adj, p_x1);

    // layer 2 GEMMs
    gemm_k<1><<<dim3(128, 1, 1), 256>>>(p_x1, W_out, p_h2, nullptr, nullptr,
                                        nullptr, Bq * Nq, Hq * Oq, Hq * Oq);
    gemm_k<1><<<dim3(128, 1, 1), 256>>>(p_x1, p_lin_wT, p_linp, nullptr, nullptr,
                                        nullptr, Bq * Nq, Hq * Oq, Hq * Oq);
    // layer-2 attention scores
    sdots_k<<<(Bq * Nq) / 8, 256>>>(p_h2, ao_src, ao_dst, p_s1b, p_s2b, 1);
    attn_k<1><<<dim3(16, 1, Bq), 256>>>(p_h2, p_s1b, p_s2b, adj, p_att2);

    // final: relu((linp + lin_b + att2) @ ln_wT + ln_b)
    gemm_k<2><<<dim3(128, 1, 1), 256>>>(p_linp, p_ln_wT, (float*)d_out, p_att2,
                                        lin_b, ln_b, Bq * Nq, Oq, Oq);
}

// round 2
// speedup vs baseline: 1.0320x; 1.0320x over previous
#include <cuda_runtime.h>
#include <math.h>

#define ALPHA 0.2f

static const int Bq = 8, Nq = 1024, Fq = 256, Oq = 128, Hq = 8;

typedef unsigned long long u64;

__device__ __forceinline__ u64 fma2(u64 a, u64 b, u64 c) {
    u64 d;
    asm("fma.rn.f32x2 %0, %1, %2, %3;" : "=l"(d) : "l"(a), "l"(b), "l"(c));
    return d;
}
__device__ __forceinline__ u64 splat2(float x) {
    u64 d;
    unsigned u = __float_as_uint(x);
    asm("mov.b64 %0, {%1, %1};" : "=l"(d) : "r"(u));
    return d;
}
__device__ __forceinline__ float2 unpack2(u64 v) {
    unsigned lo, hi;
    asm("mov.b64 {%0, %1}, %2;" : "=r"(lo), "=r"(hi) : "l"(v));
    return make_float2(__uint_as_float(lo), __uint_as_float(hi));
}

// ---------------- scratch (static device globals; no allocation) -------------
__device__ float g_h1[(size_t)8 * 8 * 1024 * 128];     // [B,H,N,O] 32MB
__device__ float g_s1[(size_t)8 * 8 * 1024];
__device__ float g_s2[(size_t)8 * 8 * 1024];
__device__ float g_x1[(size_t)8 * 1024 * 1024];        // [B,N,H*O] 32MB
__device__ float g_h2[(size_t)8 * 1024 * 128];
__device__ float g_linp[(size_t)8 * 1024 * 128];
__device__ float g_s1b[(size_t)8 * 1024];
__device__ float g_s2b[(size_t)8 * 1024];
__device__ float g_att2[(size_t)8 * 1024 * 128];
__device__ float g_lin_wT[(size_t)1024 * 128];
__device__ float g_ln_wT[(size_t)128 * 128];

// ---------------- transpose (in[R][C] -> out[C][R]) --------------------------
__global__ void transpose_k(const float* __restrict__ in, float* __restrict__ out,
                            int R, int C) {
    __shared__ float t[32][33];
    int c0 = blockIdx.x * 32, r0 = blockIdx.y * 32;
    int x = threadIdx.x, y = threadIdx.y;
    for (int i = y; i < 32; i += 8) {
        int r = r0 + i, c = c0 + x;
        if (r < R && c < C) t[i][x] = in[(size_t)r * C + c];
    }
    __syncthreads();
    for (int i = y; i < 32; i += 8) {
        int c = c0 + i, r = r0 + x;
        if (c < C && r < R) out[(size_t)c * R + r] = t[x][i];
    }
}

// ---------------- f32x2 tiled GEMM, BN = 128 ---------------------------------
// MODE 0: per-z batch (z = b*H + h): A = A0 + b*N*F, Bm = B0 + h*F*O, C = C0 + z*N*O
// MODE 1: dual flat GEMM: blockIdx.y selects (B0,C0) or (B1,C1)
// MODE 2: A := A0 + add + biasA (elementwise), epilogue relu(acc + biasC)
template <int MODE, int BM>
__global__ void __launch_bounds__(256)
gemm_k(const float* __restrict__ A0, const float* __restrict__ B0,
       float* __restrict__ C0, const float* __restrict__ B1,
       float* __restrict__ C1, const float* __restrict__ add,
       const float* __restrict__ biasA, const float* __restrict__ biasC,
       int K, int lda) {
    const int BK = 32;
    const int RM = BM / 16;                 // rows per thread
    __shared__ float As[BK][BM + 4];        // transposed: As[k][m]
    __shared__ float Bs[BK][128 + 4];

    const float* A;
    const float* Bm;
    float* C;
    if (MODE == 0) {
        int z = blockIdx.z;
        int b = z / Hq, h = z % Hq;
        A = A0 + (size_t)b * Nq * Fq;
        Bm = B0 + (size_t)h * Fq * Oq;
        C = C0 + (size_t)z * Nq * Oq;
    } else if (MODE == 1) {
        A = A0;
        Bm = blockIdx.y ? B1 : B0;
        C = blockIdx.y ? C1 : C0;
    } else {
        A = A0; Bm = B0; C = C0;
    }
    int mblk = blockIdx.x * BM;
    int tid = threadIdx.x;
    int tx = tid % 16, ty = tid / 16;

    u64 acc[RM][4];
#pragma unroll
    for (int r = 0; r < RM; r++)
#pragma unroll
        for (int c = 0; c < 4; c++) acc[r][c] = 0ull;

    for (int k0 = 0; k0 < K; k0 += BK) {
        // A tile: BM x 32 floats, transposed into As[k][m]
#pragma unroll
        for (int q = 0; q < BM / 32; q++) {
            int f = tid + q * 256;
            int m = f >> 3;
            int kk = (f & 7) * 4;
            const float* ap = A + (size_t)(mblk + m) * lda + (k0 + kk);
            float4 v;
            if (MODE == 2) {
                const float* dp = add + (size_t)(mblk + m) * lda + (k0 + kk);
                const float* bp = biasA + (k0 + kk);
                v.x = ap[0] + dp[0] + bp[0];
                v.y = ap[1] + dp[1] + bp[1];
                v.z = ap[2] + dp[2] + bp[2];
                v.w = ap[3] + dp[3] + bp[3];
            } else {
                v = *(const float4*)ap;
            }
            As[kk + 0][m] = v.x;
            As[kk + 1][m] = v.y;
            As[kk + 2][m] = v.z;
            As[kk + 3][m] = v.w;
        }
        // B tile: 32 x 128
#pragma unroll
        for (int q = 0; q < 4; q++) {
            int f = tid + q * 256;
            int kk = f >> 5;
            int nn = (f & 31) * 4;
            *(float4*)&Bs[kk][nn] = *(const float4*)(Bm + (size_t)(k0 + kk) * 128 + nn);
        }
        __syncthreads();
#pragma unroll 8
        for (int kk = 0; kk < BK; kk++) {
            u64 as_[RM];
#pragma unroll
            for (int rq = 0; rq < RM / 4; rq++) {
                float4 av = *(const float4*)&As[kk][ty * RM + rq * 4];
                as_[rq * 4 + 0] = splat2(av.x);
                as_[rq * 4 + 1] = splat2(av.y);
                as_[rq * 4 + 2] = splat2(av.z);
                as_[rq * 4 + 3] = splat2(av.w);
            }
            ulonglong2 b0 = *(const ulonglong2*)&Bs[kk][tx * 4];
            ulonglong2 b1 = *(const ulonglong2*)&Bs[kk][64 + tx * 4];
            u64 bs_[4] = {b0.x, b0.y, b1.x, b1.y};
#pragma unroll
            for (int r = 0; r < RM; r++)
#pragma unroll
                for (int c = 0; c < 4; c++) acc[r][c] = fma2(as_[r], bs_[c], acc[r][c]);
        }
        __syncthreads();
    }
    // epilogue
#pragma unroll
    for (int r = 0; r < RM; r++) {
        int gm = mblk + ty * RM + r;
        float* crow = C + (size_t)gm * 128;
        float2 p0 = unpack2(acc[r][0]);
        float2 p1 = unpack2(acc[r][1]);
        float2 p2 = unpack2(acc[r][2]);
        float2 p3 = unpack2(acc[r][3]);
        float v[8] = {p0.x, p0.y, p1.x, p1.y, p2.x, p2.y, p3.x, p3.y};
        if (MODE == 2) {
#pragma unroll
            for (int c = 0; c < 4; c++) {
                v[c] = v[c] + biasC[tx * 4 + c];
                v[c] = v[c] > 0.f ? v[c] : 0.f;
                v[c + 4] = v[c + 4] + biasC[64 + tx * 4 + c];
                v[c + 4] = v[c + 4] > 0.f ? v[c + 4] : 0.f;
            }
        }
        *(float4*)&crow[tx * 4] = make_float4(v[0], v[1], v[2], v[3]);
        *(float4*)&crow[64 + tx * 4] = make_float4(v[4], v[5], v[6], v[7]);
    }
}

// ---------------- s1/s2 dot kernel ------------------------------------------
__global__ void __launch_bounds__(256)
sdots_k(const float* __restrict__ h, const float* __restrict__ asrc,
        const float* __restrict__ adst, float* __restrict__ s1,
        float* __restrict__ s2, int HH) {
    int row = blockIdx.x * 8 + (threadIdx.x >> 5);
    int lane = threadIdx.x & 31;
    int hidx = (row / Nq) % HH;
    float4 v = ((const float4*)(h + (size_t)row * Oq))[lane];
    float4 a1 = ((const float4*)(asrc + (size_t)hidx * Oq))[lane];
    float4 a2 = ((const float4*)(adst + (size_t)hidx * Oq))[lane];
    float d1 = v.x * a1.x + v.y * a1.y + v.z * a1.z + v.w * a1.w;
    float d2 = v.x * a2.x + v.y * a2.y + v.z * a2.z + v.w * a2.w;
#pragma unroll
    for (int o = 16; o; o >>= 1) {
        d1 += __shfl_xor_sync(0xffffffffu, d1, o);
        d2 += __shfl_xor_sync(0xffffffffu, d2, o);
    }
    if (lane == 0) {
        s1[row] = d1;
        s2[row] = d2;
    }
}

// ---------------- fused masked-softmax attention (no max pass) ---------------
// p_ij = adj ? exp(lrelu(s1_i+s2_j)) : 0 ; out_i = (sum_j p_ij h_j) / (sum_j p_ij)
// MODE 0: layer-1 (H heads, elu, writes x1[b,n,h*O+o]); MODE 1: layer-2
template <int MODE, int BM>
__global__ void __launch_bounds__(256)
attn_k(const float* __restrict__ hmat, const float* __restrict__ s1g,
       const float* __restrict__ s2g, const int* __restrict__ adj,
       float* __restrict__ out) {
    const int HH = (MODE == 0) ? Hq : 1;
    const int RM = BM / 16;
    const int P = 256 / BM;                 // denom partials per row
    int z = blockIdx.z;
    int b = z / HH, h = z % HH;
    int i0 = blockIdx.x * BM;
    const float* hb = hmat + (size_t)z * Nq * Oq;
    const float* s1 = s1g + (size_t)z * Nq;
    const float* s2 = s2g + (size_t)z * Nq;
    const int* adjb = adj + (size_t)b * Nq * Nq;

    __shared__ float s2s[Nq];
    __shared__ float s1s[BM];
    __shared__ float ds2[BM][4];
    __shared__ float hs[32][Oq + 4];
    __shared__ float psT[32][BM + 1];       // psT[j][i]

    int tid = threadIdx.x;
    ((float4*)s2s)[tid] = ((const float4*)s2)[tid];
    if (tid < BM) s1s[tid] = s1[i0 + tid];
    __syncthreads();

    int tx = tid % 16, ty = tid / 16;
    u64 acc[RM][4];
#pragma unroll
    for (int r = 0; r < RM; r++)
#pragma unroll
        for (int c = 0; c < 4; c++) acc[r][c] = 0ull;
    float dloc = 0.f;

    int jc = tid & 31, irow = tid >> 5;
    int drow = tid & (BM - 1), dpart = tid / BM;
    int jb = dpart * (32 / P);

    for (int j0 = 0; j0 < Nq; j0 += 32) {
        // hs: 32 x 128 value tile
#pragma unroll
        for (int q = 0; q < 4; q++) {
            int f = tid + q * 256;
            int jj = f >> 5;
            int oo = (f & 31) * 4;
            *(float4*)&hs[jj][oo] = *(const float4*)(hb + (size_t)(j0 + jj) * Oq + oo);
        }
        // probability tile psT[j][i]
        float s2v = s2s[j0 + jc];
        const int* acol = adjb + (size_t)i0 * Nq + j0 + jc;
#pragma unroll
        for (int s = 0; s < BM / 8; s++) {
            int i = irow + s * 8;
            float e = s1s[i] + s2v;
            e = e > 0.f ? e : ALPHA * e;
            int a = acol[(size_t)i * Nq];
            psT[jc][i] = a > 0 ? __expf(e) : 0.f;
        }
        __syncthreads();
        // denominator partials
        {
            float sg = 0.f;
#pragma unroll
            for (int jj = 0; jj < 32 / P; jj++) sg += psT[jb + jj][drow];
            dloc += sg;
        }
        // GEMM: acc += psT^T @ hs
#pragma unroll 8
        for (int kk = 0; kk < 32; kk++) {
            u64 as_[RM];
#pragma unroll
            for (int r = 0; r < RM; r++) as_[r] = splat2(psT[kk][ty * RM + r]);
            ulonglong2 b0 = *(const ulonglong2*)&hs[kk][tx * 4];
            ulonglong2 b1 = *(const ulonglong2*)&hs[kk][64 + tx * 4];
            u64 bs_[4] = {b0.x, b0.y, b1.x, b1.y};
#pragma unroll
            for (int r = 0; r < RM; r++)
#pragma unroll
                for (int c = 0; c < 4; c++) acc[r][c] = fma2(as_[r], bs_[c], acc[r][c]);
        }
        __syncthreads();
    }
    ds2[drow][dpart] = dloc;
    __syncthreads();

    // epilogue
#pragma unroll
    for (int r = 0; r < RM; r++) {
        int i = ty * RM + r;
        float den = 0.f;
#pragma unroll
        for (int p = 0; p < P; p++) den += ds2[i][p];
        float inv = 1.f / den;
        int gi = i0 + i;
        float2 p0 = unpack2(acc[r][0]);
        float2 p1 = unpack2(acc[r][1]);
        float2 p2 = unpack2(acc[r][2]);
        float2 p3 = unpack2(acc[r][3]);
        float v[8] = {p0.x, p0.y, p1.x, p1.y, p2.x, p2.y, p3.x, p3.y};
#pragma unroll
        for (int c = 0; c < 8; c++) v[c] *= inv;
        if (MODE == 0) {
#pragma unroll
            for (int c = 0; c < 8; c++) v[c] = v[c] > 0.f ? v[c] : expm1f(v[c]);
            float* orow = out + ((size_t)b * Nq + gi) * (Hq * Oq) + h * Oq;
            *(float4*)&orow[tx * 4] = make_float4(v[0], v[1], v[2], v[3]);
            *(float4*)&orow[64 + tx * 4] = make_float4(v[4], v[5], v[6], v[7]);
        } else {
            float* orow = out + ((size_t)b * Nq + gi) * Oq;
            *(float4*)&orow[tx * 4] = make_float4(v[0], v[1], v[2], v[3]);
            *(float4*)&orow[64 + tx * 4] = make_float4(v[4], v[5], v[6], v[7]);
        }
    }
}

// ---------------- launch ------------------------------------------------------
extern "C" void kernel_launch(void* const* d_in, const int* in_sizes, int n_in,
                              void* d_out, int out_size) {
    (void)in_sizes; (void)n_in; (void)out_size;
    const float* inputs = (const float*)d_in[0];
    const int* adj = (const int*)d_in[1];
    const float* W_att = (const float*)d_in[3];
    const float* a_src = (const float*)d_in[4];
    const float* a_dst = (const float*)d_in[5];
    const float* W_out = (const float*)d_in[6];
    const float* ao_src = (const float*)d_in[7];
    const float* ao_dst = (const float*)d_in[8];
    const float* lin_w = (const float*)d_in[9];
    const float* lin_b = (const float*)d_in[10];
    const float* ln_w = (const float*)d_in[11];
    const float* ln_b = (const float*)d_in[12];

    float *p_h1, *p_s1, *p_s2, *p_x1, *p_h2, *p_linp, *p_s1b, *p_s2b, *p_att2,
        *p_lin_wT, *p_ln_wT;
    cudaGetSymbolAddress((void**)&p_h1, g_h1);
    cudaGetSymbolAddress((void**)&p_s1, g_s1);
    cudaGetSymbolAddress((void**)&p_s2, g_s2);
    cudaGetSymbolAddress((void**)&p_x1, g_x1);
    cudaGetSymbolAddress((void**)&p_h2, g_h2);
    cudaGetSymbolAddress((void**)&p_linp, g_linp);
    cudaGetSymbolAddress((void**)&p_s1b, g_s1b);
    cudaGetSymbolAddress((void**)&p_s2b, g_s2b);
    cudaGetSymbolAddress((void**)&p_att2, g_att2);
    cudaGetSymbolAddress((void**)&p_lin_wT, g_lin_wT);
    cudaGetSymbolAddress((void**)&p_ln_wT, g_ln_wT);

    // weight transposes
    transpose_k<<<dim3(32, 4), dim3(32, 8)>>>(lin_w, p_lin_wT, 128, 1024);
    transpose_k<<<dim3(4, 4), dim3(32, 8)>>>(ln_w, p_ln_wT, 128, 128);

    // layer 1: h1[b,h] = x[b] @ W[h]
    gemm_k<0, 128><<<dim3(8, 1, 64), 256>>>(inputs, W_att, p_h1, nullptr, nullptr,
                                            nullptr, nullptr, nullptr, Fq, Fq);
    // s1/s2
    sdots_k<<<(Bq * Hq * Nq) / 8, 256>>>(p_h1, a_src, a_dst, p_s1, p_s2, Hq);
    // fused attention -> x1 (with elu, interleaved heads)
    attn_k<0, 128><<<dim3(8, 1, Bq * Hq), 256>>>(p_h1, p_s1, p_s2, adj, p_x1);

    // layer 2: dual GEMM (W_out -> h2, lin_wT -> linp)
    gemm_k<1, 128><<<dim3(64, 2, 1), 256>>>(p_x1, W_out, p_h2, p_lin_wT, p_linp,
                                            nullptr, nullptr, nullptr,
                                            Hq * Oq, Hq * Oq);
    // layer-2 attention scores + attention
    sdots_k<<<(Bq * Nq) / 8, 256>>>(p_h2, ao_src, ao_dst, p_s1b, p_s2b, 1);
    attn_k<1, 64><<<dim3(16, 1, Bq), 256>>>(p_h2, p_s1b, p_s2b, adj, p_att2);

    // final: relu((linp + lin_b + att2) @ ln_wT + ln_b)
    gemm_k<2, 64><<<dim3(128, 1, 1), 256>>>(p_linp, p_ln_wT, (float*)d_out,
                                            nullptr, nullptr, p_att2, lin_b,
                                            ln_b, Oq, Oq);
}

// round 3
// speedup vs baseline: 2.0850x; 2.0204x over previous
#include <cuda_runtime.h>
#include <cuda_fp16.h>
#include <math.h>

#define ALPHA 0.2f

static const int Bq = 8, Nq = 1024, Fq = 256, Oq = 128, Hq = 8;

typedef unsigned long long u64;

// ---------------- f32x2 helpers (final fp32 gemm only) -----------------------
__device__ __forceinline__ u64 fma2(u64 a, u64 b, u64 c) {
    u64 d;
    asm("fma.rn.f32x2 %0, %1, %2, %3;" : "=l"(d) : "l"(a), "l"(b), "l"(c));
    return d;
}
__device__ __forceinline__ u64 splat2(float x) {
    u64 d;
    unsigned u = __float_as_uint(x);
    asm("mov.b64 %0, {%1, %1};" : "=l"(d) : "r"(u));
    return d;
}
__device__ __forceinline__ float2 unpack2(u64 v) {
    unsigned lo, hi;
    asm("mov.b64 {%0, %1}, %2;" : "=r"(lo), "=r"(hi) : "l"(v));
    return make_float2(__uint_as_float(lo), __uint_as_float(hi));
}

// ---------------- tensor-core helpers ---------------------------------------
__device__ __forceinline__ void ldsm4(unsigned* r, const void* p) {
    unsigned a = (unsigned)__cvta_generic_to_shared(p);
    asm volatile("ldmatrix.sync.aligned.m8n8.x4.shared.b16 {%0,%1,%2,%3}, [%4];"
                 : "=r"(r[0]), "=r"(r[1]), "=r"(r[2]), "=r"(r[3]) : "r"(a));
}
__device__ __forceinline__ void mma16816(float* d, const unsigned* a,
                                         const unsigned* b, const float* c) {
    asm volatile(
        "mma.sync.aligned.m16n8k16.row.col.f32.f16.f16.f32 "
        "{%0,%1,%2,%3},{%4,%5,%6,%7},{%8,%9},{%10,%11,%12,%13};"
        : "=f"(d[0]), "=f"(d[1]), "=f"(d[2]), "=f"(d[3])
        : "r"(a[0]), "r"(a[1]), "r"(a[2]), "r"(a[3]), "r"(b[0]), "r"(b[1]),
          "f"(c[0]), "f"(c[1]), "f"(c[2]), "f"(c[3]));
}

// ---------------- scratch ----------------------------------------------------
__device__ __half g_in16[(size_t)8192 * 256];
__device__ __half g_wattT[(size_t)8 * 128 * 256];
__device__ __half g_h1T[(size_t)64 * 128 * 1024];     // [z][o][j]
__device__ __half g_x1[(size_t)8192 * 1024];          // [b*N+n][h*O+o]
__device__ __half g_woutT[(size_t)128 * 1024];
__device__ __half g_linw16[(size_t)128 * 1024];
__device__ __half g_h2T[(size_t)8 * 128 * 1024];
__device__ float g_linp[(size_t)8192 * 128];
__device__ float g_att2[(size_t)8192 * 128];
__device__ float g_s1[(size_t)64 * 1024];
__device__ float g_s2[(size_t)64 * 1024];
__device__ float g_s1b[(size_t)8 * 1024];
__device__ float g_s2b[(size_t)8 * 1024];
__device__ float g_ln_wT[(size_t)128 * 128];

// ---------------- prep kernels ----------------------------------------------
__global__ void c2h_k(const float* __restrict__ in, __half* __restrict__ out,
                      int n4) {
    int i = blockIdx.x * 256 + threadIdx.x;
    if (i < n4) {
        float4 v = ((const float4*)in)[i];
        half2 a = __floats2half2_rn(v.x, v.y);
        half2 b = __floats2half2_rn(v.z, v.w);
        uint2 o;
        o.x = *(unsigned*)&a;
        o.y = *(unsigned*)&b;
        *(uint2*)(out + (size_t)i * 4) = o;
    }
}

// in fp32 [z][R][C] -> out fp16 [z][C][R]
__global__ void t2h_k(const float* __restrict__ in, __half* __restrict__ out,
                      int R, int C) {
    __shared__ float t[32][33];
    int z = blockIdx.z;
    in += (size_t)z * R * C;
    out += (size_t)z * R * C;
    int c0 = blockIdx.x * 32, r0 = blockIdx.y * 32;
    int x = threadIdx.x, y = threadIdx.y;
    for (int i = y; i < 32; i += 8) t[i][x] = in[(size_t)(r0 + i) * C + c0 + x];
    __syncthreads();
    for (int i = y; i < 32; i += 8)
        out[(size_t)(c0 + i) * R + r0 + x] = __float2half_rn(t[x][i]);
}

__global__ void transpose_k(const float* __restrict__ in, float* __restrict__ out,
                            int R, int C) {
    __shared__ float t[32][33];
    int c0 = blockIdx.x * 32, r0 = blockIdx.y * 32;
    int x = threadIdx.x, y = threadIdx.y;
    for (int i = y; i < 32; i += 8) {
        int r = r0 + i, c = c0 + x;
        if (r < R && c < C) t[i][x] = in[(size_t)r * C + c];
    }
    __syncthreads();
    for (int i = y; i < 32; i += 8) {
        int c = c0 + i, r = r0 + x;
        if (c < C && r < R) out[(size_t)c * R + r] = t[x][i];
    }
}

// ---------------- tensor GEMM: C = A @ Bt^T ---------------------------------
// MODE 0: h1T[z][o][j] : A=WattT[h] (128x256), Bt=in16[b] j-rows, fp16 out
// MODE 1: h2T[b][o][j] : A=woutT (128x1024), Bt=x1[b] j-rows, fp16 out
// MODE 2: linp[m][o]   : A=x1 m-rows (8192x1024), Bt=linw16 (128x1024), fp32 out
template <int MODE>
__global__ __launch_bounds__(256) void tg_k(const __half* __restrict__ Aroot,
                                            const __half* __restrict__ Btroot,
                                            void* __restrict__ Croot) {
    const int K = (MODE == 0) ? 256 : 1024;
    const int PAD = 72;
    __shared__ __half As[128 * PAD];
    __shared__ __half Bs[128 * PAD];
    int tid = threadIdx.x, bx = blockIdx.x, z = blockIdx.z;

    const __half* A;
    const __half* Bt;
    __half* Ch = nullptr;
    float* Cf = nullptr;
    int lda, ldb, n0 = 0;
    if (MODE == 0) {
        int b = z >> 3, h = z & 7;
        A = Aroot + (size_t)h * 128 * 256;
        lda = 256;
        Bt = Btroot + (size_t)b * 1024 * 256 + (size_t)bx * 128 * 256;
        ldb = 256;
        Ch = (__half*)Croot + (size_t)z * 131072;
        n0 = bx * 128;
    } else if (MODE == 1) {
        A = Aroot;
        lda = 1024;
        Bt = Btroot + (size_t)z * 1048576 + (size_t)bx * 128 * 1024;
        ldb = 1024;
        Ch = (__half*)Croot + (size_t)z * 131072;
        n0 = bx * 128;
    } else {
        A = Aroot + (size_t)bx * 128 * 1024;
        lda = 1024;
        Bt = Btroot;
        ldb = 1024;
        Cf = (float*)Croot + (size_t)bx * 128 * 128;
    }

    int w = tid >> 5, lane = tid & 31;
    int wm = (w & 3) * 32, wn = (w >> 2) * 64;
    int ar = (lane & 7) | (((lane >> 3) & 1) << 3);
    int akh = (lane >> 4) << 3;
    int bn = ((lane >> 4) << 3) | (lane & 7);
    int bkh = ((lane >> 3) & 1) << 3;

    float acc[2][8][4];
#pragma unroll
    for (int mt = 0; mt < 2; mt++)
#pragma unroll
        for (int n8 = 0; n8 < 8; n8++)
#pragma unroll
            for (int e = 0; e < 4; e++) acc[mt][n8][e] = 0.f;

    for (int k0 = 0; k0 < K; k0 += 64) {
#pragma unroll
        for (int q = 0; q < 4; q++) {
            int f = tid + q * 256;
            int row = f >> 3, c8 = f & 7;
            *(uint4*)&As[row * PAD + c8 * 8] =
                *(const uint4*)(A + (size_t)row * lda + k0 + c8 * 8);
            *(uint4*)&Bs[row * PAD + c8 * 8] =
                *(const uint4*)(Bt + (size_t)row * ldb + k0 + c8 * 8);
        }
        __syncthreads();
#pragma unroll
        for (int kk = 0; kk < 64; kk += 16) {
            unsigned af[2][4], bf[4][4];
            ldsm4(af[0], &As[(wm + ar) * PAD + kk + akh]);
            ldsm4(af[1], &As[(wm + 16 + ar) * PAD + kk + akh]);
#pragma unroll
            for (int np = 0; np < 4; np++)
                ldsm4(bf[np], &Bs[(wn + np * 16 + bn) * PAD + kk + bkh]);
#pragma unroll
            for (int mt = 0; mt < 2; mt++)
#pragma unroll
                for (int n8 = 0; n8 < 8; n8++)
                    mma16816(acc[mt][n8], af[mt], &bf[n8 >> 1][(n8 & 1) * 2],
                             acc[mt][n8]);
        }
        __syncthreads();
    }

    int r0 = lane >> 2, cc = (lane & 3) * 2;
#pragma unroll
    for (int mt = 0; mt < 2; mt++)
#pragma unroll
        for (int n8 = 0; n8 < 8; n8++) {
            int row0 = wm + mt * 16 + r0;
            int col = wn + n8 * 8 + cc;
            if (MODE <= 1) {
                half2 lo = __floats2half2_rn(acc[mt][n8][0], acc[mt][n8][1]);
                half2 hi = __floats2half2_rn(acc[mt][n8][2], acc[mt][n8][3]);
                *(half2*)&Ch[(size_t)row0 * 1024 + n0 + col] = lo;
                *(half2*)&Ch[(size_t)(row0 + 8) * 1024 + n0 + col] = hi;
            } else {
                *(float2*)&Cf[(size_t)row0 * 128 + col] =
                    make_float2(acc[mt][n8][0], acc[mt][n8][1]);
                *(float2*)&Cf[(size_t)(row0 + 8) * 128 + col] =
                    make_float2(acc[mt][n8][2], acc[mt][n8][3]);
            }
        }
}

// ---------------- s1/s2 from transposed fp16 h -------------------------------
__global__ __launch_bounds__(256) void sdots_t(const __half* __restrict__ hT,
                                               const float* __restrict__ asrc,
                                               const float* __restrict__ adst,
                                               float* __restrict__ s1,
                                               float* __restrict__ s2, int hh) {
    __shared__ float a1s[128], a2s[128];
    int z = blockIdx.x, tid = threadIdx.x;
    int hidx = z % hh;
    if (tid < 128) a1s[tid] = asrc[hidx * 128 + tid];
    else a2s[tid - 128] = adst[hidx * 128 + tid - 128];
    __syncthreads();
    const __half* hz = hT + (size_t)z * 131072;
    int j0 = tid * 4;
    float A1[4] = {0.f, 0.f, 0.f, 0.f}, A2[4] = {0.f, 0.f, 0.f, 0.f};
    for (int o = 0; o < 128; o++) {
        float v1 = a1s[o], v2 = a2s[o];
        uint2 raw = *(const uint2*)(hz + (size_t)o * 1024 + j0);
        half2 h0 = *(half2*)&raw.x;
        half2 h1 = *(half2*)&raw.y;
        float2 f0 = __half22float2(h0), f1 = __half22float2(h1);
        A1[0] += v1 * f0.x; A1[1] += v1 * f0.y;
        A1[2] += v1 * f1.x; A1[3] += v1 * f1.y;
        A2[0] += v2 * f0.x; A2[1] += v2 * f0.y;
        A2[2] += v2 * f1.x; A2[3] += v2 * f1.y;
    }
    *(float4*)&s1[(size_t)z * 1024 + j0] = make_float4(A1[0], A1[1], A1[2], A1[3]);
    *(float4*)&s2[(size_t)z * 1024 + j0] = make_float4(A2[0], A2[1], A2[2], A2[3]);
}

// ---------------- tensor-core fused attention --------------------------------
// p = adj ? exp(lrelu(s1_i+s2_j) - 8) : 0 ; out_i = (sum_j p h_j) / (sum_j p)
// MODE 0: layer-1 (writes x1 fp16 with elu); MODE 1: layer-2 (att2 fp32)
template <int MODE>
__global__ __launch_bounds__(256) void at_k(const __half* __restrict__ hT,
                                            const float* __restrict__ s1g,
                                            const float* __restrict__ s2g,
                                            const int* __restrict__ adj,
                                            void* __restrict__ outp) {
    const int PAD = 56;
    __shared__ __half Ps[128 * PAD];
    __shared__ __half Vs[128 * PAD];
    __shared__ float s2s[1024], s1s[128], ds[128];
    int tid = threadIdx.x, bx = blockIdx.x, z = blockIdx.z;
    int b, h;
    if (MODE == 0) { b = z >> 3; h = z & 7; }
    else { b = z; h = 0; }
    int i0 = bx * 128;
    const __half* hz = hT + (size_t)z * 131072;
    const float* s1 = s1g + (size_t)z * 1024;
    const float* s2 = s2g + (size_t)z * 1024;
    const int* adjb = adj + (size_t)b * 1024 * 1024;

    ((float4*)s2s)[tid] = ((const float4*)s2)[tid];
    if (tid < 128) s1s[tid] = s1[i0 + tid];
    __syncthreads();

    int w = tid >> 5, lane = tid & 31;
    int wm = (w & 3) * 32, wn = (w >> 2) * 64;
    int ar = (lane & 7) | (((lane >> 3) & 1) << 3);
    int akh = (lane >> 4) << 3;
    int bn = ((lane >> 4) << 3) | (lane & 7);
    int bkh = ((lane >> 3) & 1) << 3;

    float acc[2][8][4];
#pragma unroll
    for (int mt = 0; mt < 2; mt++)
#pragma unroll
        for (int n8 = 0; n8 < 8; n8++)
#pragma unroll
            for (int e = 0; e < 4; e++) acc[mt][n8][e] = 0.f;
    float dl[16];
#pragma unroll
    for (int s = 0; s < 16; s++) dl[s] = 0.f;

    for (int j0 = 0; j0 < 1024; j0 += 32) {
        // V tile: Vs[o][jj] from hT (already transposed)
#pragma unroll
        for (int q = 0; q < 2; q++) {
            int f = tid + q * 256;
            int row = f >> 2, c = f & 3;
            *(uint4*)&Vs[row * PAD + c * 8] =
                *(const uint4*)(hz + (size_t)row * 1024 + j0 + c * 8);
        }
        // P tile (fp16) + denom accumulation
        float s2v = s2s[j0 + lane];
        const int* acol = adjb + (size_t)(i0 + w) * 1024 + j0 + lane;
#pragma unroll
        for (int s = 0; s < 16; s++) {
            int i = w + s * 8;
            float e = s1s[i] + s2v;
            e = e > 0.f ? e : ALPHA * e;
            int a = acol[(size_t)s * 8 * 1024];
            float p = a > 0 ? __expf(e - 8.f) : 0.f;
            Ps[i * PAD + lane] = __float2half_rn(p);
            dl[s] += p;
        }
        __syncthreads();
#pragma unroll
        for (int kk = 0; kk < 32; kk += 16) {
            unsigned af[2][4], bf[4][4];
            ldsm4(af[0], &Ps[(wm + ar) * PAD + kk + akh]);
            ldsm4(af[1], &Ps[(wm + 16 + ar) * PAD + kk + akh]);
#pragma unroll
            for (int np = 0; np < 4; np++)
                ldsm4(bf[np], &Vs[(wn + np * 16 + bn) * PAD + kk + bkh]);
#pragma unroll
            for (int mt = 0; mt < 2; mt++)
#pragma unroll
                for (int n8 = 0; n8 < 8; n8++)
                    mma16816(acc[mt][n8], af[mt], &bf[n8 >> 1][(n8 & 1) * 2],
                             acc[mt][n8]);
        }
        __syncthreads();
    }

    // denominator reduce (lanes hold disjoint j)
#pragma unroll
    for (int s = 0; s < 16; s++) {
        float v = dl[s];
#pragma unroll
        for (int o = 16; o; o >>= 1) v += __shfl_xor_sync(0xffffffffu, v, o);
        if (lane == 0) ds[s * 8 + w] = v;
    }
    __syncthreads();

    int r0 = lane >> 2, cc = (lane & 3) * 2;
#pragma unroll
    for (int mt = 0; mt < 2; mt++)
#pragma unroll
        for (int n8 = 0; n8 < 8; n8++) {
            int row0 = wm + mt * 16 + r0, row1 = row0 + 8;
            int col = wn + n8 * 8 + cc;
            float inv0 = 1.f / ds[row0], inv1 = 1.f / ds[row1];
            float f0 = acc[mt][n8][0] * inv0, f1 = acc[mt][n8][1] * inv0;
            float f2 = acc[mt][n8][2] * inv1, f3 = acc[mt][n8][3] * inv1;
            if (MODE == 0) {
                f0 = f0 > 0.f ? f0 : expm1f(f0);
                f1 = f1 > 0.f ? f1 : expm1f(f1);
                f2 = f2 > 0.f ? f2 : expm1f(f2);
                f3 = f3 > 0.f ? f3 : expm1f(f3);
                __half* x1 = (__half*)outp;
                *(half2*)&x1[((size_t)b * 1024 + i0 + row0) * 1024 + h * 128 + col] =
                    __floats2half2_rn(f0, f1);
                *(half2*)&x1[((size_t)b * 1024 + i0 + row1) * 1024 + h * 128 + col] =
                    __floats2half2_rn(f2, f3);
            } else {
                float* o2 = (float*)outp;
                *(float2*)&o2[((size_t)b * 1024 + i0 + row0) * 128 + col] =
                    make_float2(f0, f1);
                *(float2*)&o2[((size_t)b * 1024 + i0 + row1) * 128 + col] =
                    make_float2(f2, f3);
            }
        }
}

// ---------------- final fp32 gemm: relu((linp+att2+lin_b) @ ln_wT + ln_b) ----
__global__ void __launch_bounds__(256)
final_k(const float* __restrict__ A0, const float* __restrict__ B0,
        float* __restrict__ C0, const float* __restrict__ add,
        const float* __restrict__ biasA, const float* __restrict__ biasC) {
    const int BK = 32, BM = 64, RM = 4;
    __shared__ float As[BK][BM + 4];
    __shared__ float Bs[BK][128 + 4];
    int mblk = blockIdx.x * BM;
    int tid = threadIdx.x;
    int tx = tid % 16, ty = tid / 16;
    u64 acc[RM][4];
#pragma unroll
    for (int r = 0; r < RM; r++)
#pragma unroll
        for (int c = 0; c < 4; c++) acc[r][c] = 0ull;

    for (int k0 = 0; k0 < 128; k0 += BK) {
#pragma unroll
        for (int q = 0; q < BM / 32; q++) {
            int f = tid + q * 256;
            int m = f >> 3;
            int kk = (f & 7) * 4;
            const float* ap = A0 + (size_t)(mblk + m) * 128 + (k0 + kk);
            const float* dp = add + (size_t)(mblk + m) * 128 + (k0 + kk);
            const float* bp = biasA + (k0 + kk);
            float4 v;
            v.x = ap[0] + dp[0] + bp[0];
            v.y = ap[1] + dp[1] + bp[1];
            v.z = ap[2] + dp[2] + bp[2];
            v.w = ap[3] + dp[3] + bp[3];
            As[kk + 0][m] = v.x;
            As[kk + 1][m] = v.y;
            As[kk + 2][m] = v.z;
            As[kk + 3][m] = v.w;
        }
#pragma unroll
        for (int q = 0; q < 4; q++) {
            int f = tid + q * 256;
            int kk = f >> 5;
            int nn = (f & 31) * 4;
            *(float4*)&Bs[kk][nn] = *(const float4*)(B0 + (size_t)(k0 + kk) * 128 + nn);
        }
        __syncthreads();
#pragma unroll 8
        for (int kk = 0; kk < BK; kk++) {
            u64 as_[RM];
            float4 av = *(const float4*)&As[kk][ty * RM];
            as_[0] = splat2(av.x);
            as_[1] = splat2(av.y);
            as_[2] = splat2(av.z);
            as_[3] = splat2(av.w);
            ulonglong2 b0 = *(const ulonglong2*)&Bs[kk][tx * 4];
            ulonglong2 b1 = *(const ulonglong2*)&Bs[kk][64 + tx * 4];
            u64 bs_[4] = {b0.x, b0.y, b1.x, b1.y};
#pragma unroll
            for (int r = 0; r < RM; r++)
#pragma unroll
                for (int c = 0; c < 4; c++) acc[r][c] = fma2(as_[r], bs_[c], acc[r][c]);
        }
        __syncthreads();
    }
#pragma unroll
    for (int r = 0; r < RM; r++) {
        int gm = mblk + ty * RM + r;
        float* crow = C0 + (size_t)gm * 128;
        float2 p0 = unpack2(acc[r][0]);
        float2 p1 = unpack2(acc[r][1]);
        float2 p2 = unpack2(acc[r][2]);
        float2 p3 = unpack2(acc[r][3]);
        float v[8] = {p0.x, p0.y, p1.x, p1.y, p2.x, p2.y, p3.x, p3.y};
#pragma unroll
        for (int c = 0; c < 4; c++) {
            v[c] = v[c] + biasC[tx * 4 + c];
            v[c] = v[c] > 0.f ? v[c] : 0.f;
            v[c + 4] = v[c + 4] + biasC[64 + tx * 4 + c];
            v[c + 4] = v[c + 4] > 0.f ? v[c + 4] : 0.f;
        }
        *(float4*)&crow[tx * 4] = make_float4(v[0], v[1], v[2], v[3]);
        *(float4*)&crow[64 + tx * 4] = make_float4(v[4], v[5], v[6], v[7]);
    }
}

// ---------------- launch ------------------------------------------------------
extern "C" void kernel_launch(void* const* d_in, const int* in_sizes, int n_in,
                              void* d_out, int out_size) {
    (void)in_sizes; (void)n_in; (void)out_size;
    const float* inputs = (const float*)d_in[0];
    const int* adj = (const int*)d_in[1];
    const float* W_att = (const float*)d_in[3];
    const float* a_src = (const float*)d_in[4];
    const float* a_dst = (const float*)d_in[5];
    const float* W_out = (const float*)d_in[6];
    const float* ao_src = (const float*)d_in[7];
    const float* ao_dst = (const float*)d_in[8];
    const float* lin_w = (const float*)d_in[9];
    const float* lin_b = (const float*)d_in[10];
    const float* ln_w = (const float*)d_in[11];
    const float* ln_b = (const float*)d_in[12];

    __half *p_in16, *p_wattT, *p_h1T, *p_x1, *p_woutT, *p_linw16, *p_h2T;
    float *p_linp, *p_att2, *p_s1, *p_s2, *p_s1b, *p_s2b, *p_ln_wT;
    cudaGetSymbolAddress((void**)&p_in16, g_in16);
    cudaGetSymbolAddress((void**)&p_wattT, g_wattT);
    cudaGetSymbolAddress((void**)&p_h1T, g_h1T);
    cudaGetSymbolAddress((void**)&p_x1, g_x1);
    cudaGetSymbolAddress((void**)&p_woutT, g_woutT);
    cudaGetSymbolAddress((void**)&p_linw16, g_linw16);
    cudaGetSymbolAddress((void**)&p_h2T, g_h2T);
    cudaGetSymbolAddress((void**)&p_linp, g_linp);
    cudaGetSymbolAddress((void**)&p_att2, g_att2);
    cudaGetSymbolAddress((void**)&p_s1, g_s1);
    cudaGetSymbolAddress((void**)&p_s2, g_s2);
    cudaGetSymbolAddress((void**)&p_s1b, g_s1b);
    cudaGetSymbolAddress((void**)&p_s2b, g_s2b);
    cudaGetSymbolAddress((void**)&p_ln_wT, g_ln_wT);

    // prep: conversions + transposes
    c2h_k<<<2048, 256>>>(inputs, p_in16, 2097152 / 4);
    c2h_k<<<128, 256>>>(lin_w, p_linw16, 131072 / 4);
    t2h_k<<<dim3(4, 8, 8), dim3(32, 8)>>>(W_att, p_wattT, 256, 128);
    t2h_k<<<dim3(4, 32, 1), dim3(32, 8)>>>(W_out, p_woutT, 1024, 128);
    transpose_k<<<dim3(4, 4), dim3(32, 8)>>>(ln_w, p_ln_wT, 128, 128);

    // layer 1: h1T[z][o][j] = W[h]^T @ x[b]^T
    tg_k<0><<<dim3(8, 1, 64), 256>>>(p_wattT, p_in16, p_h1T);
    sdots_t<<<64, 256>>>(p_h1T, a_src, a_dst, p_s1, p_s2, Hq);
    at_k<0><<<dim3(8, 1, 64), 256>>>(p_h1T, p_s1, p_s2, adj, p_x1);

    // layer 2
    tg_k<1><<<dim3(8, 1, 8), 256>>>(p_woutT, p_x1, p_h2T);
    tg_k<2><<<dim3(64, 1, 1), 256>>>(p_x1, p_linw16, p_linp);
    sdots_t<<<8, 256>>>(p_h2T, ao_src, ao_dst, p_s1b, p_s2b, 1);
    at_k<1><<<dim3(8, 1, 8), 256>>>(p_h2T, p_s1b, p_s2b, adj, p_att2);

    // final
    final_k<<<128, 256>>>(p_linp, p_ln_wT, (float*)d_out, p_att2, lin_b, ln_b);
}

// round 4
// speedup vs baseline: 2.6997x; 1.2948x over previous
#include <cuda_runtime.h>
#include <cuda_fp16.h>
#include <math.h>

#define ALPHA 0.2f

static const int Bq = 8, Nq = 1024, Fq = 256, Oq = 128, Hq = 8;

typedef unsigned long long u64;

// ---------------- f32x2 helpers (final fp32 gemm only) -----------------------
__device__ __forceinline__ u64 fma2(u64 a, u64 b, u64 c) {
    u64 d;
    asm("fma.rn.f32x2 %0, %1, %2, %3;" : "=l"(d) : "l"(a), "l"(b), "l"(c));
    return d;
}
__device__ __forceinline__ u64 splat2(float x) {
    u64 d;
    unsigned u = __float_as_uint(x);
    asm("mov.b64 %0, {%1, %1};" : "=l"(d) : "r"(u));
    return d;
}
__device__ __forceinline__ float2 unpack2(u64 v) {
    unsigned lo, hi;
    asm("mov.b64 {%0, %1}, %2;" : "=r"(lo), "=r"(hi) : "l"(v));
    return make_float2(__uint_as_float(lo), __uint_as_float(hi));
}

// ---------------- tensor-core helpers ---------------------------------------
__device__ __forceinline__ void ldsm4(unsigned* r, const void* p) {
    unsigned a = (unsigned)__cvta_generic_to_shared(p);
    asm volatile("ldmatrix.sync.aligned.m8n8.x4.shared.b16 {%0,%1,%2,%3}, [%4];"
                 : "=r"(r[0]), "=r"(r[1]), "=r"(r[2]), "=r"(r[3]) : "r"(a));
}
__device__ __forceinline__ void mma16816(float* d, const unsigned* a,
                                         const unsigned* b, const float* c) {
    asm volatile(
        "mma.sync.aligned.m16n8k16.row.col.f32.f16.f16.f32 "
        "{%0,%1,%2,%3},{%4,%5,%6,%7},{%8,%9},{%10,%11,%12,%13};"
        : "=f"(d[0]), "=f"(d[1]), "=f"(d[2]), "=f"(d[3])
        : "r"(a[0]), "r"(a[1]), "r"(a[2]), "r"(a[3]), "r"(b[0]), "r"(b[1]),
          "f"(c[0]), "f"(c[1]), "f"(c[2]), "f"(c[3]));
}
__device__ __forceinline__ void cpa16(void* smem_dst, const void* gsrc) {
    unsigned a = (unsigned)__cvta_generic_to_shared(smem_dst);
    asm volatile("cp.async.ca.shared.global [%0], [%1], 16;" :: "r"(a), "l"(gsrc));
}
__device__ __forceinline__ void cpa_commit() {
    asm volatile("cp.async.commit_group;" ::: "memory");
}
__device__ __forceinline__ void cpa_wait0() {
    asm volatile("cp.async.wait_group 0;" ::: "memory");
}

// ---------------- scratch ----------------------------------------------------
__device__ __half g_in16[(size_t)8192 * 256];
__device__ __half g_wattT[(size_t)8 * 128 * 256];
__device__ __half g_h1T[(size_t)64 * 128 * 1024];     // [z][o][j]
__device__ __half g_x1[(size_t)8192 * 1024];          // [b*N+n][h*O+o]
__device__ __half g_woutT[(size_t)128 * 1024];
__device__ __half g_linw16[(size_t)128 * 1024];
__device__ __half g_h2T[(size_t)8 * 128 * 1024];
__device__ float g_linp[(size_t)8192 * 128];
__device__ float g_att2[(size_t)8192 * 128];
__device__ float g_s1[(size_t)64 * 1024];
__device__ float g_s2[(size_t)64 * 1024];
__device__ float g_s1b[(size_t)8 * 1024];
__device__ float g_s2b[(size_t)8 * 1024];
__device__ float g_ln_wT[(size_t)128 * 128];

// ---------------- prep kernels ----------------------------------------------
__global__ void c2h_k(const float* __restrict__ in, __half* __restrict__ out,
                      int n4) {
    int i = blockIdx.x * 256 + threadIdx.x;
    if (i < n4) {
        float4 v = ((const float4*)in)[i];
        half2 a = __floats2half2_rn(v.x, v.y);
        half2 b = __floats2half2_rn(v.z, v.w);
        uint2 o;
        o.x = *(unsigned*)&a;
        o.y = *(unsigned*)&b;
        *(uint2*)(out + (size_t)i * 4) = o;
    }
}

// in fp32 [z][R][C] -> out fp16 [z][C][R]
__global__ void t2h_k(const float* __restrict__ in, __half* __restrict__ out,
                      int R, int C) {
    __shared__ float t[32][33];
    int z = blockIdx.z;
    in += (size_t)z * R * C;
    out += (size_t)z * R * C;
    int c0 = blockIdx.x * 32, r0 = blockIdx.y * 32;
    int x = threadIdx.x, y = threadIdx.y;
    for (int i = y; i < 32; i += 8) t[i][x] = in[(size_t)(r0 + i) * C + c0 + x];
    __syncthreads();
    for (int i = y; i < 32; i += 8)
        out[(size_t)(c0 + i) * R + r0 + x] = __float2half_rn(t[x][i]);
}

__global__ void transpose_k(const float* __restrict__ in, float* __restrict__ out,
                            int R, int C) {
    __shared__ float t[32][33];
    int c0 = blockIdx.x * 32, r0 = blockIdx.y * 32;
    int x = threadIdx.x, y = threadIdx.y;
    for (int i = y; i < 32; i += 8) {
        int r = r0 + i, c = c0 + x;
        if (r < R && c < C) t[i][x] = in[(size_t)r * C + c];
    }
    __syncthreads();
    for (int i = y; i < 32; i += 8) {
        int c = c0 + i, r = r0 + x;
        if (c < C && r < R) out[(size_t)c * R + r] = t[x][i];
    }
}

// ---------------- tensor GEMM: C = A @ Bt^T ---------------------------------
template <int MODE>
__global__ __launch_bounds__(256) void tg_k(const __half* __restrict__ Aroot,
                                            const __half* __restrict__ Btroot,
                                            void* __restrict__ Croot) {
    const int K = (MODE == 0) ? 256 : 1024;
    const int PAD = 72;
    __shared__ __half As[128 * PAD];
    __shared__ __half Bs[128 * PAD];
    int tid = threadIdx.x, bx = blockIdx.x, z = blockIdx.z;

    const __half* A;
    const __half* Bt;
    __half* Ch = nullptr;
    float* Cf = nullptr;
    int lda, ldb, n0 = 0;
    if (MODE == 0) {
        int b = z >> 3, h = z & 7;
        A = Aroot + (size_t)h * 128 * 256;
        lda = 256;
        Bt = Btroot + (size_t)b * 1024 * 256 + (size_t)bx * 128 * 256;
        ldb = 256;
        Ch = (__half*)Croot + (size_t)z * 131072;
        n0 = bx * 128;
    } else if (MODE == 1) {
        A = Aroot;
        lda = 1024;
        Bt = Btroot + (size_t)z * 1048576 + (size_t)bx * 128 * 1024;
        ldb = 1024;
        Ch = (__half*)Croot + (size_t)z * 131072;
        n0 = bx * 128;
    } else {
        A = Aroot + (size_t)bx * 128 * 1024;
        lda = 1024;
        Bt = Btroot;
        ldb = 1024;
        Cf = (float*)Croot + (size_t)bx * 128 * 128;
    }

    int w = tid >> 5, lane = tid & 31;
    int wm = (w & 3) * 32, wn = (w >> 2) * 64;
    int ar = (lane & 7) | (((lane >> 3) & 1) << 3);
    int akh = (lane >> 4) << 3;
    int bn = ((lane >> 4) << 3) | (lane & 7);
    int bkh = ((lane >> 3) & 1) << 3;

    float acc[2][8][4];
#pragma unroll
    for (int mt = 0; mt < 2; mt++)
#pragma unroll
        for (int n8 = 0; n8 < 8; n8++)
#pragma unroll
            for (int e = 0; e < 4; e++) acc[mt][n8][e] = 0.f;

    for (int k0 = 0; k0 < K; k0 += 64) {
#pragma unroll
        for (int q = 0; q < 4; q++) {
            int f = tid + q * 256;
            int row = f >> 3, c8 = f & 7;
            *(uint4*)&As[row * PAD + c8 * 8] =
                *(const uint4*)(A + (size_t)row * lda + k0 + c8 * 8);
            *(uint4*)&Bs[row * PAD + c8 * 8] =
                *(const uint4*)(Bt + (size_t)row * ldb + k0 + c8 * 8);
        }
        __syncthreads();
#pragma unroll
        for (int kk = 0; kk < 64; kk += 16) {
            unsigned af[2][4], bf[4][4];
            ldsm4(af[0], &As[(wm + ar) * PAD + kk + akh]);
            ldsm4(af[1], &As[(wm + 16 + ar) * PAD + kk + akh]);
#pragma unroll
            for (int np = 0; np < 4; np++)
                ldsm4(bf[np], &Bs[(wn + np * 16 + bn) * PAD + kk + bkh]);
#pragma unroll
            for (int mt = 0; mt < 2; mt++)
#pragma unroll
                for (int n8 = 0; n8 < 8; n8++)
                    mma16816(acc[mt][n8], af[mt], &bf[n8 >> 1][(n8 & 1) * 2],
                             acc[mt][n8]);
        }
        __syncthreads();
    }

    int r0 = lane >> 2, cc = (lane & 3) * 2;
#pragma unroll
    for (int mt = 0; mt < 2; mt++)
#pragma unroll
        for (int n8 = 0; n8 < 8; n8++) {
            int row0 = wm + mt * 16 + r0;
            int col = wn + n8 * 8 + cc;
            if (MODE <= 1) {
                half2 lo = __floats2half2_rn(acc[mt][n8][0], acc[mt][n8][1]);
                half2 hi = __floats2half2_rn(acc[mt][n8][2], acc[mt][n8][3]);
                *(half2*)&Ch[(size_t)row0 * 1024 + n0 + col] = lo;
                *(half2*)&Ch[(size_t)(row0 + 8) * 1024 + n0 + col] = hi;
            } else {
                *(float2*)&Cf[(size_t)row0 * 128 + col] =
                    make_float2(acc[mt][n8][0], acc[mt][n8][1]);
                *(float2*)&Cf[(size_t)(row0 + 8) * 128 + col] =
                    make_float2(acc[mt][n8][2], acc[mt][n8][3]);
            }
        }
}

// ---------------- s1/s2 from transposed fp16 h -------------------------------
__global__ __launch_bounds__(256) void sdots_t(const __half* __restrict__ hT,
                                               const float* __restrict__ asrc,
                                               const float* __restrict__ adst,
                                               float* __restrict__ s1,
                                               float* __restrict__ s2, int hh) {
    __shared__ float a1s[128], a2s[128];
    int z = blockIdx.x, tid = threadIdx.x;
    int hidx = z % hh;
    if (tid < 128) a1s[tid] = asrc[hidx * 128 + tid];
    else a2s[tid - 128] = adst[hidx * 128 + tid - 128];
    __syncthreads();
    const __half* hz = hT + (size_t)z * 131072;
    int j0 = tid * 4;
    float A1[4] = {0.f, 0.f, 0.f, 0.f}, A2[4] = {0.f, 0.f, 0.f, 0.f};
    for (int o = 0; o < 128; o++) {
        float v1 = a1s[o], v2 = a2s[o];
        uint2 raw = *(const uint2*)(hz + (size_t)o * 1024 + j0);
        half2 h0 = *(half2*)&raw.x;
        half2 h1 = *(half2*)&raw.y;
        float2 f0 = __half22float2(h0), f1 = __half22float2(h1);
        A1[0] += v1 * f0.x; A1[1] += v1 * f0.y;
        A1[2] += v1 * f1.x; A1[3] += v1 * f1.y;
        A2[0] += v2 * f0.x; A2[1] += v2 * f0.y;
        A2[2] += v2 * f1.x; A2[3] += v2 * f1.y;
    }
    *(float4*)&s1[(size_t)z * 1024 + j0] = make_float4(A1[0], A1[1], A1[2], A1[3]);
    *(float4*)&s2[(size_t)z * 1024 + j0] = make_float4(A2[0], A2[1], A2[2], A2[3]);
}

// ---------------- pipelined tensor-core fused attention ----------------------
// p = adj ? exp(lrelu(s1_i+s2_j) - 8) : 0 ; out_i = (sum_j p h_j) / (sum_j p)
// j-tile 64, double-buffered P and V, cp.async for V, 1 sync per tile.
#define APAD 72
template <int MODE>
__global__ __launch_bounds__(256) void at_k(const __half* __restrict__ hT,
                                            const float* __restrict__ s1g,
                                            const float* __restrict__ s2g,
                                            const int* __restrict__ adj,
                                            void* __restrict__ outp) {
    extern __shared__ char smraw[];
    __half* Ps = (__half*)smraw;                       // 2 * 128*APAD
    __half* Vs = Ps + 2 * 128 * APAD;                  // 2 * 128*APAD
    float* s1s = (float*)(Vs + 2 * 128 * APAD);        // 128
    float* ds = s1s + 128;                             // 128
    float* s2s = ds + 128;                             // 1024

    int tid = threadIdx.x, bx = blockIdx.x, z = blockIdx.z;
    int b, h;
    if (MODE == 0) { b = z >> 3; h = z & 7; }
    else { b = z; h = 0; }
    int i0 = bx * 128;
    const __half* hz = hT + (size_t)z * 131072;
    const float* s1 = s1g + (size_t)z * 1024;
    const float* s2 = s2g + (size_t)z * 1024;
    const int* adjb = adj + (size_t)b * 1024 * 1024;

    ((float4*)s2s)[tid] = ((const float4*)s2)[tid];
    if (tid < 128) s1s[tid] = s1[i0 + tid];
    __syncthreads();

    int w = tid >> 5, lane = tid & 31;
    int wm = (w & 3) * 32, wn = (w >> 2) * 64;
    int ar = (lane & 7) | (((lane >> 3) & 1) << 3);
    int akh = (lane >> 4) << 3;
    int bn = ((lane >> 4) << 3) | (lane & 7);
    int bkh = ((lane >> 3) & 1) << 3;

    float acc[2][8][4];
#pragma unroll
    for (int mt = 0; mt < 2; mt++)
#pragma unroll
        for (int n8 = 0; n8 < 8; n8++)
#pragma unroll
            for (int e = 0; e < 4; e++) acc[mt][n8][e] = 0.f;
    float dl[16];
#pragma unroll
    for (int s = 0; s < 16; s++) dl[s] = 0.f;

    // ---- helpers as lambdas ----
    auto issueV = [&](int buf, int j0) {
        __half* vb = Vs + buf * 128 * APAD;
#pragma unroll
        for (int q = 0; q < 4; q++) {
            int f = tid + q * 256;
            int row = f >> 3, c8 = f & 7;
            cpa16(&vb[row * APAD + c8 * 8],
                  hz + (size_t)row * 1024 + j0 + c8 * 8);
        }
        cpa_commit();
    };
    auto buildP = [&](int buf, int j0) {
        __half* pb = Ps + buf * 128 * APAD;
        float s2a = s2s[j0 + 2 * lane];
        float s2b = s2s[j0 + 2 * lane + 1];
        const int* ap = adjb + (size_t)(i0 + w) * 1024 + j0 + 2 * lane;
#pragma unroll
        for (int s = 0; s < 16; s++) {
            int i = w + s * 8;
            int2 a = *(const int2*)(ap + (size_t)s * 8 * 1024);
            float e1 = s1s[i] + s2a;
            e1 = e1 > 0.f ? e1 : ALPHA * e1;
            float e2 = s1s[i] + s2b;
            e2 = e2 > 0.f ? e2 : ALPHA * e2;
            float p1 = a.x > 0 ? __expf(e1 - 8.f) : 0.f;
            float p2 = a.y > 0 ? __expf(e2 - 8.f) : 0.f;
            *(half2*)&pb[i * APAD + 2 * lane] = __floats2half2_rn(p1, p2);
            dl[s] += p1 + p2;
        }
    };

    // prologue
    issueV(0, 0);
    buildP(0, 0);

    for (int t = 0; t < 16; t++) {
        int cb = t & 1, nb = cb ^ 1;
        cpa_wait0();
        __syncthreads();
        if (t < 15) issueV(nb, (t + 1) * 64);
        // MMA on tile t
        const __half* pb = Ps + cb * 128 * APAD;
        const __half* vb = Vs + cb * 128 * APAD;
#pragma unroll
        for (int kk = 0; kk < 64; kk += 16) {
            unsigned af[2][4], bf[4][4];
            ldsm4(af[0], &pb[(wm + ar) * APAD + kk + akh]);
            ldsm4(af[1], &pb[(wm + 16 + ar) * APAD + kk + akh]);
#pragma unroll
            for (int np = 0; np < 4; np++)
                ldsm4(bf[np], &vb[(wn + np * 16 + bn) * APAD + kk + bkh]);
#pragma unroll
            for (int mt = 0; mt < 2; mt++)
#pragma unroll
                for (int n8 = 0; n8 < 8; n8++)
                    mma16816(acc[mt][n8], af[mt], &bf[n8 >> 1][(n8 & 1) * 2],
                             acc[mt][n8]);
        }
        if (t < 15) buildP(nb, (t + 1) * 64);
    }

    // denominator reduce (each warp owns rows w+8s, lanes cover all j)
#pragma unroll
    for (int s = 0; s < 16; s++) {
        float v = dl[s];
#pragma unroll
        for (int o = 16; o; o >>= 1) v += __shfl_xor_sync(0xffffffffu, v, o);
        if (lane == 0) ds[s * 8 + w] = v;
    }
    __syncthreads();

    int r0 = lane >> 2, cc = (lane & 3) * 2;
#pragma unroll
    for (int mt = 0; mt < 2; mt++)
#pragma unroll
        for (int n8 = 0; n8 < 8; n8++) {
            int row0 = wm + mt * 16 + r0, row1 = row0 + 8;
            int col = wn + n8 * 8 + cc;
            float inv0 = 1.f / ds[row0], inv1 = 1.f / ds[row1];
            float f0 = acc[mt][n8][0] * inv0, f1 = acc[mt][n8][1] * inv0;
            float f2 = acc[mt][n8][2] * inv1, f3 = acc[mt][n8][3] * inv1;
            if (MODE == 0) {
                f0 = f0 > 0.f ? f0 : expm1f(f0);
                f1 = f1 > 0.f ? f1 : expm1f(f1);
                f2 = f2 > 0.f ? f2 : expm1f(f2);
                f3 = f3 > 0.f ? f3 : expm1f(f3);
                __half* x1 = (__half*)outp;
                *(half2*)&x1[((size_t)b * 1024 + i0 + row0) * 1024 + h * 128 + col] =
                    __floats2half2_rn(f0, f1);
                *(half2*)&x1[((size_t)b * 1024 + i0 + row1) * 1024 + h * 128 + col] =
                    __floats2half2_rn(f2, f3);
            } else {
                float* o2 = (float*)outp;
                *(float2*)&o2[((size_t)b * 1024 + i0 + row0) * 128 + col] =
                    make_float2(f0, f1);
                *(float2*)&o2[((size_t)b * 1024 + i0 + row1) * 128 + col] =
                    make_float2(f2, f3);
            }
        }
}

// ---------------- final fp32 gemm: relu((linp+att2+lin_b) @ ln_wT + ln_b) ----
__global__ void __launch_bounds__(256)
final_k(const float* __restrict__ A0, const float* __restrict__ B0,
        float* __restrict__ C0, const float* __restrict__ add,
        const float* __restrict__ biasA, const float* __restrict__ biasC) {
    const int BK = 32, BM = 64, RM = 4;
    __shared__ float As[BK][BM + 4];
    __shared__ float Bs[BK][128 + 4];
    int mblk = blockIdx.x * BM;
    int tid = threadIdx.x;
    int tx = tid % 16, ty = tid / 16;
    u64 acc[RM][4];
#pragma unroll
    for (int r = 0; r < RM; r++)
#pragma unroll
        for (int c = 0; c < 4; c++) acc[r][c] = 0ull;

    for (int k0 = 0; k0 < 128; k0 += BK) {
#pragma unroll
        for (int q = 0; q < BM / 32; q++) {
            int f = tid + q * 256;
            int m = f >> 3;
            int kk = (f & 7) * 4;
            const float* ap = A0 + (size_t)(mblk + m) * 128 + (k0 + kk);
            const float* dp = add + (size_t)(mblk + m) * 128 + (k0 + kk);
            const float* bp = biasA + (k0 + kk);
            float4 v;
            v.x = ap[0] + dp[0] + bp[0];
            v.y = ap[1] + dp[1] + bp[1];
            v.z = ap[2] + dp[2] + bp[2];
            v.w = ap[3] + dp[3] + bp[3];
            As[kk + 0][m] = v.x;
            As[kk + 1][m] = v.y;
            As[kk + 2][m] = v.z;
            As[kk + 3][m] = v.w;
        }
#pragma unroll
        for (int q = 0; q < 4; q++) {
            int f = tid + q * 256;
            int kk = f >> 5;
            int nn = (f & 31) * 4;
            *(float4*)&Bs[kk][nn] = *(const float4*)(B0 + (size_t)(k0 + kk) * 128 + nn);
        }
        __syncthreads();
#pragma unroll 8
        for (int kk = 0; kk < BK; kk++) {
            u64 as_[RM];
            float4 av = *(const float4*)&As[kk][ty * RM];
            as_[0] = splat2(av.x);
            as_[1] = splat2(av.y);
            as_[2] = splat2(av.z);
            as_[3] = splat2(av.w);
            ulonglong2 b0 = *(const ulonglong2*)&Bs[kk][tx * 4];
            ulonglong2 b1 = *(const ulonglong2*)&Bs[kk][64 + tx * 4];
            u64 bs_[4] = {b0.x, b0.y, b1.x, b1.y};
#pragma unroll
            for (int r = 0; r < RM; r++)
#pragma unroll
                for (int c = 0; c < 4; c++) acc[r][c] = fma2(as_[r], bs_[c], acc[r][c]);
        }
        __syncthreads();
    }
#pragma unroll
    for (int r = 0; r < RM; r++) {
        int gm = mblk + ty * RM + r;
        float* crow = C0 + (size_t)gm * 128;
        float2 p0 = unpack2(acc[r][0]);
        float2 p1 = unpack2(acc[r][1]);
        float2 p2 = unpack2(acc[r][2]);
        float2 p3 = unpack2(acc[r][3]);
        float v[8] = {p0.x, p0.y, p1.x, p1.y, p2.x, p2.y, p3.x, p3.y};
#pragma unroll
        for (int c = 0; c < 4; c++) {
            v[c] = v[c] + biasC[tx * 4 + c];
            v[c] = v[c] > 0.f ? v[c] : 0.f;
            v[c + 4] = v[c + 4] + biasC[64 + tx * 4 + c];
            v[c + 4] = v[c + 4] > 0.f ? v[c + 4] : 0.f;
        }
        *(float4*)&crow[tx * 4] = make_float4(v[0], v[1], v[2], v[3]);
        *(float4*)&crow[64 + tx * 4] = make_float4(v[4], v[5], v[6], v[7]);
    }
}

// ---------------- launch ------------------------------------------------------
extern "C" void kernel_launch(void* const* d_in, const int* in_sizes, int n_in,
                              void* d_out, int out_size) {
    (void)in_sizes; (void)n_in; (void)out_size;
    const float* inputs = (const float*)d_in[0];
    const int* adj = (const int*)d_in[1];
    const float* W_att = (const float*)d_in[3];
    const float* a_src = (const float*)d_in[4];
    const float* a_dst = (const float*)d_in[5];
    const float* W_out = (const float*)d_in[6];
    const float* ao_src = (const float*)d_in[7];
    const float* ao_dst = (const float*)d_in[8];
    const float* lin_w = (const float*)d_in[9];
    const float* lin_b = (const float*)d_in[10];
    const float* ln_w = (const float*)d_in[11];
    const float* ln_b = (const float*)d_in[12];

    __half *p_in16, *p_wattT, *p_h1T, *p_x1, *p_woutT, *p_linw16, *p_h2T;
    float *p_linp, *p_att2, *p_s1, *p_s2, *p_s1b, *p_s2b, *p_ln_wT;
    cudaGetSymbolAddress((void**)&p_in16, g_in16);
    cudaGetSymbolAddress((void**)&p_wattT, g_wattT);
    cudaGetSymbolAddress((void**)&p_h1T, g_h1T);
    cudaGetSymbolAddress((void**)&p_x1, g_x1);
    cudaGetSymbolAddress((void**)&p_woutT, g_woutT);
    cudaGetSymbolAddress((void**)&p_linw16, g_linw16);
    cudaGetSymbolAddress((void**)&p_h2T, g_h2T);
    cudaGetSymbolAddress((void**)&p_linp, g_linp);
    cudaGetSymbolAddress((void**)&p_att2, g_att2);
    cudaGetSymbolAddress((void**)&p_s1, g_s1);
    cudaGetSymbolAddress((void**)&p_s2, g_s2);
    cudaGetSymbolAddress((void**)&p_s1b, g_s1b);
    cudaGetSymbolAddress((void**)&p_s2b, g_s2b);
    cudaGetSymbolAddress((void**)&p_ln_wT, g_ln_wT);

    const int AT_SMEM = (2 * 128 * APAD * 2) * 2 + (128 + 128 + 1024) * 4;
    cudaFuncSetAttribute(at_k<0>, cudaFuncAttributeMaxDynamicSharedMemorySize,
                         AT_SMEM);
    cudaFuncSetAttribute(at_k<1>, cudaFuncAttributeMaxDynamicSharedMemorySize,
                         AT_SMEM);

    // ---- ordered so at_k<0> is the 6th launch (ncu -s 5 -c 1 captures it) ----
    c2h_k<<<2048, 256>>>(inputs, p_in16, 2097152 / 4);                     // 0
    t2h_k<<<dim3(4, 8, 8), dim3(32, 8)>>>(W_att, p_wattT, 256, 128);       // 1
    tg_k<0><<<dim3(8, 1, 64), 256>>>(p_wattT, p_in16, p_h1T);              // 2
    sdots_t<<<64, 256>>>(p_h1T, a_src, a_dst, p_s1, p_s2, Hq);             // 3
    c2h_k<<<128, 256>>>(lin_w, p_linw16, 131072 / 4);                      // 4
    at_k<0><<<dim3(8, 1, 64), 256, AT_SMEM>>>(p_h1T, p_s1, p_s2, adj, p_x1); // 5
    t2h_k<<<dim3(4, 32, 1), dim3(32, 8)>>>(W_out, p_woutT, 1024, 128);     // 6
    transpose_k<<<dim3(4, 4), dim3(32, 8)>>>(ln_w, p_ln_wT, 128, 128);     // 7
    tg_k<1><<<dim3(8, 1, 8), 256>>>(p_woutT, p_x1, p_h2T);                 // 8
    tg_k<2><<<dim3(64, 1, 1), 256>>>(p_x1, p_linw16, p_linp);              // 9
    sdots_t<<<8, 256>>>(p_h2T, ao_src, ao_dst, p_s1b, p_s2b, 1);           // 10
    at_k<1><<<dim3(8, 1, 8), 256, AT_SMEM>>>(p_h2T, p_s1b, p_s2b, adj, p_att2); // 11
    final_k<<<128, 256>>>(p_linp, p_ln_wT, (float*)d_out, p_att2, lin_b, ln_b); // 12
}

// round 5
// speedup vs baseline: 3.1351x; 1.1613x over previous
#include <cuda_runtime.h>
#include <cuda_fp16.h>
#include <math.h>

#define ALPHA 0.2f

static const int Bq = 8, Nq = 1024, Fq = 256, Oq = 128, Hq = 8;

typedef unsigned long long u64;

// ---------------- f32x2 helpers (final fp32 gemm only) -----------------------
__device__ __forceinline__ u64 fma2(u64 a, u64 b, u64 c) {
    u64 d;
    asm("fma.rn.f32x2 %0, %1, %2, %3;" : "=l"(d) : "l"(a), "l"(b), "l"(c));
    return d;
}
__device__ __forceinline__ u64 splat2(float x) {
    u64 d;
    unsigned u = __float_as_uint(x);
    asm("mov.b64 %0, {%1, %1};" : "=l"(d) : "r"(u));
    return d;
}
__device__ __forceinline__ float2 unpack2(u64 v) {
    unsigned lo, hi;
    asm("mov.b64 {%0, %1}, %2;" : "=r"(lo), "=r"(hi) : "l"(v));
    return make_float2(__uint_as_float(lo), __uint_as_float(hi));
}

// ---------------- tensor-core helpers ---------------------------------------
__device__ __forceinline__ void ldsm4(unsigned* r, const void* p) {
    unsigned a = (unsigned)__cvta_generic_to_shared(p);
    asm volatile("ldmatrix.sync.aligned.m8n8.x4.shared.b16 {%0,%1,%2,%3}, [%4];"
                 : "=r"(r[0]), "=r"(r[1]), "=r"(r[2]), "=r"(r[3]) : "r"(a));
}
__device__ __forceinline__ void mma16816(float* d, const unsigned* a,
                                         const unsigned* b, const float* c) {
    asm volatile(
        "mma.sync.aligned.m16n8k16.row.col.f32.f16.f16.f32 "
        "{%0,%1,%2,%3},{%4,%5,%6,%7},{%8,%9},{%10,%11,%12,%13};"
        : "=f"(d[0]), "=f"(d[1]), "=f"(d[2]), "=f"(d[3])
        : "r"(a[0]), "r"(a[1]), "r"(a[2]), "r"(a[3]), "r"(b[0]), "r"(b[1]),
          "f"(c[0]), "f"(c[1]), "f"(c[2]), "f"(c[3]));
}
__device__ __forceinline__ void cpa16(void* smem_dst, const void* gsrc) {
    unsigned a = (unsigned)__cvta_generic_to_shared(smem_dst);
    asm volatile("cp.async.ca.shared.global [%0], [%1], 16;" :: "r"(a), "l"(gsrc));
}
__device__ __forceinline__ void cpa_commit() {
    asm volatile("cp.async.commit_group;" ::: "memory");
}
__device__ __forceinline__ void cpa_wait0() {
    asm volatile("cp.async.wait_group 0;" ::: "memory");
}

// ---------------- scratch ----------------------------------------------------
__device__ __half g_in16[(size_t)8192 * 256];
__device__ __half g_wattT[(size_t)8 * 128 * 256];
__device__ __half g_h1T[(size_t)64 * 128 * 1024];     // [z][o][j]
__device__ __half g_x1[(size_t)8192 * 1024];          // [b*N+n][h*O+o]
__device__ __half g_woutT[(size_t)128 * 1024];
__device__ __half g_linw16[(size_t)128 * 1024];
__device__ __half g_h2T[(size_t)8 * 128 * 1024];
__device__ float g_linp[(size_t)8192 * 128];
__device__ float g_att2[(size_t)8192 * 128];
__device__ float g_s1p[(size_t)4 * 65536];
__device__ float g_s2p[(size_t)4 * 65536];
__device__ float g_ln_wT[(size_t)128 * 128];
__device__ unsigned g_mask[(size_t)8 * 1024 * 32];    // adj bitmask, 1MB

// ---------------- prep kernels ----------------------------------------------
__global__ void c2h_k(const float* __restrict__ in, __half* __restrict__ out,
                      int n4) {
    int i = blockIdx.x * 256 + threadIdx.x;
    if (i < n4) {
        float4 v = ((const float4*)in)[i];
        half2 a = __floats2half2_rn(v.x, v.y);
        half2 b = __floats2half2_rn(v.z, v.w);
        uint2 o;
        o.x = *(unsigned*)&a;
        o.y = *(unsigned*)&b;
        *(uint2*)(out + (size_t)i * 4) = o;
    }
}

__global__ void packadj_k(const int* __restrict__ adj,
                          unsigned* __restrict__ mask) {
    int widx = blockIdx.x * 8 + (threadIdx.x >> 5);
    int lane = threadIdx.x & 31;
    int v = adj[(size_t)widx * 32 + lane];
    unsigned m = __ballot_sync(0xffffffffu, v > 0);
    if (lane == 0) mask[widx] = m;
}

// in fp32 [z][R][C] -> out fp16 [z][C][R]
__global__ void t2h_k(const float* __restrict__ in, __half* __restrict__ out,
                      int R, int C) {
    __shared__ float t[32][33];
    int z = blockIdx.z;
    in += (size_t)z * R * C;
    out += (size_t)z * R * C;
    int c0 = blockIdx.x * 32, r0 = blockIdx.y * 32;
    int x = threadIdx.x, y = threadIdx.y;
    for (int i = y; i < 32; i += 8) t[i][x] = in[(size_t)(r0 + i) * C + c0 + x];
    __syncthreads();
    for (int i = y; i < 32; i += 8)
        out[(size_t)(c0 + i) * R + r0 + x] = __float2half_rn(t[x][i]);
}

__global__ void transpose_k(const float* __restrict__ in, float* __restrict__ out,
                            int R, int C) {
    __shared__ float t[32][33];
    int c0 = blockIdx.x * 32, r0 = blockIdx.y * 32;
    int x = threadIdx.x, y = threadIdx.y;
    for (int i = y; i < 32; i += 8) {
        int r = r0 + i, c = c0 + x;
        if (r < R && c < C) t[i][x] = in[(size_t)r * C + c];
    }
    __syncthreads();
    for (int i = y; i < 32; i += 8) {
        int c = c0 + i, r = r0 + x;
        if (c < C && r < R) out[(size_t)c * R + r] = t[x][i];
    }
}

// ---------------- tensor GEMM: C = A @ Bt^T ---------------------------------
// MODE 0: h1T[z][o][j]: A=WattT[h] 128x256, Bt=in16[b] (TN=128 j rows)
// MODE 1: h2T[b][o][j]: A=woutT 128x1024, Bt=x1[b]   (TN=64 j rows)
// MODE 2: linp[m][o]  : A=x1 (TM=64 m rows), Bt=linw16 128x1024, fp32 out
template <int MODE>
__global__ __launch_bounds__(256) void tg_k(const __half* __restrict__ Aroot,
                                            const __half* __restrict__ Btroot,
                                            void* __restrict__ Croot) {
    const int K = (MODE == 0) ? 256 : 1024;
    const int TM = (MODE == 2) ? 64 : 128;
    const int TN = (MODE == 1) ? 64 : 128;
    const int MW = TM / 32;       // m-warps
    const int NW = 8 / MW;        // n-warps
    const int NSP = TN / NW;      // n-span per warp
    const int N8 = NSP / 8;
    const int PAD = 72;
    __shared__ __half As[TM * PAD];
    __shared__ __half Bs[TN * PAD];
    int tid = threadIdx.x, bx = blockIdx.x, z = blockIdx.z;

    const __half* A;
    const __half* Bt;
    __half* Ch = nullptr;
    float* Cf = nullptr;
    int lda, ldb, n0 = 0;
    if (MODE == 0) {
        int b = z >> 3, h = z & 7;
        A = Aroot + (size_t)h * 128 * 256;
        lda = 256;
        Bt = Btroot + (size_t)b * 1024 * 256 + (size_t)bx * 128 * 256;
        ldb = 256;
        Ch = (__half*)Croot + (size_t)z * 131072;
        n0 = bx * 128;
    } else if (MODE == 1) {
        A = Aroot;
        lda = 1024;
        Bt = Btroot + (size_t)z * 1048576 + (size_t)bx * 64 * 1024;
        ldb = 1024;
        Ch = (__half*)Croot + (size_t)z * 131072;
        n0 = bx * 64;
    } else {
        A = Aroot + (size_t)bx * 64 * 1024;
        lda = 1024;
        Bt = Btroot;
        ldb = 1024;
        Cf = (float*)Croot + (size_t)bx * 64 * 128;
    }

    int w = tid >> 5, lane = tid & 31;
    int mw = w % MW, nw = w / MW;
    int wm = mw * 32, wn = nw * NSP;
    int ar = (lane & 7) | (((lane >> 3) & 1) << 3);
    int akh = (lane >> 4) << 3;
    int bn = ((lane >> 4) << 3) | (lane & 7);
    int bkh = ((lane >> 3) & 1) << 3;

    float acc[2][N8][4];
#pragma unroll
    for (int mt = 0; mt < 2; mt++)
#pragma unroll
        for (int n8 = 0; n8 < N8; n8++)
#pragma unroll
            for (int e = 0; e < 4; e++) acc[mt][n8][e] = 0.f;

    for (int k0 = 0; k0 < K; k0 += 64) {
#pragma unroll
        for (int q = 0; q < TM / 32; q++) {
            int f = tid + q * 256;
            int row = f >> 3, c8 = f & 7;
            *(uint4*)&As[row * PAD + c8 * 8] =
                *(const uint4*)(A + (size_t)row * lda + k0 + c8 * 8);
        }
#pragma unroll
        for (int q = 0; q < TN / 32; q++) {
            int f = tid + q * 256;
            int row = f >> 3, c8 = f & 7;
            *(uint4*)&Bs[row * PAD + c8 * 8] =
                *(const uint4*)(Bt + (size_t)row * ldb + k0 + c8 * 8);
        }
        __syncthreads();
#pragma unroll
        for (int kk = 0; kk < 64; kk += 16) {
            unsigned af[2][4], bf[N8 / 2][4];
            ldsm4(af[0], &As[(wm + ar) * PAD + kk + akh]);
            ldsm4(af[1], &As[(wm + 16 + ar) * PAD + kk + akh]);
#pragma unroll
            for (int np = 0; np < N8 / 2; np++)
                ldsm4(bf[np], &Bs[(wn + np * 16 + bn) * PAD + kk + bkh]);
#pragma unroll
            for (int mt = 0; mt < 2; mt++)
#pragma unroll
                for (int n8 = 0; n8 < N8; n8++)
                    mma16816(acc[mt][n8], af[mt], &bf[n8 >> 1][(n8 & 1) * 2],
                             acc[mt][n8]);
        }
        __syncthreads();
    }

    int r0 = lane >> 2, cc = (lane & 3) * 2;
#pragma unroll
    for (int mt = 0; mt < 2; mt++)
#pragma unroll
        for (int n8 = 0; n8 < N8; n8++) {
            int row0 = wm + mt * 16 + r0;
            int col = wn + n8 * 8 + cc;
            if (MODE <= 1) {
                half2 lo = __floats2half2_rn(acc[mt][n8][0], acc[mt][n8][1]);
                half2 hi = __floats2half2_rn(acc[mt][n8][2], acc[mt][n8][3]);
                *(half2*)&Ch[(size_t)row0 * 1024 + n0 + col] = lo;
                *(half2*)&Ch[(size_t)(row0 + 8) * 1024 + n0 + col] = hi;
            } else {
                *(float2*)&Cf[(size_t)row0 * 128 + col] =
                    make_float2(acc[mt][n8][0], acc[mt][n8][1]);
                *(float2*)&Cf[(size_t)(row0 + 8) * 128 + col] =
                    make_float2(acc[mt][n8][2], acc[mt][n8][3]);
            }
        }
}

// ---------------- s1/s2 partial dots (o-chunked for occupancy) ---------------
// block (z, oc): s1p[oc*cstr + z*1024 + j] = sum_{o in chunk} asrc[o]*hT[z][o][j]
__global__ __launch_bounds__(256) void sdots_t(const __half* __restrict__ hT,
                                               const float* __restrict__ asrc,
                                               const float* __restrict__ adst,
                                               float* __restrict__ s1p,
                                               float* __restrict__ s2p, int hh,
                                               int cstr) {
    __shared__ float a1s[32], a2s[32];
    int z = blockIdx.x, oc = blockIdx.y, tid = threadIdx.x;
    int hidx = z % hh;
    if (tid < 32) a1s[tid] = asrc[hidx * 128 + oc * 32 + tid];
    else if (tid < 64) a2s[tid - 32] = adst[hidx * 128 + oc * 32 + tid - 32];
    __syncthreads();
    const __half* hz = hT + (size_t)z * 131072 + (size_t)oc * 32 * 1024;
    int j0 = tid * 4;
    float A1[4] = {0.f, 0.f, 0.f, 0.f}, A2[4] = {0.f, 0.f, 0.f, 0.f};
#pragma unroll 8
    for (int o = 0; o < 32; o++) {
        float v1 = a1s[o], v2 = a2s[o];
        uint2 raw = *(const uint2*)(hz + (size_t)o * 1024 + j0);
        half2 h0 = *(half2*)&raw.x;
        half2 h1 = *(half2*)&raw.y;
        float2 f0 = __half22float2(h0), f1 = __half22float2(h1);
        A1[0] += v1 * f0.x; A1[1] += v1 * f0.y;
        A1[2] += v1 * f1.x; A1[3] += v1 * f1.y;
        A2[0] += v2 * f0.x; A2[1] += v2 * f0.y;
        A2[2] += v2 * f1.x; A2[3] += v2 * f1.y;
    }
    size_t off = (size_t)oc * cstr + (size_t)z * 1024 + j0;
    *(float4*)&s1p[off] = make_float4(A1[0], A1[1], A1[2], A1[3]);
    *(float4*)&s2p[off] = make_float4(A2[0], A2[1], A2[2], A2[3]);
}

// ---------------- pipelined tensor-core fused attention ----------------------
// p = adjbit ? exp(lrelu(s1_i+s2_j) - 8) : 0; out_i = (sum p h_j)/(sum p)
#define APAD 72
template <int MODE>
__global__ __launch_bounds__(256) void at_k(const __half* __restrict__ hT,
                                            const float* __restrict__ s1p,
                                            const float* __restrict__ s2p,
                                            const unsigned* __restrict__ mask,
                                            void* __restrict__ outp, int cstr) {
    const int TM = (MODE == 0) ? 128 : 64;
    const int MW = TM / 32;       // m-warps: 4 or 2
    const int NW = 8 / MW;        // 2 or 4
    const int NSP = 128 / NW;     // 64 or 32
    const int N8 = NSP / 8;       // 8 or 4
    const int SC = TM / 8;        // rows per warp in P-build

    extern __shared__ char smraw[];
    __half* Ps = (__half*)smraw;                        // 2 * TM*APAD
    __half* Vs = Ps + 2 * TM * APAD;                    // 2 * 128*APAD
    float* s1s = (float*)(Vs + 2 * 128 * APAD);         // TM
    float* ds = s1s + TM;                               // TM
    float* s2s = ds + TM;                               // 1024

    int tid = threadIdx.x, bx = blockIdx.x, z = blockIdx.z;
    int b, h;
    if (MODE == 0) { b = z >> 3; h = z & 7; }
    else { b = z; h = 0; }
    int i0 = bx * TM;
    const __half* hz = hT + (size_t)z * 131072;
    const unsigned* maskb = mask + (size_t)b * 1024 * 32;

    {
        float4 v = make_float4(0.f, 0.f, 0.f, 0.f);
#pragma unroll
        for (int c = 0; c < 4; c++) {
            float4 p = ((const float4*)(s2p + (size_t)c * cstr + (size_t)z * 1024))[tid];
            v.x += p.x; v.y += p.y; v.z += p.z; v.w += p.w;
        }
        ((float4*)s2s)[tid] = v;
        if (tid < TM) {
            float s = 0.f;
#pragma unroll
            for (int c = 0; c < 4; c++)
                s += s1p[(size_t)c * cstr + (size_t)z * 1024 + i0 + tid];
            s1s[tid] = s;
        }
    }
    __syncthreads();

    int w = tid >> 5, lane = tid & 31;
    int mw = w % MW, nw = w / MW;
    int wm = mw * 32, wn = nw * NSP;
    int ar = (lane & 7) | (((lane >> 3) & 1) << 3);
    int akh = (lane >> 4) << 3;
    int bn = ((lane >> 4) << 3) | (lane & 7);
    int bkh = ((lane >> 3) & 1) << 3;

    float acc[2][N8][4];
#pragma unroll
    for (int mt = 0; mt < 2; mt++)
#pragma unroll
        for (int n8 = 0; n8 < N8; n8++)
#pragma unroll
            for (int e = 0; e < 4; e++) acc[mt][n8][e] = 0.f;
    float dl[SC];
#pragma unroll
    for (int s = 0; s < SC; s++) dl[s] = 0.f;

    int bitpos = (2 * lane) & 31;

    auto issueV = [&](int buf, int j0) {
        __half* vb = Vs + buf * 128 * APAD;
#pragma unroll
        for (int q = 0; q < 4; q++) {
            int f = tid + q * 256;
            int row = f >> 3, c8 = f & 7;
            cpa16(&vb[row * APAD + c8 * 8],
                  hz + (size_t)row * 1024 + j0 + c8 * 8);
        }
        cpa_commit();
    };
    auto buildP = [&](int buf, int j0) {
        __half* pb = Ps + buf * TM * APAD;
        float s2a = s2s[j0 + 2 * lane];
        float s2b = s2s[j0 + 2 * lane + 1];
        const unsigned* mp = maskb + ((size_t)(i0 + w) << 5) + (j0 >> 5) + (lane >> 4);
#pragma unroll
        for (int s = 0; s < SC; s++) {
            int i = w + s * 8;
            unsigned m = mp[(size_t)s * 256];
            unsigned two = (m >> bitpos) & 3u;
            float s1v = s1s[i];
            float e1 = s1v + s2a;
            e1 = e1 > 0.f ? e1 : ALPHA * e1;
            float e2 = s1v + s2b;
            e2 = e2 > 0.f ? e2 : ALPHA * e2;
            float p1 = (two & 1u) ? __expf(e1 - 8.f) : 0.f;
            float p2 = (two & 2u) ? __expf(e2 - 8.f) : 0.f;
            *(half2*)&pb[i * APAD + 2 * lane] = __floats2half2_rn(p1, p2);
            dl[s] += p1 + p2;
        }
    };

    issueV(0, 0);
    buildP(0, 0);

    for (int t = 0; t < 16; t++) {
        int cb = t & 1, nb = cb ^ 1;
        cpa_wait0();
        __syncthreads();
        if (t < 15) issueV(nb, (t + 1) * 64);
        const __half* pb = Ps + cb * TM * APAD;
        const __half* vb = Vs + cb * 128 * APAD;
#pragma unroll
        for (int kk = 0; kk < 64; kk += 16) {
            unsigned af[2][4], bf[N8 / 2][4];
            ldsm4(af[0], &pb[(wm + ar) * APAD + kk + akh]);
            ldsm4(af[1], &pb[(wm + 16 + ar) * APAD + kk + akh]);
#pragma unroll
            for (int np = 0; np < N8 / 2; np++)
                ldsm4(bf[np], &vb[(wn + np * 16 + bn) * APAD + kk + bkh]);
#pragma unroll
            for (int mt = 0; mt < 2; mt++)
#pragma unroll
                for (int n8 = 0; n8 < N8; n8++)
                    mma16816(acc[mt][n8], af[mt], &bf[n8 >> 1][(n8 & 1) * 2],
                             acc[mt][n8]);
        }
        if (t < 15) buildP(nb, (t + 1) * 64);
    }

#pragma unroll
    for (int s = 0; s < SC; s++) {
        float v = dl[s];
#pragma unroll
        for (int o = 16; o; o >>= 1) v += __shfl_xor_sync(0xffffffffu, v, o);
        if (lane == 0) ds[s * 8 + w] = v;
    }
    __syncthreads();

    int r0 = lane >> 2, cc = (lane & 3) * 2;
#pragma unroll
    for (int mt = 0; mt < 2; mt++)
#pragma unroll
        for (int n8 = 0; n8 < N8; n8++) {
            int row0 = wm + mt * 16 + r0, row1 = row0 + 8;
            int col = wn + n8 * 8 + cc;
            float inv0 = 1.f / ds[row0], inv1 = 1.f / ds[row1];
            float f0 = acc[mt][n8][0] * inv0, f1 = acc[mt][n8][1] * inv0;
            float f2 = acc[mt][n8][2] * inv1, f3 = acc[mt][n8][3] * inv1;
            if (MODE == 0) {
                f0 = f0 > 0.f ? f0 : expm1f(f0);
                f1 = f1 > 0.f ? f1 : expm1f(f1);
                f2 = f2 > 0.f ? f2 : expm1f(f2);
                f3 = f3 > 0.f ? f3 : expm1f(f3);
                __half* x1 = (__half*)outp;
                *(half2*)&x1[((size_t)b * 1024 + i0 + row0) * 1024 + h * 128 + col] =
                    __floats2half2_rn(f0, f1);
                *(half2*)&x1[((size_t)b * 1024 + i0 + row1) * 1024 + h * 128 + col] =
                    __floats2half2_rn(f2, f3);
            } else {
                float* o2 = (float*)outp;
                *(float2*)&o2[((size_t)b * 1024 + i0 + row0) * 128 + col] =
                    make_float2(f0, f1);
                *(float2*)&o2[((size_t)b * 1024 + i0 + row1) * 128 + col] =
                    make_float2(f2, f3);
            }
        }
}

// ---------------- final fp32 gemm: relu((linp+att2+lin_b) @ ln_wT + ln_b) ----
__global__ void __launch_bounds__(256)
final_k(const float* __restrict__ A0, const float* __restrict__ B0,
        float* __restrict__ C0, const float* __restrict__ add,
        const float* __restrict__ biasA, const float* __restrict__ biasC) {
    const int BK = 32, BM = 64, RM = 4;
    __shared__ float As[BK][BM + 4];
    __shared__ float Bs[BK][128 + 4];
    int mblk = blockIdx.x * BM;
    int tid = threadIdx.x;
    int tx = tid % 16, ty = tid / 16;
    u64 acc[RM][4];
#pragma unroll
    for (int r = 0; r < RM; r++)
#pragma unroll
        for (int c = 0; c < 4; c++) acc[r][c] = 0ull;

    for (int k0 = 0; k0 < 128; k0 += BK) {
#pragma unroll
        for (int q = 0; q < BM / 32; q++) {
            int f = tid + q * 256;
            int m = f >> 3;
            int kk = (f & 7) * 4;
            const float* ap = A0 + (size_t)(mblk + m) * 128 + (k0 + kk);
            const float* dp = add + (size_t)(mblk + m) * 128 + (k0 + kk);
            const float* bp = biasA + (k0 + kk);
            float4 v;
            v.x = ap[0] + dp[0] + bp[0];
            v.y = ap[1] + dp[1] + bp[1];
            v.z = ap[2] + dp[2] + bp[2];
            v.w = ap[3] + dp[3] + bp[3];
            As[kk + 0][m] = v.x;
            As[kk + 1][m] = v.y;
            As[kk + 2][m] = v.z;
            As[kk + 3][m] = v.w;
        }
#pragma unroll
        for (int q = 0; q < 4; q++) {
            int f = tid + q * 256;
            int kk = f >> 5;
            int nn = (f & 31) * 4;
            *(float4*)&Bs[kk][nn] = *(const float4*)(B0 + (size_t)(k0 + kk) * 128 + nn);
        }
        __syncthreads();
#pragma unroll 8
        for (int kk = 0; kk < BK; kk++) {
            u64 as_[RM];
            float4 av = *(const float4*)&As[kk][ty * RM];
            as_[0] = splat2(av.x);
            as_[1] = splat2(av.y);
            as_[2] = splat2(av.z);
            as_[3] = splat2(av.w);
            ulonglong2 b0 = *(const ulonglong2*)&Bs[kk][tx * 4];
            ulonglong2 b1 = *(const ulonglong2*)&Bs[kk][64 + tx * 4];
            u64 bs_[4] = {b0.x, b0.y, b1.x, b1.y};
#pragma unroll
            for (int r = 0; r < RM; r++)
#pragma unroll
                for (int c = 0; c < 4; c++) acc[r][c] = fma2(as_[r], bs_[c], acc[r][c]);
        }
        __syncthreads();
    }
#pragma unroll
    for (int r = 0; r < RM; r++) {
        int gm = mblk + ty * RM + r;
        float* crow = C0 + (size_t)gm * 128;
        float2 p0 = unpack2(acc[r][0]);
        float2 p1 = unpack2(acc[r][1]);
        float2 p2 = unpack2(acc[r][2]);
        float2 p3 = unpack2(acc[r][3]);
        float v[8] = {p0.x, p0.y, p1.x, p1.y, p2.x, p2.y, p3.x, p3.y};
#pragma unroll
        for (int c = 0; c < 4; c++) {
            v[c] = v[c] + biasC[tx * 4 + c];
            v[c] = v[c] > 0.f ? v[c] : 0.f;
            v[c + 4] = v[c + 4] + biasC[64 + tx * 4 + c];
            v[c + 4] = v[c + 4] > 0.f ? v[c + 4] : 0.f;
        }
        *(float4*)&crow[tx * 4] = make_float4(v[0], v[1], v[2], v[3]);
        *(float4*)&crow[64 + tx * 4] = make_float4(v[4], v[5], v[6], v[7]);
    }
}

// ---------------- launch ------------------------------------------------------
extern "C" void kernel_launch(void* const* d_in, const int* in_sizes, int n_in,
                              void* d_out, int out_size) {
    (void)in_sizes; (void)n_in; (void)out_size;
    const float* inputs = (const float*)d_in[0];
    const int* adj = (const int*)d_in[1];
    const float* W_att = (const float*)d_in[3];
    const float* a_src = (const float*)d_in[4];
    const float* a_dst = (const float*)d_in[5];
    const float* W_out = (const float*)d_in[6];
    const float* ao_src = (const float*)d_in[7];
    const float* ao_dst = (const float*)d_in[8];
    const float* lin_w = (const float*)d_in[9];
    const float* lin_b = (const float*)d_in[10];
    const float* ln_w = (const float*)d_in[11];
    const float* ln_b = (const float*)d_in[12];

    __half *p_in16, *p_wattT, *p_h1T, *p_x1, *p_woutT, *p_linw16, *p_h2T;
    float *p_linp, *p_att2, *p_s1p, *p_s2p, *p_ln_wT;
    unsigned* p_mask;
    cudaGetSymbolAddress((void**)&p_in16, g_in16);
    cudaGetSymbolAddress((void**)&p_wattT, g_wattT);
    cudaGetSymbolAddress((void**)&p_h1T, g_h1T);
    cudaGetSymbolAddress((void**)&p_x1, g_x1);
    cudaGetSymbolAddress((void**)&p_woutT, g_woutT);
    cudaGetSymbolAddress((void**)&p_linw16, g_linw16);
    cudaGetSymbolAddress((void**)&p_h2T, g_h2T);
    cudaGetSymbolAddress((void**)&p_linp, g_linp);
    cudaGetSymbolAddress((void**)&p_att2, g_att2);
    cudaGetSymbolAddress((void**)&p_s1p, g_s1p);
    cudaGetSymbolAddress((void**)&p_s2p, g_s2p);
    cudaGetSymbolAddress((void**)&p_ln_wT, g_ln_wT);
    cudaGetSymbolAddress((void**)&p_mask, g_mask);

    const int AT0_SMEM = (2 * 128 * APAD + 2 * 128 * APAD) * 2 + (128 + 128 + 1024) * 4;
    const int AT1_SMEM = (2 * 64 * APAD + 2 * 128 * APAD) * 2 + (64 + 64 + 1024) * 4;
    cudaFuncSetAttribute(at_k<0>, cudaFuncAttributeMaxDynamicSharedMemorySize,
                         AT0_SMEM);
    cudaFuncSetAttribute(at_k<1>, cudaFuncAttributeMaxDynamicSharedMemorySize,
                         AT1_SMEM);

    // ---- ordered so at_k<0> is the 6th launch (ncu -s 5 -c 1) ----
    c2h_k<<<2048, 256>>>(inputs, p_in16, 2097152 / 4);                       // 0
    t2h_k<<<dim3(4, 8, 8), dim3(32, 8)>>>(W_att, p_wattT, 256, 128);         // 1
    tg_k<0><<<dim3(8, 1, 64), 256>>>(p_wattT, p_in16, p_h1T);                // 2
    packadj_k<<<32768, 256>>>(adj, p_mask);                                  // 3
    sdots_t<<<dim3(64, 4), 256>>>(p_h1T, a_src, a_dst, p_s1p, p_s2p, Hq,
                                  65536);                                    // 4
    at_k<0><<<dim3(8, 1, 64), 256, AT0_SMEM>>>(p_h1T, p_s1p, p_s2p, p_mask,
                                               p_x1, 65536);                 // 5
    c2h_k<<<128, 256>>>(lin_w, p_linw16, 131072 / 4);                        // 6
    t2h_k<<<dim3(4, 32, 1), dim3(32, 8)>>>(W_out, p_woutT, 1024, 128);       // 7
    transpose_k<<<dim3(4, 4), dim3(32, 8)>>>(ln_w, p_ln_wT, 128, 128);       // 8
    tg_k<1><<<dim3(16, 1, 8), 256>>>(p_woutT, p_x1, p_h2T);                  // 9
    tg_k<2><<<dim3(128, 1, 1), 256>>>(p_x1, p_linw16, p_linp);               // 10
    sdots_t<<<dim3(8, 4), 256>>>(p_h2T, ao_src, ao_dst, p_s1p, p_s2p, 1,
                                 8192);                                      // 11
    at_k<1><<<dim3(16, 1, 8), 256, AT1_SMEM>>>(p_h2T, p_s1p, p_s2p, p_mask,
                                               p_att2, 8192);                // 12
    final_k<<<128, 256>>>(p_linp, p_ln_wT, (float*)d_out, p_att2, lin_b, ln_b); // 13
}

// round 6
// speedup vs baseline: 3.9339x; 1.2548x over previous
#include <cuda_runtime.h>
#include <cuda_fp16.h>
#include <math.h>

#define ALPHA 0.2f
#define LOG2E 1.44269504f
#define EXPSH 11.54156036f   // 8 * log2(e)

static const int Bq = 8, Nq = 1024, Fq = 256, Oq = 128, Hq = 8;

typedef unsigned long long u64;

// ---------------- f32x2 helpers (final fp32 gemm only) -----------------------
__device__ __forceinline__ u64 fma2(u64 a, u64 b, u64 c) {
    u64 d;
    asm("fma.rn.f32x2 %0, %1, %2, %3;" : "=l"(d) : "l"(a), "l"(b), "l"(c));
    return d;
}
__device__ __forceinline__ u64 splat2(float x) {
    u64 d;
    unsigned u = __float_as_uint(x);
    asm("mov.b64 %0, {%1, %1};" : "=l"(d) : "r"(u));
    return d;
}
__device__ __forceinline__ float2 unpack2(u64 v) {
    unsigned lo, hi;
    asm("mov.b64 {%0, %1}, %2;" : "=r"(lo), "=r"(hi) : "l"(v));
    return make_float2(__uint_as_float(lo), __uint_as_float(hi));
}
__device__ __forceinline__ float ex2a(float x) {
    float y;
    asm("ex2.approx.ftz.f32 %0, %1;" : "=f"(y) : "f"(x));
    return y;
}

// ---------------- tensor-core helpers ---------------------------------------
__device__ __forceinline__ void ldsm4(unsigned* r, const void* p) {
    unsigned a = (unsigned)__cvta_generic_to_shared(p);
    asm volatile("ldmatrix.sync.aligned.m8n8.x4.shared.b16 {%0,%1,%2,%3}, [%4];"
                 : "=r"(r[0]), "=r"(r[1]), "=r"(r[2]), "=r"(r[3]) : "r"(a));
}
__device__ __forceinline__ void mma16816(float* d, const unsigned* a,
                                         const unsigned* b, const float* c) {
    asm volatile(
        "mma.sync.aligned.m16n8k16.row.col.f32.f16.f16.f32 "
        "{%0,%1,%2,%3},{%4,%5,%6,%7},{%8,%9},{%10,%11,%12,%13};"
        : "=f"(d[0]), "=f"(d[1]), "=f"(d[2]), "=f"(d[3])
        : "r"(a[0]), "r"(a[1]), "r"(a[2]), "r"(a[3]), "r"(b[0]), "r"(b[1]),
          "f"(c[0]), "f"(c[1]), "f"(c[2]), "f"(c[3]));
}
__device__ __forceinline__ void cpa16(void* smem_dst, const void* gsrc) {
    unsigned a = (unsigned)__cvta_generic_to_shared(smem_dst);
    asm volatile("cp.async.ca.shared.global [%0], [%1], 16;" :: "r"(a), "l"(gsrc));
}
__device__ __forceinline__ void cpa_commit() {
    asm volatile("cp.async.commit_group;" ::: "memory");
}
__device__ __forceinline__ void cpa_wait0() {
    asm volatile("cp.async.wait_group 0;" ::: "memory");
}

// ---------------- scratch ----------------------------------------------------
__device__ __half g_in16[(size_t)8192 * 256];
__device__ __half g_wattT[(size_t)8 * 128 * 256];
__device__ __half g_h1T[(size_t)64 * 128 * 1024];     // [z][o][j]
__device__ __half g_x1[(size_t)8192 * 1024];          // [b*N+n][h*O+o]
__device__ __half g_woutT[(size_t)128 * 1024];
__device__ __half g_linw16[(size_t)128 * 1024];
__device__ __half g_h2T[(size_t)8 * 128 * 1024];
__device__ float g_linp[(size_t)8192 * 128];
__device__ float g_att2[(size_t)8192 * 128];
__device__ float g_s1p[(size_t)4 * 65536];
__device__ float g_s2p[(size_t)4 * 65536];
__device__ float g_ln_wT[(size_t)128 * 128];
__device__ unsigned g_mask[(size_t)8 * 1024 * 32];    // adj bitmask, 1MB

// ---------------- prep kernels ----------------------------------------------
__global__ void c2h_k(const float* __restrict__ in, __half* __restrict__ out,
                      int n4) {
    int i = blockIdx.x * 256 + threadIdx.x;
    if (i < n4) {
        float4 v = ((const float4*)in)[i];
        half2 a = __floats2half2_rn(v.x, v.y);
        half2 b = __floats2half2_rn(v.z, v.w);
        uint2 o;
        o.x = *(unsigned*)&a;
        o.y = *(unsigned*)&b;
        *(uint2*)(out + (size_t)i * 4) = o;
    }
}

// vectorized adj -> bitmask: int4 per thread, shuffle-OR across 8 lanes
__global__ void packadj_k(const int* __restrict__ adj,
                          unsigned* __restrict__ mask) {
    int t = blockIdx.x * 256 + threadIdx.x;   // int4 index
    int lane = threadIdx.x & 31;
    int4 v = ((const int4*)adj)[t];
    unsigned nib = (v.x > 0 ? 1u : 0u) | (v.y > 0 ? 2u : 0u) |
                   (v.z > 0 ? 4u : 0u) | (v.w > 0 ? 8u : 0u);
    unsigned r = nib << ((lane & 7) * 4);
    r |= __shfl_xor_sync(0xffffffffu, r, 1);
    r |= __shfl_xor_sync(0xffffffffu, r, 2);
    r |= __shfl_xor_sync(0xffffffffu, r, 4);
    if ((lane & 7) == 0) mask[t >> 3] = r;
}

// in fp32 [z][R][C] -> out fp16 [z][C][R]
__global__ void t2h_k(const float* __restrict__ in, __half* __restrict__ out,
                      int R, int C) {
    __shared__ float t[32][33];
    int z = blockIdx.z;
    in += (size_t)z * R * C;
    out += (size_t)z * R * C;
    int c0 = blockIdx.x * 32, r0 = blockIdx.y * 32;
    int x = threadIdx.x, y = threadIdx.y;
    for (int i = y; i < 32; i += 8) t[i][x] = in[(size_t)(r0 + i) * C + c0 + x];
    __syncthreads();
    for (int i = y; i < 32; i += 8)
        out[(size_t)(c0 + i) * R + r0 + x] = __float2half_rn(t[x][i]);
}

__global__ void transpose_k(const float* __restrict__ in, float* __restrict__ out,
                            int R, int C) {
    __shared__ float t[32][33];
    int c0 = blockIdx.x * 32, r0 = blockIdx.y * 32;
    int x = threadIdx.x, y = threadIdx.y;
    for (int i = y; i < 32; i += 8) {
        int r = r0 + i, c = c0 + x;
        if (r < R && c < C) t[i][x] = in[(size_t)r * C + c];
    }
    __syncthreads();
    for (int i = y; i < 32; i += 8) {
        int c = c0 + i, r = r0 + x;
        if (c < C && r < R) out[(size_t)c * R + r] = t[x][i];
    }
}

// ---------------- tensor GEMM: C = A @ Bt^T ---------------------------------
template <int MODE>
__global__ __launch_bounds__(256) void tg_k(const __half* __restrict__ Aroot,
                                            const __half* __restrict__ Btroot,
                                            void* __restrict__ Croot) {
    const int K = (MODE == 0) ? 256 : 1024;
    const int TM = (MODE == 2) ? 64 : 128;
    const int TN = (MODE == 1) ? 64 : 128;
    const int MW = TM / 32;
    const int NW = 8 / MW;
    const int NSP = TN / NW;
    const int N8 = NSP / 8;
    const int PAD = 72;
    __shared__ __half As[TM * PAD];
    __shared__ __half Bs[TN * PAD];
    int tid = threadIdx.x, bx = blockIdx.x, z = blockIdx.z;

    const __half* A;
    const __half* Bt;
    __half* Ch = nullptr;
    float* Cf = nullptr;
    int lda, ldb, n0 = 0;
    if (MODE == 0) {
        int b = z >> 3, h = z & 7;
        A = Aroot + (size_t)h * 128 * 256;
        lda = 256;
        Bt = Btroot + (size_t)b * 1024 * 256 + (size_t)bx * 128 * 256;
        ldb = 256;
        Ch = (__half*)Croot + (size_t)z * 131072;
        n0 = bx * 128;
    } else if (MODE == 1) {
        A = Aroot;
        lda = 1024;
        Bt = Btroot + (size_t)z * 1048576 + (size_t)bx * 64 * 1024;
        ldb = 1024;
        Ch = (__half*)Croot + (size_t)z * 131072;
        n0 = bx * 64;
    } else {
        A = Aroot + (size_t)bx * 64 * 1024;
        lda = 1024;
        Bt = Btroot;
        ldb = 1024;
        Cf = (float*)Croot + (size_t)bx * 64 * 128;
    }

    int w = tid >> 5, lane = tid & 31;
    int mw = w % MW, nw = w / MW;
    int wm = mw * 32, wn = nw * NSP;
    int ar = (lane & 7) | (((lane >> 3) & 1) << 3);
    int akh = (lane >> 4) << 3;
    int bn = ((lane >> 4) << 3) | (lane & 7);
    int bkh = ((lane >> 3) & 1) << 3;

    float acc[2][N8][4];
#pragma unroll
    for (int mt = 0; mt < 2; mt++)
#pragma unroll
        for (int n8 = 0; n8 < N8; n8++)
#pragma unroll
            for (int e = 0; e < 4; e++) acc[mt][n8][e] = 0.f;

    for (int k0 = 0; k0 < K; k0 += 64) {
#pragma unroll
        for (int q = 0; q < TM / 32; q++) {
            int f = tid + q * 256;
            int row = f >> 3, c8 = f & 7;
            *(uint4*)&As[row * PAD + c8 * 8] =
                *(const uint4*)(A + (size_t)row * lda + k0 + c8 * 8);
        }
#pragma unroll
        for (int q = 0; q < TN / 32; q++) {
            int f = tid + q * 256;
            int row = f >> 3, c8 = f & 7;
            *(uint4*)&Bs[row * PAD + c8 * 8] =
                *(const uint4*)(Bt + (size_t)row * ldb + k0 + c8 * 8);
        }
        __syncthreads();
#pragma unroll
        for (int kk = 0; kk < 64; kk += 16) {
            unsigned af[2][4], bf[N8 / 2][4];
            ldsm4(af[0], &As[(wm + ar) * PAD + kk + akh]);
            ldsm4(af[1], &As[(wm + 16 + ar) * PAD + kk + akh]);
#pragma unroll
            for (int np = 0; np < N8 / 2; np++)
                ldsm4(bf[np], &Bs[(wn + np * 16 + bn) * PAD + kk + bkh]);
#pragma unroll
            for (int mt = 0; mt < 2; mt++)
#pragma unroll
                for (int n8 = 0; n8 < N8; n8++)
                    mma16816(acc[mt][n8], af[mt], &bf[n8 >> 1][(n8 & 1) * 2],
                             acc[mt][n8]);
        }
        __syncthreads();
    }

    int r0 = lane >> 2, cc = (lane & 3) * 2;
#pragma unroll
    for (int mt = 0; mt < 2; mt++)
#pragma unroll
        for (int n8 = 0; n8 < N8; n8++) {
            int row0 = wm + mt * 16 + r0;
            int col = wn + n8 * 8 + cc;
            if (MODE <= 1) {
                half2 lo = __floats2half2_rn(acc[mt][n8][0], acc[mt][n8][1]);
                half2 hi = __floats2half2_rn(acc[mt][n8][2], acc[mt][n8][3]);
                *(half2*)&Ch[(size_t)row0 * 1024 + n0 + col] = lo;
                *(half2*)&Ch[(size_t)(row0 + 8) * 1024 + n0 + col] = hi;
            } else {
                *(float2*)&Cf[(size_t)row0 * 128 + col] =
                    make_float2(acc[mt][n8][0], acc[mt][n8][1]);
                *(float2*)&Cf[(size_t)(row0 + 8) * 128 + col] =
                    make_float2(acc[mt][n8][2], acc[mt][n8][3]);
            }
        }
}

// ---------------- s1/s2 partial dots (scaled by log2e) -----------------------
__global__ __launch_bounds__(256) void sdots_t(const __half* __restrict__ hT,
                                               const float* __restrict__ asrc,
                                               const float* __restrict__ adst,
                                               float* __restrict__ s1p,
                                               float* __restrict__ s2p, int hh,
                                               int cstr) {
    __shared__ float a1s[32], a2s[32];
    int z = blockIdx.x, oc = blockIdx.y, tid = threadIdx.x;
    int hidx = z % hh;
    if (tid < 32) a1s[tid] = asrc[hidx * 128 + oc * 32 + tid] * LOG2E;
    else if (tid < 64) a2s[tid - 32] = adst[hidx * 128 + oc * 32 + tid - 32] * LOG2E;
    __syncthreads();
    const __half* hz = hT + (size_t)z * 131072 + (size_t)oc * 32 * 1024;
    int j0 = tid * 4;
    float A1[4] = {0.f, 0.f, 0.f, 0.f}, A2[4] = {0.f, 0.f, 0.f, 0.f};
#pragma unroll 8
    for (int o = 0; o < 32; o++) {
        float v1 = a1s[o], v2 = a2s[o];
        uint2 raw = *(const uint2*)(hz + (size_t)o * 1024 + j0);
        half2 h0 = *(half2*)&raw.x;
        half2 h1 = *(half2*)&raw.y;
        float2 f0 = __half22float2(h0), f1 = __half22float2(h1);
        A1[0] += v1 * f0.x; A1[1] += v1 * f0.y;
        A1[2] += v1 * f1.x; A1[3] += v1 * f1.y;
        A2[0] += v2 * f0.x; A2[1] += v2 * f0.y;
        A2[2] += v2 * f1.x; A2[3] += v2 * f1.y;
    }
    size_t off = (size_t)oc * cstr + (size_t)z * 1024 + j0;
    *(float4*)&s1p[off] = make_float4(A1[0], A1[1], A1[2], A1[3]);
    *(float4*)&s2p[off] = make_float4(A2[0], A2[1], A2[2], A2[3]);
}

// ---------------- pipelined tensor-core fused attention ----------------------
// scores pre-scaled by log2e: p = bit ? ex2(lrelu(s1+s2) - 8*log2e) : 0
#define APAD 72
template <int MODE>
__global__ __launch_bounds__(256) void at_k(const __half* __restrict__ hT,
                                            const float* __restrict__ s1p,
                                            const float* __restrict__ s2p,
                                            const unsigned* __restrict__ mask,
                                            void* __restrict__ outp, int cstr) {
    const int TM = (MODE == 0) ? 128 : 64;
    const int MW = TM / 32;
    const int NW = 8 / MW;
    const int NSP = 128 / NW;
    const int N8 = NSP / 8;
    const int SC = TM / 8;
    const int LOGSC = (MODE == 0) ? 4 : 3;

    extern __shared__ char smraw[];
    __half* Ps = (__half*)smraw;
    __half* Vs = Ps + 2 * TM * APAD;
    float* s1s = (float*)(Vs + 2 * 128 * APAD);
    float* ds = s1s + TM;
    float* s2s = ds + TM;

    int tid = threadIdx.x, bx = blockIdx.x, z = blockIdx.z;
    int b, h;
    if (MODE == 0) { b = z >> 3; h = z & 7; }
    else { b = z; h = 0; }
    int i0 = bx * TM;
    const __half* hz = hT + (size_t)z * 131072;
    const unsigned* maskb = mask + (size_t)b * 1024 * 32;

    {
        float4 v = make_float4(0.f, 0.f, 0.f, 0.f);
#pragma unroll
        for (int c = 0; c < 4; c++) {
            float4 p = ((const float4*)(s2p + (size_t)c * cstr + (size_t)z * 1024))[tid];
            v.x += p.x; v.y += p.y; v.z += p.z; v.w += p.w;
        }
        ((float4*)s2s)[tid] = v;
        if (tid < TM) {
            float s = 0.f;
#pragma unroll
            for (int c = 0; c < 4; c++)
                s += s1p[(size_t)c * cstr + (size_t)z * 1024 + i0 + tid];
            s1s[tid] = s;
        }
    }
    __syncthreads();

    int w = tid >> 5, lane = tid & 31;
    int mw = w % MW, nw = w / MW;
    int wm = mw * 32, wn = nw * NSP;
    int ar = (lane & 7) | (((lane >> 3) & 1) << 3);
    int akh = (lane >> 4) << 3;
    int bn = ((lane >> 4) << 3) | (lane & 7);
    int bkh = ((lane >> 3) & 1) << 3;

    float acc[2][N8][4];
#pragma unroll
    for (int mt = 0; mt < 2; mt++)
#pragma unroll
        for (int n8 = 0; n8 < N8; n8++)
#pragma unroll
            for (int e = 0; e < 4; e++) acc[mt][n8][e] = 0.f;
    float dl[SC];
#pragma unroll
    for (int s = 0; s < SC; s++) dl[s] = 0.f;

    int bitpos = (2 * lane) & 31;

    auto issueV = [&](int buf, int j0) {
        __half* vb = Vs + buf * 128 * APAD;
#pragma unroll
        for (int q = 0; q < 4; q++) {
            int f = tid + q * 256;
            int row = f >> 3, c8 = f & 7;
            cpa16(&vb[row * APAD + c8 * 8],
                  hz + (size_t)row * 1024 + j0 + c8 * 8);
        }
        cpa_commit();
    };
    // warp-cooperative mask load: lane l holds word (s = l & (SC-1), wsel = l>>LOGSC)
    auto loadMaskW = [&](int j0) -> unsigned {
        int s = lane & (SC - 1);
        int wsel = (lane >> LOGSC) & 1;
        return maskb[((size_t)(i0 + w + s * 8) << 5) + (j0 >> 5) + wsel];
    };
    auto computeP = [&](int buf, int j0, unsigned mpre) {
        __half* pb = Ps + buf * TM * APAD;
        float s2a = s2s[j0 + 2 * lane];
        float s2b = s2s[j0 + 2 * lane + 1];
#pragma unroll
        for (int s = 0; s < SC; s++) {
            int i = w + s * 8;
            unsigned m = __shfl_sync(0xffffffffu, mpre,
                                     ((lane >> 4) << LOGSC) | s);
            unsigned two = (m >> bitpos) & 3u;
            float s1v = s1s[i];
            float e1 = s1v + s2a;
            e1 = e1 > 0.f ? e1 : ALPHA * e1;
            float e2 = s1v + s2b;
            e2 = e2 > 0.f ? e2 : ALPHA * e2;
            float p1 = (two & 1u) ? ex2a(e1 - EXPSH) : 0.f;
            float p2 = (two & 2u) ? ex2a(e2 - EXPSH) : 0.f;
            *(half2*)&pb[i * APAD + 2 * lane] = __floats2half2_rn(p1, p2);
            dl[s] += p1 + p2;
        }
    };

    unsigned mpre = loadMaskW(0);
    issueV(0, 0);
    computeP(0, 0, mpre);

    for (int t = 0; t < 16; t++) {
        int cb = t & 1, nb = cb ^ 1;
        cpa_wait0();
        __syncthreads();
        if (t < 15) {
            issueV(nb, (t + 1) * 64);
            mpre = loadMaskW((t + 1) * 64);
        }
        const __half* pb = Ps + cb * TM * APAD;
        const __half* vb = Vs + cb * 128 * APAD;
#pragma unroll
        for (int kk = 0; kk < 64; kk += 16) {
            unsigned af[2][4], bf[N8 / 2][4];
            ldsm4(af[0], &pb[(wm + ar) * APAD + kk + akh]);
            ldsm4(af[1], &pb[(wm + 16 + ar) * APAD + kk + akh]);
#pragma unroll
            for (int np = 0; np < N8 / 2; np++)
                ldsm4(bf[np], &vb[(wn + np * 16 + bn) * APAD + kk + bkh]);
#pragma unroll
            for (int mt = 0; mt < 2; mt++)
#pragma unroll
                for (int n8 = 0; n8 < N8; n8++)
                    mma16816(acc[mt][n8], af[mt], &bf[n8 >> 1][(n8 & 1) * 2],
                             acc[mt][n8]);
        }
        if (t < 15) computeP(nb, (t + 1) * 64, mpre);
    }

#pragma unroll
    for (int s = 0; s < SC; s++) {
        float v = dl[s];
#pragma unroll
        for (int o = 16; o; o >>= 1) v += __shfl_xor_sync(0xffffffffu, v, o);
        if (lane == 0) ds[s * 8 + w] = v;
    }
    __syncthreads();

    int r0 = lane >> 2, cc = (lane & 3) * 2;
#pragma unroll
    for (int mt = 0; mt < 2; mt++)
#pragma unroll
        for (int n8 = 0; n8 < N8; n8++) {
            int row0 = wm + mt * 16 + r0, row1 = row0 + 8;
            int col = wn + n8 * 8 + cc;
            float inv0 = 1.f / ds[row0], inv1 = 1.f / ds[row1];
            float f0 = acc[mt][n8][0] * inv0, f1 = acc[mt][n8][1] * inv0;
            float f2 = acc[mt][n8][2] * inv1, f3 = acc[mt][n8][3] * inv1;
            if (MODE == 0) {
                f0 = f0 > 0.f ? f0 : expm1f(f0);
                f1 = f1 > 0.f ? f1 : expm1f(f1);
                f2 = f2 > 0.f ? f2 : expm1f(f2);
                f3 = f3 > 0.f ? f3 : expm1f(f3);
                __half* x1 = (__half*)outp;
                *(half2*)&x1[((size_t)b * 1024 + i0 + row0) * 1024 + h * 128 + col] =
                    __floats2half2_rn(f0, f1);
                *(half2*)&x1[((size_t)b * 1024 + i0 + row1) * 1024 + h * 128 + col] =
                    __floats2half2_rn(f2, f3);
            } else {
                float* o2 = (float*)outp;
                *(float2*)&o2[((size_t)b * 1024 + i0 + row0) * 128 + col] =
                    make_float2(f0, f1);
                *(float2*)&o2[((size_t)b * 1024 + i0 + row1) * 128 + col] =
                    make_float2(f2, f3);
            }
        }
}

// ---------------- final fp32 gemm: relu((linp+att2+lin_b) @ ln_wT + ln_b) ----
__global__ void __launch_bounds__(256)
final_k(const float* __restrict__ A0, const float* __restrict__ B0,
        float* __restrict__ C0, const float* __restrict__ add,
        const float* __restrict__ biasA, const float* __restrict__ biasC) {
    const int BK = 32, BM = 64, RM = 4;
    __shared__ float As[BK][BM + 4];
    __shared__ float Bs[BK][128 + 4];
    int mblk = blockIdx.x * BM;
    int tid = threadIdx.x;
    int tx = tid % 16, ty = tid / 16;
    u64 acc[RM][4];
#pragma unroll
    for (int r = 0; r < RM; r++)
#pragma unroll
        for (int c = 0; c < 4; c++) acc[r][c] = 0ull;

    for (int k0 = 0; k0 < 128; k0 += BK) {
#pragma unroll
        for (int q = 0; q < BM / 32; q++) {
            int f = tid + q * 256;
            int m = f >> 3;
            int kk = (f & 7) * 4;
            const float* ap = A0 + (size_t)(mblk + m) * 128 + (k0 + kk);
            const float* dp = add + (size_t)(mblk + m) * 128 + (k0 + kk);
            const float* bp = biasA + (k0 + kk);
            float4 v;
            v.x = ap[0] + dp[0] + bp[0];
            v.y = ap[1] + dp[1] + bp[1];
            v.z = ap[2] + dp[2] + bp[2];
            v.w = ap[3] + dp[3] + bp[3];
            As[kk + 0][m] = v.x;
            As[kk + 1][m] = v.y;
            As[kk + 2][m] = v.z;
            As[kk + 3][m] = v.w;
        }
#pragma unroll
        for (int q = 0; q < 4; q++) {
            int f = tid + q * 256;
            int kk = f >> 5;
            int nn = (f & 31) * 4;
            *(float4*)&Bs[kk][nn] = *(const float4*)(B0 + (size_t)(k0 + kk) * 128 + nn);
        }
        __syncthreads();
#pragma unroll 8
        for (int kk = 0; kk < BK; kk++) {
            u64 as_[RM];
            float4 av = *(const float4*)&As[kk][ty * RM];
            as_[0] = splat2(av.x);
            as_[1] = splat2(av.y);
            as_[2] = splat2(av.z);
            as_[3] = splat2(av.w);
            ulonglong2 b0 = *(const ulonglong2*)&Bs[kk][tx * 4];
            ulonglong2 b1 = *(const ulonglong2*)&Bs[kk][64 + tx * 4];
            u64 bs_[4] = {b0.x, b0.y, b1.x, b1.y};
#pragma unroll
            for (int r = 0; r < RM; r++)
#pragma unroll
                for (int c = 0; c < 4; c++) acc[r][c] = fma2(as_[r], bs_[c], acc[r][c]);
        }
        __syncthreads();
    }
#pragma unroll
    for (int r = 0; r < RM; r++) {
        int gm = mblk + ty * RM + r;
        float* crow = C0 + (size_t)gm * 128;
        float2 p0 = unpack2(acc[r][0]);
        float2 p1 = unpack2(acc[r][1]);
        float2 p2 = unpack2(acc[r][2]);
        float2 p3 = unpack2(acc[r][3]);
        float v[8] = {p0.x, p0.y, p1.x, p1.y, p2.x, p2.y, p3.x, p3.y};
#pragma unroll
        for (int c = 0; c < 4; c++) {
            v[c] = v[c] + biasC[tx * 4 + c];
            v[c] = v[c] > 0.f ? v[c] : 0.f;
            v[c + 4] = v[c + 4] + biasC[64 + tx * 4 + c];
            v[c + 4] = v[c + 4] > 0.f ? v[c + 4] : 0.f;
        }
        *(float4*)&crow[tx * 4] = make_float4(v[0], v[1], v[2], v[3]);
        *(float4*)&crow[64 + tx * 4] = make_float4(v[4], v[5], v[6], v[7]);
    }
}

// ---------------- launch ------------------------------------------------------
extern "C" void kernel_launch(void* const* d_in, const int* in_sizes, int n_in,
                              void* d_out, int out_size) {
    (void)in_sizes; (void)n_in; (void)out_size;
    const float* inputs = (const float*)d_in[0];
    const int* adj = (const int*)d_in[1];
    const float* W_att = (const float*)d_in[3];
    const float* a_src = (const float*)d_in[4];
    const float* a_dst = (const float*)d_in[5];
    const float* W_out = (const float*)d_in[6];
    const float* ao_src = (const float*)d_in[7];
    const float* ao_dst = (const float*)d_in[8];
    const float* lin_w = (const float*)d_in[9];
    const float* lin_b = (const float*)d_in[10];
    const float* ln_w = (const float*)d_in[11];
    const float* ln_b = (const float*)d_in[12];

    __half *p_in16, *p_wattT, *p_h1T, *p_x1, *p_woutT, *p_linw16, *p_h2T;
    float *p_linp, *p_att2, *p_s1p, *p_s2p, *p_ln_wT;
    unsigned* p_mask;
    cudaGetSymbolAddress((void**)&p_in16, g_in16);
    cudaGetSymbolAddress((void**)&p_wattT, g_wattT);
    cudaGetSymbolAddress((void**)&p_h1T, g_h1T);
    cudaGetSymbolAddress((void**)&p_x1, g_x1);
    cudaGetSymbolAddress((void**)&p_woutT, g_woutT);
    cudaGetSymbolAddress((void**)&p_linw16, g_linw16);
    cudaGetSymbolAddress((void**)&p_h2T, g_h2T);
    cudaGetSymbolAddress((void**)&p_linp, g_linp);
    cudaGetSymbolAddress((void**)&p_att2, g_att2);
    cudaGetSymbolAddress((void**)&p_s1p, g_s1p);
    cudaGetSymbolAddress((void**)&p_s2p, g_s2p);
    cudaGetSymbolAddress((void**)&p_ln_wT, g_ln_wT);
    cudaGetSymbolAddress((void**)&p_mask, g_mask);

    const int AT0_SMEM = (2 * 128 * APAD + 2 * 128 * APAD) * 2 + (128 + 128 + 1024) * 4;
    const int AT1_SMEM = (2 * 64 * APAD + 2 * 128 * APAD) * 2 + (64 + 64 + 1024) * 4;
    cudaFuncSetAttribute(at_k<0>, cudaFuncAttributeMaxDynamicSharedMemorySize,
                         AT0_SMEM);
    cudaFuncSetAttribute(at_k<1>, cudaFuncAttributeMaxDynamicSharedMemorySize,
                         AT1_SMEM);

    // ---- ordered so at_k<0> is the 6th launch (ncu -s 5 -c 1) ----
    c2h_k<<<2048, 256>>>(inputs, p_in16, 2097152 / 4);                       // 0
    t2h_k<<<dim3(4, 8, 8), dim3(32, 8)>>>(W_att, p_wattT, 256, 128);         // 1
    tg_k<0><<<dim3(8, 1, 64), 256>>>(p_wattT, p_in16, p_h1T);                // 2
    packadj_k<<<8192, 256>>>(adj, p_mask);                                   // 3
    sdots_t<<<dim3(64, 4), 256>>>(p_h1T, a_src, a_dst, p_s1p, p_s2p, Hq,
                                  65536);                                    // 4
    at_k<0><<<dim3(8, 1, 64), 256, AT0_SMEM>>>(p_h1T, p_s1p, p_s2p, p_mask,
                                               p_x1, 65536);                 // 5
    c2h_k<<<128, 256>>>(lin_w, p_linw16, 131072 / 4);                        // 6
    t2h_k<<<dim3(4, 32, 1), dim3(32, 8)>>>(W_out, p_woutT, 1024, 128);       // 7
    transpose_k<<<dim3(4, 4), dim3(32, 8)>>>(ln_w, p_ln_wT, 128, 128);       // 8
    tg_k<1><<<dim3(16, 1, 8), 256>>>(p_woutT, p_x1, p_h2T);                  // 9
    tg_k<2><<<dim3(128, 1, 1), 256>>>(p_x1, p_linw16, p_linp);               // 10
    sdots_t<<<dim3(8, 4), 256>>>(p_h2T, ao_src, ao_dst, p_s1p, p_s2p, 1,
                                 8192);                                      // 11
    at_k<1><<<dim3(16, 1, 8), 256, AT1_SMEM>>>(p_h2T, p_s1p, p_s2p, p_mask,
                                               p_att2, 8192);                // 12
    final_k<<<128, 256>>>(p_linp, p_ln_wT, (float*)d_out, p_att2, lin_b, ln_b); // 13
}

// round 9
// speedup vs baseline: 4.2536x; 1.0813x over previous
#include <cuda_runtime.h>
#include <cuda_fp16.h>
#include <math.h>
#include <stdint.h>

#define ALPHA 0.2f
#define LOG2E 1.44269504f
#define EXPSH 11.54156036f   // 8 * log2(e)

static const int Bq = 8, Nq = 1024, Fq = 256, Oq = 128, Hq = 8;

typedef unsigned long long u64;

// ---------------- f32x2 helpers (final fp32 gemm only) -----------------------
__device__ __forceinline__ u64 fma2(u64 a, u64 b, u64 c) {
    u64 d;
    asm("fma.rn.f32x2 %0, %1, %2, %3;" : "=l"(d) : "l"(a), "l"(b), "l"(c));
    return d;
}
__device__ __forceinline__ u64 splat2(float x) {
    u64 d;
    unsigned u = __float_as_uint(x);
    asm("mov.b64 %0, {%1, %1};" : "=l"(d) : "r"(u));
    return d;
}
__device__ __forceinline__ float2 unpack2(u64 v) {
    unsigned lo, hi;
    asm("mov.b64 {%0, %1}, %2;" : "=r"(lo), "=r"(hi) : "l"(v));
    return make_float2(__uint_as_float(lo), __uint_as_float(hi));
}
__device__ __forceinline__ float ex2a(float x) {
    float y;
    asm("ex2.approx.ftz.f32 %0, %1;" : "=f"(y) : "f"(x));
    return y;
}

// ---------------- tensor-core helpers ---------------------------------------
__device__ __forceinline__ void ldsm4(unsigned* r, const void* p) {
    unsigned a = (unsigned)__cvta_generic_to_shared(p);
    asm volatile("ldmatrix.sync.aligned.m8n8.x4.shared.b16 {%0,%1,%2,%3}, [%4];"
                 : "=r"(r[0]), "=r"(r[1]), "=r"(r[2]), "=r"(r[3]) : "r"(a));
}
__device__ __forceinline__ void mma16816(float* d, const unsigned* a,
                                         const unsigned* b, const float* c) {
    asm volatile(
        "mma.sync.aligned.m16n8k16.row.col.f32.f16.f16.f32 "
        "{%0,%1,%2,%3},{%4,%5,%6,%7},{%8,%9},{%10,%11,%12,%13};"
        : "=f"(d[0]), "=f"(d[1]), "=f"(d[2]), "=f"(d[3])
        : "r"(a[0]), "r"(a[1]), "r"(a[2]), "r"(a[3]), "r"(b[0]), "r"(b[1]),
          "f"(c[0]), "f"(c[1]), "f"(c[2]), "f"(c[3]));
}
__device__ __forceinline__ void cpa16(void* smem_dst, const void* gsrc) {
    unsigned a = (unsigned)__cvta_generic_to_shared(smem_dst);
    asm volatile("cp.async.ca.shared.global [%0], [%1], 16;" :: "r"(a), "l"(gsrc));
}
__device__ __forceinline__ void cpa_commit() {
    asm volatile("cp.async.commit_group;" ::: "memory");
}
__device__ __forceinline__ void cpa_wait0() {
    asm volatile("cp.async.wait_group 0;" ::: "memory");
}

// ---------------- scratch ----------------------------------------------------
__device__ __half g_in16[(size_t)8192 * 256];
__device__ __half g_wattT[(size_t)8 * 128 * 256];
__device__ __half g_h1T[(size_t)64 * 128 * 1024];     // [z][o][j]
__device__ __half g_x1[(size_t)8192 * 1024];          // [b*N+n][h*O+o]
__device__ __half g_woutT[(size_t)128 * 1024];
__device__ __half g_linw16[(size_t)128 * 1024];
__device__ __half g_h2T[(size_t)8 * 128 * 1024];
__device__ float g_linp[(size_t)8192 * 128];
__device__ float g_att2[(size_t)8192 * 128];
__device__ float g_s1p[(size_t)4 * 65536];
__device__ float g_s2p[(size_t)4 * 65536];
__device__ float g_ln_wT[(size_t)128 * 128];
__device__ unsigned g_mask[(size_t)8 * 1024 * 32];    // adj bitmask, 1MB

// ---------------- prep kernels ----------------------------------------------
__global__ void c2h_k(const float* __restrict__ in, __half* __restrict__ out,
                      int n4) {
    int i = blockIdx.x * 256 + threadIdx.x;
    if (i < n4) {
        float4 v = ((const float4*)in)[i];
        half2 a = __floats2half2_rn(v.x, v.y);
        half2 b = __floats2half2_rn(v.z, v.w);
        uint2 o;
        o.x = *(unsigned*)&a;
        o.y = *(unsigned*)&b;
        *(uint2*)(out + (size_t)i * 4) = o;
    }
}

// adj -> bitmask: 16 ints/thread (4x int4), combine 2 lanes via shuffle
__global__ void packadj_k(const int* __restrict__ adj,
                          unsigned* __restrict__ mask) {
    int t = blockIdx.x * 256 + threadIdx.x;
    int lane = threadIdx.x & 31;
    const int4* p = (const int4*)adj + (size_t)t * 4;
    int4 a = p[0], b = p[1], c = p[2], d = p[3];
    unsigned bits = (a.x > 0 ? 1u : 0u) | (a.y > 0 ? 2u : 0u) |
                    (a.z > 0 ? 4u : 0u) | (a.w > 0 ? 8u : 0u) |
                    (b.x > 0 ? 16u : 0u) | (b.y > 0 ? 32u : 0u) |
                    (b.z > 0 ? 64u : 0u) | (b.w > 0 ? 128u : 0u) |
                    (c.x > 0 ? 256u : 0u) | (c.y > 0 ? 512u : 0u) |
                    (c.z > 0 ? 1024u : 0u) | (c.w > 0 ? 2048u : 0u) |
                    (d.x > 0 ? 4096u : 0u) | (d.y > 0 ? 8192u : 0u) |
                    (d.z > 0 ? 16384u : 0u) | (d.w > 0 ? 32768u : 0u);
    unsigned r = bits << ((lane & 1) * 16);
    r |= __shfl_xor_sync(0xffffffffu, r, 1);
    if ((lane & 1) == 0) mask[t >> 1] = r;
}

// in fp32 [z][R][C] -> out fp16 [z][C][R]
__global__ void t2h_k(const float* __restrict__ in, __half* __restrict__ out,
                      int R, int C) {
    __shared__ float t[32][33];
    int z = blockIdx.z;
    in += (size_t)z * R * C;
    out += (size_t)z * R * C;
    int c0 = blockIdx.x * 32, r0 = blockIdx.y * 32;
    int x = threadIdx.x, y = threadIdx.y;
    for (int i = y; i < 32; i += 8) t[i][x] = in[(size_t)(r0 + i) * C + c0 + x];
    __syncthreads();
    for (int i = y; i < 32; i += 8)
        out[(size_t)(c0 + i) * R + r0 + x] = __float2half_rn(t[x][i]);
}

__global__ void transpose_k(const float* __restrict__ in, float* __restrict__ out,
                            int R, int C) {
    __shared__ float t[32][33];
    int c0 = blockIdx.x * 32, r0 = blockIdx.y * 32;
    int x = threadIdx.x, y = threadIdx.y;
    for (int i = y; i < 32; i += 8) {
        int r = r0 + i, c = c0 + x;
        if (r < R && c < C) t[i][x] = in[(size_t)r * C + c];
    }
    __syncthreads();
    for (int i = y; i < 32; i += 8) {
        int c = c0 + i, r = r0 + x;
        if (c < C && r < R) out[(size_t)c * R + r] = t[x][i];
    }
}

// ---------------- tensor GEMM (mma.sync, cp.async double-buffered) ----------
// C = A @ Bt^T.  MODE 0: h1T; MODE 1: h2T; MODE 2: linp (fp32 out)
template <int MODE>
__global__ __launch_bounds__(256) void tg_k(const __half* __restrict__ Aroot,
                                            const __half* __restrict__ Btroot,
                                            void* __restrict__ Croot) {
    const int K = (MODE == 0) ? 256 : 1024;
    const int NIT = K / 64;
    const int TM = (MODE == 2) ? 64 : 128;
    const int TN = (MODE == 1) ? 64 : 128;
    const int MW = TM / 32;
    const int NW = 8 / MW;
    const int NSP = TN / NW;
    const int N8 = NSP / 8;
    const int PAD = 72;
    extern __shared__ __half smh[];
    __half* As = smh;                    // 2 * TM*PAD
    __half* Bs = smh + 2 * TM * PAD;     // 2 * TN*PAD
    int tid = threadIdx.x, bx = blockIdx.x, z = blockIdx.z;

    const __half* A;
    const __half* Bt;
    __half* Ch = nullptr;
    float* Cf = nullptr;
    int lda, ldb, n0 = 0;
    if (MODE == 0) {
        int b = z >> 3, h = z & 7;
        A = Aroot + (size_t)h * 128 * 256;
        lda = 256;
        Bt = Btroot + (size_t)b * 1024 * 256 + (size_t)bx * 128 * 256;
        ldb = 256;
        Ch = (__half*)Croot + (size_t)z * 131072;
        n0 = bx * 128;
    } else if (MODE == 1) {
        A = Aroot;
        lda = 1024;
        Bt = Btroot + (size_t)z * 1048576 + (size_t)bx * 64 * 1024;
        ldb = 1024;
        Ch = (__half*)Croot + (size_t)z * 131072;
        n0 = bx * 64;
    } else {
        A = Aroot + (size_t)bx * 64 * 1024;
        lda = 1024;
        Bt = Btroot;
        ldb = 1024;
        Cf = (float*)Croot + (size_t)bx * 64 * 128;
    }

    int w = tid >> 5, lane = tid & 31;
    int mw = w % MW, nw = w / MW;
    int wm = mw * 32, wn = nw * NSP;
    int ar = (lane & 7) | (((lane >> 3) & 1) << 3);
    int akh = (lane >> 4) << 3;
    int bn = ((lane >> 4) << 3) | (lane & 7);
    int bkh = ((lane >> 3) & 1) << 3;

    auto loadTiles = [&](int buf, int k0) {
        __half* ab = As + buf * TM * PAD;
        __half* bb = Bs + buf * TN * PAD;
#pragma unroll
        for (int q = 0; q < TM / 32; q++) {
            int f = tid + q * 256;
            int row = f >> 3, c8 = f & 7;
            cpa16(&ab[row * PAD + c8 * 8], A + (size_t)row * lda + k0 + c8 * 8);
        }
#pragma unroll
        for (int q = 0; q < TN / 32; q++) {
            int f = tid + q * 256;
            int row = f >> 3, c8 = f & 7;
            cpa16(&bb[row * PAD + c8 * 8], Bt + (size_t)row * ldb + k0 + c8 * 8);
        }
        cpa_commit();
    };

    float acc[2][N8][4];
#pragma unroll
    for (int mt = 0; mt < 2; mt++)
#pragma unroll
        for (int n8 = 0; n8 < N8; n8++)
#pragma unroll
            for (int e = 0; e < 4; e++) acc[mt][n8][e] = 0.f;

    loadTiles(0, 0);
    for (int it = 0; it < NIT; it++) {
        int cb = it & 1;
        cpa_wait0();
        __syncthreads();
        if (it + 1 < NIT) loadTiles(cb ^ 1, (it + 1) * 64);
        const __half* ab = As + cb * TM * PAD;
        const __half* bb = Bs + cb * TN * PAD;
#pragma unroll
        for (int kk = 0; kk < 64; kk += 16) {
            unsigned af[2][4], bf[N8 / 2][4];
            ldsm4(af[0], &ab[(wm + ar) * PAD + kk + akh]);
            ldsm4(af[1], &ab[(wm + 16 + ar) * PAD + kk + akh]);
#pragma unroll
            for (int np = 0; np < N8 / 2; np++)
                ldsm4(bf[np], &bb[(wn + np * 16 + bn) * PAD + kk + bkh]);
#pragma unroll
            for (int mt = 0; mt < 2; mt++)
#pragma unroll
                for (int n8 = 0; n8 < N8; n8++)
                    mma16816(acc[mt][n8], af[mt], &bf[n8 >> 1][(n8 & 1) * 2],
                             acc[mt][n8]);
        }
    }

    __syncthreads();
    int r0 = lane >> 2, cc = (lane & 3) * 2;
#pragma unroll
    for (int mt = 0; mt < 2; mt++)
#pragma unroll
        for (int n8 = 0; n8 < N8; n8++) {
            int row0 = wm + mt * 16 + r0;
            int col = wn + n8 * 8 + cc;
            if (MODE <= 1) {
                half2 lo = __floats2half2_rn(acc[mt][n8][0], acc[mt][n8][1]);
                half2 hi = __floats2half2_rn(acc[mt][n8][2], acc[mt][n8][3]);
                *(half2*)&Ch[(size_t)row0 * 1024 + n0 + col] = lo;
                *(half2*)&Ch[(size_t)(row0 + 8) * 1024 + n0 + col] = hi;
            } else {
                *(float2*)&Cf[(size_t)row0 * 128 + col] =
                    make_float2(acc[mt][n8][0], acc[mt][n8][1]);
                *(float2*)&Cf[(size_t)(row0 + 8) * 128 + col] =
                    make_float2(acc[mt][n8][2], acc[mt][n8][3]);
            }
        }
}

// ---------------- s1/s2 partial dots (scaled by log2e) -----------------------
__global__ __launch_bounds__(256) void sdots_t(const __half* __restrict__ hT,
                                               const float* __restrict__ asrc,
                                               const float* __restrict__ adst,
                                               float* __restrict__ s1p,
                                               float* __restrict__ s2p, int hh,
                                               int cstr) {
    __shared__ float a1s[32], a2s[32];
    int z = blockIdx.x, oc = blockIdx.y, tid = threadIdx.x;
    int hidx = z % hh;
    if (tid < 32) a1s[tid] = asrc[hidx * 128 + oc * 32 + tid] * LOG2E;
    else if (tid < 64) a2s[tid - 32] = adst[hidx * 128 + oc * 32 + tid - 32] * LOG2E;
    __syncthreads();
    const __half* hz = hT + (size_t)z * 131072 + (size_t)oc * 32 * 1024;
    int j0 = tid * 4;
    float A1[4] = {0.f, 0.f, 0.f, 0.f}, A2[4] = {0.f, 0.f, 0.f, 0.f};
#pragma unroll 8
    for (int o = 0; o < 32; o++) {
        float v1 = a1s[o], v2 = a2s[o];
        uint2 raw = *(const uint2*)(hz + (size_t)o * 1024 + j0);
        half2 h0 = *(half2*)&raw.x;
        half2 h1 = *(half2*)&raw.y;
        float2 f0 = __half22float2(h0), f1 = __half22float2(h1);
        A1[0] += v1 * f0.x; A1[1] += v1 * f0.y;
        A1[2] += v1 * f1.x; A1[3] += v1 * f1.y;
        A2[0] += v2 * f0.x; A2[1] += v2 * f0.y;
        A2[2] += v2 * f1.x; A2[3] += v2 * f1.y;
    }
    size_t off = (size_t)oc * cstr + (size_t)z * 1024 + j0;
    *(float4*)&s1p[off] = make_float4(A1[0], A1[1], A1[2], A1[3]);
    *(float4*)&s2p[off] = make_float4(A2[0], A2[1], A2[2], A2[3]);
}

// ---------------- pipelined HMMA fused attention ------------------------------
// scores pre-scaled by log2e: p = bit ? ex2(lrelu(s1+s2) - 8*log2e) : 0
#define APAD 72
template <int MODE>
__global__ __launch_bounds__(256) void at_k(const __half* __restrict__ hT,
                                            const float* __restrict__ s1p,
                                            const float* __restrict__ s2p,
                                            const unsigned* __restrict__ mask,
                                            void* __restrict__ outp, int cstr) {
    const int TM = (MODE == 0) ? 128 : 64;
    const int MW = TM / 32;
    const int NW = 8 / MW;
    const int NSP = 128 / NW;
    const int N8 = NSP / 8;
    const int SC = TM / 8;
    const int LOGSC = (MODE == 0) ? 4 : 3;

    extern __shared__ char smraw[];
    __half* Ps = (__half*)smraw;
    __half* Vs = Ps + 2 * TM * APAD;
    float* s1s = (float*)(Vs + 2 * 128 * APAD);
    float* ds = s1s + TM;
    float* s2s = ds + TM;

    int tid = threadIdx.x, bx = blockIdx.x, z = blockIdx.z;
    int b, h;
    if (MODE == 0) { b = z >> 3; h = z & 7; }
    else { b = z; h = 0; }
    int i0 = bx * TM;
    const __half* hz = hT + (size_t)z * 131072;
    const unsigned* maskb = mask + (size_t)b * 32768;

    {
        float4 v = make_float4(0.f, 0.f, 0.f, 0.f);
#pragma unroll
        for (int c = 0; c < 4; c++) {
            float4 p = ((const float4*)(s2p + (size_t)c * cstr + (size_t)z * 1024))[tid];
            v.x += p.x; v.y += p.y; v.z += p.z; v.w += p.w;
        }
        ((float4*)s2s)[tid] = v;
        if (tid < TM) {
            float s = 0.f;
#pragma unroll
            for (int c = 0; c < 4; c++)
                s += s1p[(size_t)c * cstr + (size_t)z * 1024 + i0 + tid];
            s1s[tid] = s;
        }
    }
    __syncthreads();

    int w = tid >> 5, lane = tid & 31;
    int mw = w % MW, nw = w / MW;
    int wm = mw * 32, wn = nw * NSP;
    int ar = (lane & 7) | (((lane >> 3) & 1) << 3);
    int akh = (lane >> 4) << 3;
    int bn = ((lane >> 4) << 3) | (lane & 7);
    int bkh = ((lane >> 3) & 1) << 3;

    float acc[2][N8][4];
#pragma unroll
    for (int mt = 0; mt < 2; mt++)
#pragma unroll
        for (int n8 = 0; n8 < N8; n8++)
#pragma unroll
            for (int e = 0; e < 4; e++) acc[mt][n8][e] = 0.f;
    float dl[SC];
#pragma unroll
    for (int s = 0; s < SC; s++) dl[s] = 0.f;

    int bitpos = (2 * lane) & 31;

    auto issueV = [&](int buf, int j0) {
        __half* vb = Vs + buf * 128 * APAD;
#pragma unroll
        for (int q = 0; q < 4; q++) {
            int f = tid + q * 256;
            int row = f >> 3, c8 = f & 7;
            cpa16(&vb[row * APAD + c8 * 8],
                  hz + (size_t)row * 1024 + j0 + c8 * 8);
        }
        cpa_commit();
    };
    auto loadMaskW = [&](int j0) -> unsigned {
        int s = lane & (SC - 1);
        int wsel = (lane >> LOGSC) & 1;
        return maskb[((size_t)(i0 + w + s * 8) << 5) + (j0 >> 5) + wsel];
    };
    auto buildP = [&](int buf, int j0, unsigned mpre) {
        __half* pb = Ps + buf * TM * APAD;
        float s2a = s2s[j0 + 2 * lane];
        float s2b = s2s[j0 + 2 * lane + 1];
#pragma unroll
        for (int s = 0; s < SC; s++) {
            int i = w + s * 8;
            unsigned m = __shfl_sync(0xffffffffu, mpre, ((lane >> 4) << LOGSC) | s);
            unsigned two = (m >> bitpos) & 3u;
            float s1v = s1s[i];
            float e1 = s1v + s2a;
            e1 = e1 > 0.f ? e1 : ALPHA * e1;
            float e2 = s1v + s2b;
            e2 = e2 > 0.f ? e2 : ALPHA * e2;
            float p1 = (two & 1u) ? ex2a(e1 - EXPSH) : 0.f;
            float p2 = (two & 2u) ? ex2a(e2 - EXPSH) : 0.f;
            *(half2*)&pb[i * APAD + 2 * lane] = __floats2half2_rn(p1, p2);
            dl[s] += p1 + p2;
        }
    };

    unsigned mpre = loadMaskW(0);
    issueV(0, 0);
    buildP(0, 0, mpre);

    for (int t = 0; t < 16; t++) {
        int cb = t & 1, nb = cb ^ 1;
        cpa_wait0();
        __syncthreads();
        if (t < 15) {
            issueV(nb, (t + 1) * 64);
            mpre = loadMaskW((t + 1) * 64);
        }
        const __half* pb = Ps + cb * TM * APAD;
        const __half* vb = Vs + cb * 128 * APAD;
#pragma unroll
        for (int kk = 0; kk < 64; kk += 16) {
            unsigned af[2][4], bf[N8 / 2][4];
            ldsm4(af[0], &pb[(wm + ar) * APAD + kk + akh]);
            ldsm4(af[1], &pb[(wm + 16 + ar) * APAD + kk + akh]);
#pragma unroll
            for (int np = 0; np < N8 / 2; np++)
                ldsm4(bf[np], &vb[(wn + np * 16 + bn) * APAD + kk + bkh]);
#pragma unroll
            for (int mt = 0; mt < 2; mt++)
#pragma unroll
                for (int n8 = 0; n8 < N8; n8++)
                    mma16816(acc[mt][n8], af[mt], &bf[n8 >> 1][(n8 & 1) * 2],
                             acc[mt][n8]);
        }
        if (t < 15) buildP(nb, (t + 1) * 64, mpre);
    }

#pragma unroll
    for (int s = 0; s < SC; s++) {
        float v = dl[s];
#pragma unroll
        for (int o = 16; o; o >>= 1) v += __shfl_xor_sync(0xffffffffu, v, o);
        if (lane == 0) ds[s * 8 + w] = v;
    }
    __syncthreads();

    int r0 = lane >> 2, cc = (lane & 3) * 2;
#pragma unroll
    for (int mt = 0; mt < 2; mt++)
#pragma unroll
        for (int n8 = 0; n8 < N8; n8++) {
            int row0 = wm + mt * 16 + r0, row1 = row0 + 8;
            int col = wn + n8 * 8 + cc;
            float inv0 = 1.f / ds[row0], inv1 = 1.f / ds[row1];
            float f0 = acc[mt][n8][0] * inv0, f1 = acc[mt][n8][1] * inv0;
            float f2 = acc[mt][n8][2] * inv1, f3 = acc[mt][n8][3] * inv1;
            if (MODE == 0) {
                f0 = f0 > 0.f ? f0 : expm1f(f0);
                f1 = f1 > 0.f ? f1 : expm1f(f1);
                f2 = f2 > 0.f ? f2 : expm1f(f2);
                f3 = f3 > 0.f ? f3 : expm1f(f3);
                __half* x1 = (__half*)outp;
                *(half2*)&x1[((size_t)b * 1024 + i0 + row0) * 1024 + h * 128 + col] =
                    __floats2half2_rn(f0, f1);
                *(half2*)&x1[((size_t)b * 1024 + i0 + row1) * 1024 + h * 128 + col] =
                    __floats2half2_rn(f2, f3);
            } else {
                float* o2 = (float*)outp;
                *(float2*)&o2[((size_t)b * 1024 + i0 + row0) * 128 + col] =
                    make_float2(f0, f1);
                *(float2*)&o2[((size_t)b * 1024 + i0 + row1) * 128 + col] =
                    make_float2(f2, f3);
            }
        }
}

// ---------------- final fp32 gemm: relu((linp+att2+lin_b) @ ln_wT + ln_b) ----
__global__ void __launch_bounds__(256)
final_k(const float* __restrict__ A0, const float* __restrict__ B0,
        float* __restrict__ C0, const float* __restrict__ add,
        const float* __restrict__ biasA, const float* __restrict__ biasC) {
    const int BK = 32, BM = 64, RM = 4;
    __shared__ float As[BK][BM + 4];
    __shared__ float Bs[BK][128 + 4];
    int mblk = blockIdx.x * BM;
    int tid = threadIdx.x;
    int tx = tid % 16, ty = tid / 16;
    u64 acc[RM][4];
#pragma unroll
    for (int r = 0; r < RM; r++)
#pragma unroll
        for (int c = 0; c < 4; c++) acc[r][c] = 0ull;

    for (int k0 = 0; k0 < 128; k0 += BK) {
#pragma unroll
        for (int q = 0; q < BM / 32; q++) {
            int f = tid + q * 256;
            int m = f >> 3;
            int kk = (f & 7) * 4;
            const float* ap = A0 + (size_t)(mblk + m) * 128 + (k0 + kk);
            const float* dp = add + (size_t)(mblk + m) * 128 + (k0 + kk);
            const float* bp = biasA + (k0 + kk);
            float4 v;
            v.x = ap[0] + dp[0] + bp[0];
            v.y = ap[1] + dp[1] + bp[1];
            v.z = ap[2] + dp[2] + bp[2];
            v.w = ap[3] + dp[3] + bp[3];
            As[kk + 0][m] = v.x;
            As[kk + 1][m] = v.y;
            As[kk + 2][m] = v.z;
            As[kk + 3][m] = v.w;
        }
#pragma unroll
        for (int q = 0; q < 4; q++) {
            int f = tid + q * 256;
            int kk = f >> 5;
            int nn = (f & 31) * 4;
            *(float4*)&Bs[kk][nn] = *(const float4*)(B0 + (size_t)(k0 + kk) * 128 + nn);
        }
        __syncthreads();
#pragma unroll 8
        for (int kk = 0; kk < BK; kk++) {
            u64 as_[RM];
            float4 av = *(const float4*)&As[kk][ty * RM];
            as_[0] = splat2(av.x);
            as_[1] = splat2(av.y);
            as_[2] = splat2(av.z);
            as_[3] = splat2(av.w);
            ulonglong2 b0 = *(const ulonglong2*)&Bs[kk][tx * 4];
            ulonglong2 b1 = *(const ulonglong2*)&Bs[kk][64 + tx * 4];
            u64 bs_[4] = {b0.x, b0.y, b1.x, b1.y};
#pragma unroll
            for (int r = 0; r < RM; r++)
#pragma unroll
                for (int c = 0; c < 4; c++) acc[r][c] = fma2(as_[r], bs_[c], acc[r][c]);
        }
        __syncthreads();
    }
#pragma unroll
    for (int r = 0; r < RM; r++) {
        int gm = mblk + ty * RM + r;
        float* crow = C0 + (size_t)gm * 128;
        float2 p0 = unpack2(acc[r][0]);
        float2 p1 = unpack2(acc[r][1]);
        float2 p2 = unpack2(acc[r][2]);
        float2 p3 = unpack2(acc[r][3]);
        float v[8] = {p0.x, p0.y, p1.x, p1.y, p2.x, p2.y, p3.x, p3.y};
#pragma unroll
        for (int c = 0; c < 4; c++) {
            v[c] = v[c] + biasC[tx * 4 + c];
            v[c] = v[c] > 0.f ? v[c] : 0.f;
            v[c + 4] = v[c + 4] + biasC[64 + tx * 4 + c];
            v[c + 4] = v[c + 4] > 0.f ? v[c + 4] : 0.f;
        }
        *(float4*)&crow[tx * 4] = make_float4(v[0], v[1], v[2], v[3]);
        *(float4*)&crow[64 + tx * 4] = make_float4(v[4], v[5], v[6], v[7]);
    }
}

// ---------------- launch ------------------------------------------------------
extern "C" void kernel_launch(void* const* d_in, const int* in_sizes, int n_in,
                              void* d_out, int out_size) {
    (void)in_sizes; (void)n_in; (void)out_size;
    const float* inputs = (const float*)d_in[0];
    const int* adj = (const int*)d_in[1];
    const float* W_att = (const float*)d_in[3];
    const float* a_src = (const float*)d_in[4];
    const float* a_dst = (const float*)d_in[5];
    const float* W_out = (const float*)d_in[6];
    const float* ao_src = (const float*)d_in[7];
    const float* ao_dst = (const float*)d_in[8];
    const float* lin_w = (const float*)d_in[9];
    const float* lin_b = (const float*)d_in[10];
    const float* ln_w = (const float*)d_in[11];
    const float* ln_b = (const float*)d_in[12];

    __half *p_in16, *p_wattT, *p_h1T, *p_x1, *p_woutT, *p_linw16, *p_h2T;
    float *p_linp, *p_att2, *p_s1p, *p_s2p, *p_ln_wT;
    unsigned* p_mask;
    cudaGetSymbolAddress((void**)&p_in16, g_in16);
    cudaGetSymbolAddress((void**)&p_wattT, g_wattT);
    cudaGetSymbolAddress((void**)&p_h1T, g_h1T);
    cudaGetSymbolAddress((void**)&p_x1, g_x1);
    cudaGetSymbolAddress((void**)&p_woutT, g_woutT);
    cudaGetSymbolAddress((void**)&p_linw16, g_linw16);
    cudaGetSymbolAddress((void**)&p_h2T, g_h2T);
    cudaGetSymbolAddress((void**)&p_linp, g_linp);
    cudaGetSymbolAddress((void**)&p_att2, g_att2);
    cudaGetSymbolAddress((void**)&p_s1p, g_s1p);
    cudaGetSymbolAddress((void**)&p_s2p, g_s2p);
    cudaGetSymbolAddress((void**)&p_ln_wT, g_ln_wT);
    cudaGetSymbolAddress((void**)&p_mask, g_mask);

    const int AT0_SMEM = (2 * 128 * APAD + 2 * 128 * APAD) * 2 + (128 + 128 + 1024) * 4;
    const int AT1_SMEM = (2 * 64 * APAD + 2 * 128 * APAD) * 2 + (64 + 64 + 1024) * 4;
    const int TG0_SMEM = 2 * (128 + 128) * 72 * 2;   // 73728
    const int TG1_SMEM = 2 * (128 + 64) * 72 * 2;    // 55296
    const int TG2_SMEM = 2 * (64 + 128) * 72 * 2;    // 55296
    cudaFuncSetAttribute(at_k<0>, cudaFuncAttributeMaxDynamicSharedMemorySize,
                         AT0_SMEM);
    cudaFuncSetAttribute(at_k<1>, cudaFuncAttributeMaxDynamicSharedMemorySize,
                         AT1_SMEM);
    cudaFuncSetAttribute(tg_k<0>, cudaFuncAttributeMaxDynamicSharedMemorySize,
                         TG0_SMEM);
    cudaFuncSetAttribute(tg_k<1>, cudaFuncAttributeMaxDynamicSharedMemorySize,
                         TG1_SMEM);
    cudaFuncSetAttribute(tg_k<2>, cudaFuncAttributeMaxDynamicSharedMemorySize,
                         TG2_SMEM);

    // ---- ordered so at_k<0> is the 6th launch (ncu -s 5 -c 1) ----
    c2h_k<<<2048, 256>>>(inputs, p_in16, 2097152 / 4);                       // 0
    t2h_k<<<dim3(4, 8, 8), dim3(32, 8)>>>(W_att, p_wattT, 256, 128);         // 1
    tg_k<0><<<dim3(8, 1, 64), 256, TG0_SMEM>>>(p_wattT, p_in16, p_h1T);      // 2
    packadj_k<<<2048, 256>>>(adj, p_mask);                                   // 3
    sdots_t<<<dim3(64, 4), 256>>>(p_h1T, a_src, a_dst, p_s1p, p_s2p, Hq,
                                  65536);                                    // 4
    at_k<0><<<dim3(8, 1, 64), 256, AT0_SMEM>>>(p_h1T, p_s1p, p_s2p, p_mask,
                                               p_x1, 65536);                 // 5
    c2h_k<<<128, 256>>>(lin_w, p_linw16, 131072 / 4);                        // 6
    t2h_k<<<dim3(4, 32, 1), dim3(32, 8)>>>(W_out, p_woutT, 1024, 128);       // 7
    transpose_k<<<dim3(4, 4), dim3(32, 8)>>>(ln_w, p_ln_wT, 128, 128);       // 8
    tg_k<1><<<dim3(16, 1, 8), 256, TG1_SMEM>>>(p_woutT, p_x1, p_h2T);        // 9
    tg_k<2><<<dim3(128, 1, 1), 256, TG2_SMEM>>>(p_x1, p_linw16, p_linp);     // 10
    sdots_t<<<dim3(8, 4), 256>>>(p_h2T, ao_src, ao_dst, p_s1p, p_s2p, 1,
                                 8192);                                      // 11
    at_k<1><<<dim3(16, 1, 8), 256, AT1_SMEM>>>(p_h2T, p_s1p, p_s2p, p_mask,
                                               p_att2, 8192);                // 12
    final_k<<<128, 256>>>(p_linp, p_ln_wT, (float*)d_out, p_att2, lin_b, ln_b); // 13
}

// round 10
// speedup vs baseline: 4.4701x; 1.0509x over previous
#include <cuda_runtime.h>
#include <cuda_fp16.h>
#include <math.h>
#include <stdint.h>

#define ALPHA 0.2f
#define LOG2E 1.44269504f
#define EXPSH 11.54156036f   // 8 * log2(e)

static const int Bq = 8, Nq = 1024, Fq = 256, Oq = 128, Hq = 8;

typedef unsigned long long u64;

// ---------------- f32x2 helpers (final fp32 gemm only) -----------------------
__device__ __forceinline__ u64 fma2(u64 a, u64 b, u64 c) {
    u64 d;
    asm("fma.rn.f32x2 %0, %1, %2, %3;" : "=l"(d) : "l"(a), "l"(b), "l"(c));
    return d;
}
__device__ __forceinline__ u64 splat2(float x) {
    u64 d;
    unsigned u = __float_as_uint(x);
    asm("mov.b64 %0, {%1, %1};" : "=l"(d) : "r"(u));
    return d;
}
__device__ __forceinline__ float2 unpack2(u64 v) {
    unsigned lo, hi;
    asm("mov.b64 {%0, %1}, %2;" : "=r"(lo), "=r"(hi) : "l"(v));
    return make_float2(__uint_as_float(lo), __uint_as_float(hi));
}
__device__ __forceinline__ float ex2a(float x) {
    float y;
    asm("ex2.approx.ftz.f32 %0, %1;" : "=f"(y) : "f"(x));
    return y;
}

// ---------------- tensor-core helpers ---------------------------------------
__device__ __forceinline__ void ldsm4(unsigned* r, const void* p) {
    unsigned a = (unsigned)__cvta_generic_to_shared(p);
    asm volatile("ldmatrix.sync.aligned.m8n8.x4.shared.b16 {%0,%1,%2,%3}, [%4];"
                 : "=r"(r[0]), "=r"(r[1]), "=r"(r[2]), "=r"(r[3]) : "r"(a));
}
__device__ __forceinline__ void mma16816(float* d, const unsigned* a,
                                         const unsigned* b, const float* c) {
    asm volatile(
        "mma.sync.aligned.m16n8k16.row.col.f32.f16.f16.f32 "
        "{%0,%1,%2,%3},{%4,%5,%6,%7},{%8,%9},{%10,%11,%12,%13};"
        : "=f"(d[0]), "=f"(d[1]), "=f"(d[2]), "=f"(d[3])
        : "r"(a[0]), "r"(a[1]), "r"(a[2]), "r"(a[3]), "r"(b[0]), "r"(b[1]),
          "f"(c[0]), "f"(c[1]), "f"(c[2]), "f"(c[3]));
}
__device__ __forceinline__ void cpa16(void* smem_dst, const void* gsrc) {
    unsigned a = (unsigned)__cvta_generic_to_shared(smem_dst);
    asm volatile("cp.async.ca.shared.global [%0], [%1], 16;" :: "r"(a), "l"(gsrc));
}
__device__ __forceinline__ void cpa_commit() {
    asm volatile("cp.async.commit_group;" ::: "memory");
}
__device__ __forceinline__ void cpa_wait0() {
    asm volatile("cp.async.wait_group 0;" ::: "memory");
}

// ---------------- scratch ----------------------------------------------------
__device__ __half g_in16[(size_t)8192 * 256];
__device__ __half g_wattT[(size_t)8 * 128 * 256];
__device__ __half g_h1T[(size_t)64 * 128 * 1024];     // [z][o][j]
__device__ __half g_x1[(size_t)8192 * 1024];          // [b*N+n][h*O+o]
__device__ __half g_woutT[(size_t)128 * 1024];
__device__ __half g_linw16[(size_t)128 * 1024];
__device__ __half g_h2T[(size_t)8 * 128 * 1024];
__device__ float g_linp[(size_t)8192 * 128];
__device__ float g_att2[(size_t)8192 * 128];
__device__ float g_s1[(size_t)64 * 1024];
__device__ float g_s2[(size_t)64 * 1024];
__device__ float g_s1b[(size_t)8 * 1024];
__device__ float g_s2b[(size_t)8 * 1024];
__device__ float g_ln_wT[(size_t)128 * 128];
__device__ unsigned g_mask[(size_t)8 * 1024 * 32];    // adj bitmask, 1MB

// ---------------- prep kernels ----------------------------------------------
__global__ void c2h_k(const float* __restrict__ in, __half* __restrict__ out,
                      int n4) {
    int i = blockIdx.x * 256 + threadIdx.x;
    if (i < n4) {
        float4 v = ((const float4*)in)[i];
        half2 a = __floats2half2_rn(v.x, v.y);
        half2 b = __floats2half2_rn(v.z, v.w);
        uint2 o;
        o.x = *(unsigned*)&a;
        o.y = *(unsigned*)&b;
        *(uint2*)(out + (size_t)i * 4) = o;
    }
}

// adj -> bitmask: 32 ints/thread (8x int4), direct word store, MLP=8
__global__ void packadj_k(const int* __restrict__ adj,
                          unsigned* __restrict__ mask) {
    int t = blockIdx.x * 256 + threadIdx.x;   // output word index
    const int4* p = (const int4*)adj + (size_t)t * 8;
    int4 v[8];
#pragma unroll
    for (int q = 0; q < 8; q++) v[q] = p[q];
    unsigned bits = 0;
#pragma unroll
    for (int q = 0; q < 8; q++) {
        bits |= (v[q].x > 0 ? 1u : 0u) << (q * 4);
        bits |= (v[q].y > 0 ? 2u : 0u) << (q * 4);
        bits |= (v[q].z > 0 ? 4u : 0u) << (q * 4);
        bits |= (v[q].w > 0 ? 8u : 0u) << (q * 4);
    }
    mask[t] = bits;
}

// in fp32 [z][R][C] -> out fp16 [z][C][R]
__global__ void t2h_k(const float* __restrict__ in, __half* __restrict__ out,
                      int R, int C) {
    __shared__ float t[32][33];
    int z = blockIdx.z;
    in += (size_t)z * R * C;
    out += (size_t)z * R * C;
    int c0 = blockIdx.x * 32, r0 = blockIdx.y * 32;
    int x = threadIdx.x, y = threadIdx.y;
    for (int i = y; i < 32; i += 8) t[i][x] = in[(size_t)(r0 + i) * C + c0 + x];
    __syncthreads();
    for (int i = y; i < 32; i += 8)
        out[(size_t)(c0 + i) * R + r0 + x] = __float2half_rn(t[x][i]);
}

__global__ void transpose_k(const float* __restrict__ in, float* __restrict__ out,
                            int R, int C) {
    __shared__ float t[32][33];
    int c0 = blockIdx.x * 32, r0 = blockIdx.y * 32;
    int x = threadIdx.x, y = threadIdx.y;
    for (int i = y; i < 32; i += 8) {
        int r = r0 + i, c = c0 + x;
        if (r < R && c < C) t[i][x] = in[(size_t)r * C + c];
    }
    __syncthreads();
    for (int i = y; i < 32; i += 8) {
        int c = c0 + i, r = r0 + x;
        if (c < C && r < R) out[(size_t)c * R + r] = t[x][i];
    }
}

// ---------------- tensor GEMM (mma.sync, cp.async double-buffered) ----------
// C = A @ Bt^T.  MODE 0: h1T (+fused s1/s2); MODE 1: h2T (+fused s1b/s2b);
// MODE 2: linp (fp32 out, no fusion)
template <int MODE>
__global__ __launch_bounds__(256) void tg_k(const __half* __restrict__ Aroot,
                                            const __half* __restrict__ Btroot,
                                            void* __restrict__ Croot,
                                            const float* __restrict__ asrc,
                                            const float* __restrict__ adst,
                                            float* __restrict__ s1g,
                                            float* __restrict__ s2g) {
    const int K = (MODE == 0) ? 256 : 1024;
    const int NIT = K / 64;
    const int TM = (MODE == 2) ? 64 : 128;
    const int TN = (MODE == 1) ? 64 : 128;
    const int MW = TM / 32;
    const int NW = 8 / MW;
    const int NSP = TN / NW;
    const int N8 = NSP / 8;
    const int PAD = 72;
    extern __shared__ __half smh[];
    __half* As = smh;                    // 2 * TM*PAD
    __half* Bs = smh + 2 * TM * PAD;     // 2 * TN*PAD
    int tid = threadIdx.x, bx = blockIdx.x, z = blockIdx.z;

    const __half* A;
    const __half* Bt;
    __half* Ch = nullptr;
    float* Cf = nullptr;
    int lda, ldb, n0 = 0, hsel = 0;
    if (MODE == 0) {
        int b = z >> 3, h = z & 7;
        hsel = h;
        A = Aroot + (size_t)h * 128 * 256;
        lda = 256;
        Bt = Btroot + (size_t)b * 1024 * 256 + (size_t)bx * 128 * 256;
        ldb = 256;
        Ch = (__half*)Croot + (size_t)z * 131072;
        n0 = bx * 128;
    } else if (MODE == 1) {
        A = Aroot;
        lda = 1024;
        Bt = Btroot + (size_t)z * 1048576 + (size_t)bx * 64 * 1024;
        ldb = 1024;
        Ch = (__half*)Croot + (size_t)z * 131072;
        n0 = bx * 64;
    } else {
        A = Aroot + (size_t)bx * 64 * 1024;
        lda = 1024;
        Bt = Btroot;
        ldb = 1024;
        Cf = (float*)Croot + (size_t)bx * 64 * 128;
    }

    int w = tid >> 5, lane = tid & 31;
    int mw = w % MW, nw = w / MW;
    int wm = mw * 32, wn = nw * NSP;
    int ar = (lane & 7) | (((lane >> 3) & 1) << 3);
    int akh = (lane >> 4) << 3;
    int bn = ((lane >> 4) << 3) | (lane & 7);
    int bkh = ((lane >> 3) & 1) << 3;

    auto loadTiles = [&](int buf, int k0) {
        __half* ab = As + buf * TM * PAD;
        __half* bb = Bs + buf * TN * PAD;
#pragma unroll
        for (int q = 0; q < TM / 32; q++) {
            int f = tid + q * 256;
            int row = f >> 3, c8 = f & 7;
            cpa16(&ab[row * PAD + c8 * 8], A + (size_t)row * lda + k0 + c8 * 8);
        }
#pragma unroll
        for (int q = 0; q < TN / 32; q++) {
            int f = tid + q * 256;
            int row = f >> 3, c8 = f & 7;
            cpa16(&bb[row * PAD + c8 * 8], Bt + (size_t)row * ldb + k0 + c8 * 8);
        }
        cpa_commit();
    };

    float acc[2][N8][4];
#pragma unroll
    for (int mt = 0; mt < 2; mt++)
#pragma unroll
        for (int n8 = 0; n8 < N8; n8++)
#pragma unroll
            for (int e = 0; e < 4; e++) acc[mt][n8][e] = 0.f;

    loadTiles(0, 0);
    for (int it = 0; it < NIT; it++) {
        int cb = it & 1;
        cpa_wait0();
        __syncthreads();
        if (it + 1 < NIT) loadTiles(cb ^ 1, (it + 1) * 64);
        const __half* ab = As + cb * TM * PAD;
        const __half* bb = Bs + cb * TN * PAD;
#pragma unroll
        for (int kk = 0; kk < 64; kk += 16) {
            unsigned af[2][4], bf[N8 / 2][4];
            ldsm4(af[0], &ab[(wm + ar) * PAD + kk + akh]);
            ldsm4(af[1], &ab[(wm + 16 + ar) * PAD + kk + akh]);
#pragma unroll
            for (int np = 0; np < N8 / 2; np++)
                ldsm4(bf[np], &bb[(wn + np * 16 + bn) * PAD + kk + bkh]);
#pragma unroll
            for (int mt = 0; mt < 2; mt++)
#pragma unroll
                for (int n8 = 0; n8 < N8; n8++)
                    mma16816(acc[mt][n8], af[mt], &bf[n8 >> 1][(n8 & 1) * 2],
                             acc[mt][n8]);
        }
    }

    __syncthreads();
    int r0 = lane >> 2, cc = (lane & 3) * 2;

    // C stores
#pragma unroll
    for (int mt = 0; mt < 2; mt++)
#pragma unroll
        for (int n8 = 0; n8 < N8; n8++) {
            int row0 = wm + mt * 16 + r0;
            int col = wn + n8 * 8 + cc;
            if (MODE <= 1) {
                half2 lo = __floats2half2_rn(acc[mt][n8][0], acc[mt][n8][1]);
                half2 hi = __floats2half2_rn(acc[mt][n8][2], acc[mt][n8][3]);
                *(half2*)&Ch[(size_t)row0 * 1024 + n0 + col] = lo;
                *(half2*)&Ch[(size_t)(row0 + 8) * 1024 + n0 + col] = hi;
            } else {
                *(float2*)&Cf[(size_t)row0 * 128 + col] =
                    make_float2(acc[mt][n8][0], acc[mt][n8][1]);
                *(float2*)&Cf[(size_t)(row0 + 8) * 128 + col] =
                    make_float2(acc[mt][n8][2], acc[mt][n8][3]);
            }
        }

    // fused s1/s2 (MODE<=1): s[j] = LOG2E * sum_o a[o] * h[o][j]
    if (MODE <= 1) {
        // rows this thread holds: wm+r0, wm+r0+8, wm+16+r0, wm+24+r0
        float a1r[4], a2r[4];
        int rws[4] = {wm + r0, wm + r0 + 8, wm + 16 + r0, wm + 24 + r0};
#pragma unroll
        for (int q = 0; q < 4; q++) {
            a1r[q] = asrc[hsel * 128 + rws[q]] * LOG2E;
            a2r[q] = adst[hsel * 128 + rws[q]] * LOG2E;
        }
        float* red = (float*)smh;   // reuse: MW * TN * 2 floats (<= 2KB..4KB)
#pragma unroll
        for (int n8 = 0; n8 < N8; n8++) {
            float s1lo = a1r[0] * acc[0][n8][0] + a1r[1] * acc[0][n8][2] +
                         a1r[2] * acc[1][n8][0] + a1r[3] * acc[1][n8][2];
            float s1hi = a1r[0] * acc[0][n8][1] + a1r[1] * acc[0][n8][3] +
                         a1r[2] * acc[1][n8][1] + a1r[3] * acc[1][n8][3];
            float s2lo = a2r[0] * acc[0][n8][0] + a2r[1] * acc[0][n8][2] +
                         a2r[2] * acc[1][n8][0] + a2r[3] * acc[1][n8][2];
            float s2hi = a2r[0] * acc[0][n8][1] + a2r[1] * acc[0][n8][3] +
                         a2r[2] * acc[1][n8][1] + a2r[3] * acc[1][n8][3];
#pragma unroll
            for (int o = 4; o < 32; o <<= 1) {
                s1lo += __shfl_xor_sync(0xffffffffu, s1lo, o);
                s1hi += __shfl_xor_sync(0xffffffffu, s1hi, o);
                s2lo += __shfl_xor_sync(0xffffffffu, s2lo, o);
                s2hi += __shfl_xor_sync(0xffffffffu, s2hi, o);
            }
            if (lane < 4) {
                int col = wn + n8 * 8 + lane * 2;
                red[(mw * TN + col) * 2 + 0] = s1lo;
                red[(mw * TN + col) * 2 + 1] = s2lo;
                red[(mw * TN + col + 1) * 2 + 0] = s1hi;
                red[(mw * TN + col + 1) * 2 + 1] = s2hi;
            }
        }
        __syncthreads();
        if (tid < TN) {
            float s1 = 0.f, s2 = 0.f;
#pragma unroll
            for (int m = 0; m < MW; m++) {
                s1 += red[(m * TN + tid) * 2 + 0];
                s2 += red[(m * TN + tid) * 2 + 1];
            }
            s1g[(size_t)z * 1024 + n0 + tid] = s1;
            s2g[(size_t)z * 1024 + n0 + tid] = s2;
        }
    }
}

// ---------------- pipelined HMMA fused attention ------------------------------
// scores pre-scaled by log2e: p = bit ? ex2(lrelu(s1+s2) - 8*log2e) : 0
#define APAD 72
template <int MODE>
__global__ __launch_bounds__(256) void at_k(const __half* __restrict__ hT,
                                            const float* __restrict__ s1g,
                                            const float* __restrict__ s2g,
                                            const unsigned* __restrict__ mask,
                                            void* __restrict__ outp) {
    const int TM = (MODE == 0) ? 128 : 64;
    const int MW = TM / 32;
    const int NW = 8 / MW;
    const int NSP = 128 / NW;
    const int N8 = NSP / 8;
    const int SC = TM / 8;
    const int LOGSC = (MODE == 0) ? 4 : 3;

    extern __shared__ char smraw[];
    __half* Ps = (__half*)smraw;
    __half* Vs = Ps + 2 * TM * APAD;
    float* s1s = (float*)(Vs + 2 * 128 * APAD);
    float* ds = s1s + TM;
    float* s2s = ds + TM;

    int tid = threadIdx.x, bx = blockIdx.x, z = blockIdx.z;
    int b, h;
    if (MODE == 0) { b = z >> 3; h = z & 7; }
    else { b = z; h = 0; }
    int i0 = bx * TM;
    const __half* hz = hT + (size_t)z * 131072;
    const unsigned* maskb = mask + (size_t)b * 32768;

    ((float4*)s2s)[tid] = ((const float4*)(s2g + (size_t)z * 1024))[tid];
    if (tid < TM) s1s[tid] = s1g[(size_t)z * 1024 + i0 + tid];
    __syncthreads();

    int w = tid >> 5, lane = tid & 31;
    int mw = w % MW, nw = w / MW;
    int wm = mw * 32, wn = nw * NSP;
    int ar = (lane & 7) | (((lane >> 3) & 1) << 3);
    int akh = (lane >> 4) << 3;
    int bn = ((lane >> 4) << 3) | (lane & 7);
    int bkh = ((lane >> 3) & 1) << 3;

    float acc[2][N8][4];
#pragma unroll
    for (int mt = 0; mt < 2; mt++)
#pragma unroll
        for (int n8 = 0; n8 < N8; n8++)
#pragma unroll
            for (int e = 0; e < 4; e++) acc[mt][n8][e] = 0.f;
    float dl[SC];
#pragma unroll
    for (int s = 0; s < SC; s++) dl[s] = 0.f;

    int bitpos = (2 * lane) & 31;

    auto issueV = [&](int buf, int j0) {
        __half* vb = Vs + buf * 128 * APAD;
#pragma unroll
        for (int q = 0; q < 4; q++) {
            int f = tid + q * 256;
            int row = f >> 3, c8 = f & 7;
            cpa16(&vb[row * APAD + c8 * 8],
                  hz + (size_t)row * 1024 + j0 + c8 * 8);
        }
        cpa_commit();
    };
    auto loadMaskW = [&](int j0) -> unsigned {
        int s = lane & (SC - 1);
        int wsel = (lane >> LOGSC) & 1;
        return maskb[((size_t)(i0 + w + s * 8) << 5) + (j0 >> 5) + wsel];
    };
    auto buildP = [&](int buf, int j0, unsigned mpre) {
        __half* pb = Ps + buf * TM * APAD;
        float s2a = s2s[j0 + 2 * lane];
        float s2b = s2s[j0 + 2 * lane + 1];
#pragma unroll
        for (int s = 0; s < SC; s++) {
            int i = w + s * 8;
            unsigned m = __shfl_sync(0xffffffffu, mpre, ((lane >> 4) << LOGSC) | s);
            unsigned two = (m >> bitpos) & 3u;
            float s1v = s1s[i];
            float e1 = s1v + s2a;
            e1 = e1 > 0.f ? e1 : ALPHA * e1;
            float e2 = s1v + s2b;
            e2 = e2 > 0.f ? e2 : ALPHA * e2;
            float p1 = (two & 1u) ? ex2a(e1 - EXPSH) : 0.f;
            float p2 = (two & 2u) ? ex2a(e2 - EXPSH) : 0.f;
            *(half2*)&pb[i * APAD + 2 * lane] = __floats2half2_rn(p1, p2);
            dl[s] += p1 + p2;
        }
    };

    unsigned mpre = loadMaskW(0);
    issueV(0, 0);
    buildP(0, 0, mpre);

    for (int t = 0; t < 16; t++) {
        int cb = t & 1, nb = cb ^ 1;
        cpa_wait0();
        __syncthreads();
        if (t < 15) {
            issueV(nb, (t + 1) * 64);
            mpre = loadMaskW((t + 1) * 64);
        }
        const __half* pb = Ps + cb * TM * APAD;
        const __half* vb = Vs + cb * 128 * APAD;
#pragma unroll
        for (int kk = 0; kk < 64; kk += 16) {
            unsigned af[2][4], bf[N8 / 2][4];
            ldsm4(af[0], &pb[(wm + ar) * APAD + kk + akh]);
            ldsm4(af[1], &pb[(wm + 16 + ar) * APAD + kk + akh]);
#pragma unroll
            for (int np = 0; np < N8 / 2; np++)
                ldsm4(bf[np], &vb[(wn + np * 16 + bn) * APAD + kk + bkh]);
#pragma unroll
            for (int mt = 0; mt < 2; mt++)
#pragma unroll
                for (int n8 = 0; n8 < N8; n8++)
                    mma16816(acc[mt][n8], af[mt], &bf[n8 >> 1][(n8 & 1) * 2],
                             acc[mt][n8]);
        }
        if (t < 15) buildP(nb, (t + 1) * 64, mpre);
    }

#pragma unroll
    for (int s = 0; s < SC; s++) {
        float v = dl[s];
#pragma unroll
        for (int o = 16; o; o >>= 1) v += __shfl_xor_sync(0xffffffffu, v, o);
        if (lane == 0) ds[s * 8 + w] = v;
    }
    __syncthreads();

    int r0 = lane >> 2, cc = (lane & 3) * 2;
#pragma unroll
    for (int mt = 0; mt < 2; mt++)
#pragma unroll
        for (int n8 = 0; n8 < N8; n8++) {
            int row0 = wm + mt * 16 + r0, row1 = row0 + 8;
            int col = wn + n8 * 8 + cc;
            float inv0 = 1.f / ds[row0], inv1 = 1.f / ds[row1];
            float f0 = acc[mt][n8][0] * inv0, f1 = acc[mt][n8][1] * inv0;
            float f2 = acc[mt][n8][2] * inv1, f3 = acc[mt][n8][3] * inv1;
            if (MODE == 0) {
                f0 = f0 > 0.f ? f0 : expm1f(f0);
                f1 = f1 > 0.f ? f1 : expm1f(f1);
                f2 = f2 > 0.f ? f2 : expm1f(f2);
                f3 = f3 > 0.f ? f3 : expm1f(f3);
                __half* x1 = (__half*)outp;
                *(half2*)&x1[((size_t)b * 1024 + i0 + row0) * 1024 + h * 128 + col] =
                    __floats2half2_rn(f0, f1);
                *(half2*)&x1[((size_t)b * 1024 + i0 + row1) * 1024 + h * 128 + col] =
                    __floats2half2_rn(f2, f3);
            } else {
                float* o2 = (float*)outp;
                *(float2*)&o2[((size_t)b * 1024 + i0 + row0) * 128 + col] =
                    make_float2(f0, f1);
                *(float2*)&o2[((size_t)b * 1024 + i0 + row1) * 128 + col] =
                    make_float2(f2, f3);
            }
        }
}

// ---------------- final fp32 gemm: relu((linp+att2+lin_b) @ ln_wT + ln_b) ----
__global__ void __launch_bounds__(256)
final_k(const float* __restrict__ A0, const float* __restrict__ B0,
        float* __restrict__ C0, const float* __restrict__ add,
        const float* __restrict__ biasA, const float* __restrict__ biasC) {
    const int BK = 32, BM = 64, RM = 4;
    __shared__ float As[BK][BM + 4];
    __shared__ float Bs[BK][128 + 4];
    int mblk = blockIdx.x * BM;
    int tid = threadIdx.x;
    int tx = tid % 16, ty = tid / 16;
    u64 acc[RM][4];
#pragma unroll
    for (int r = 0; r < RM; r++)
#pragma unroll
        for (int c = 0; c < 4; c++) acc[r][c] = 0ull;

    for (int k0 = 0; k0 < 128; k0 += BK) {
#pragma unroll
        for (int q = 0; q < BM / 32; q++) {
            int f = tid + q * 256;
            int m = f >> 3;
            int kk = (f & 7) * 4;
            const float* ap = A0 + (size_t)(mblk + m) * 128 + (k0 + kk);
            const float* dp = add + (size_t)(mblk + m) * 128 + (k0 + kk);
            const float* bp = biasA + (k0 + kk);
            float4 v;
            v.x = ap[0] + dp[0] + bp[0];
            v.y = ap[1] + dp[1] + bp[1];
            v.z = ap[2] + dp[2] + bp[2];
            v.w = ap[3] + dp[3] + bp[3];
            As[kk + 0][m] = v.x;
            As[kk + 1][m] = v.y;
            As[kk + 2][m] = v.z;
            As[kk + 3][m] = v.w;
        }
#pragma unroll
        for (int q = 0; q < 4; q++) {
            int f = tid + q * 256;
            int kk = f >> 5;
            int nn = (f & 31) * 4;
            *(float4*)&Bs[kk][nn] = *(const float4*)(B0 + (size_t)(k0 + kk) * 128 + nn);
        }
        __syncthreads();
#pragma unroll 8
        for (int kk = 0; kk < BK; kk++) {
            u64 as_[RM];
            float4 av = *(const float4*)&As[kk][ty * RM];
            as_[0] = splat2(av.x);
            as_[1] = splat2(av.y);
            as_[2] = splat2(av.z);
            as_[3] = splat2(av.w);
            ulonglong2 b0 = *(const ulonglong2*)&Bs[kk][tx * 4];
            ulonglong2 b1 = *(const ulonglong2*)&Bs[kk][64 + tx * 4];
            u64 bs_[4] = {b0.x, b0.y, b1.x, b1.y};
#pragma unroll
            for (int r = 0; r < RM; r++)
#pragma unroll
                for (int c = 0; c < 4; c++) acc[r][c] = fma2(as_[r], bs_[c], acc[r][c]);
        }
        __syncthreads();
    }
#pragma unroll
    for (int r = 0; r < RM; r++) {
        int gm = mblk + ty * RM + r;
        float* crow = C0 + (size_t)gm * 128;
        float2 p0 = unpack2(acc[r][0]);
        float2 p1 = unpack2(acc[r][1]);
        float2 p2 = unpack2(acc[r][2]);
        float2 p3 = unpack2(acc[r][3]);
        float v[8] = {p0.x, p0.y, p1.x, p1.y, p2.x, p2.y, p3.x, p3.y};
#pragma unroll
        for (int c = 0; c < 4; c++) {
            v[c] = v[c] + biasC[tx * 4 + c];
            v[c] = v[c] > 0.f ? v[c] : 0.f;
            v[c + 4] = v[c + 4] + biasC[64 + tx * 4 + c];
            v[c + 4] = v[c + 4] > 0.f ? v[c + 4] : 0.f;
        }
        *(float4*)&crow[tx * 4] = make_float4(v[0], v[1], v[2], v[3]);
        *(float4*)&crow[64 + tx * 4] = make_float4(v[4], v[5], v[6], v[7]);
    }
}

// ---------------- launch ------------------------------------------------------
extern "C" void kernel_launch(void* const* d_in, const int* in_sizes, int n_in,
                              void* d_out, int out_size) {
    (void)in_sizes; (void)n_in; (void)out_size;
    const float* inputs = (const float*)d_in[0];
    const int* adj = (const int*)d_in[1];
    const float* W_att = (const float*)d_in[3];
    const float* a_src = (const float*)d_in[4];
    const float* a_dst = (const float*)d_in[5];
    const float* W_out = (const float*)d_in[6];
    const float* ao_src = (const float*)d_in[7];
    const float* ao_dst = (const float*)d_in[8];
    const float* lin_w = (const float*)d_in[9];
    const float* lin_b = (const float*)d_in[10];
    const float* ln_w = (const float*)d_in[11];
    const float* ln_b = (const float*)d_in[12];

    __half *p_in16, *p_wattT, *p_h1T, *p_x1, *p_woutT, *p_linw16, *p_h2T;
    float *p_linp, *p_att2, *p_s1, *p_s2, *p_s1b, *p_s2b, *p_ln_wT;
    unsigned* p_mask;
    cudaGetSymbolAddress((void**)&p_in16, g_in16);
    cudaGetSymbolAddress((void**)&p_wattT, g_wattT);
    cudaGetSymbolAddress((void**)&p_h1T, g_h1T);
    cudaGetSymbolAddress((void**)&p_x1, g_x1);
    cudaGetSymbolAddress((void**)&p_woutT, g_woutT);
    cudaGetSymbolAddress((void**)&p_linw16, g_linw16);
    cudaGetSymbolAddress((void**)&p_h2T, g_h2T);
    cudaGetSymbolAddress((void**)&p_linp, g_linp);
    cudaGetSymbolAddress((void**)&p_att2, g_att2);
    cudaGetSymbolAddress((void**)&p_s1, g_s1);
    cudaGetSymbolAddress((void**)&p_s2, g_s2);
    cudaGetSymbolAddress((void**)&p_s1b, g_s1b);
    cudaGetSymbolAddress((void**)&p_s2b, g_s2b);
    cudaGetSymbolAddress((void**)&p_ln_wT, g_ln_wT);
    cudaGetSymbolAddress((void**)&p_mask, g_mask);

    const int AT0_SMEM = (2 * 128 * APAD + 2 * 128 * APAD) * 2 + (128 + 128 + 1024) * 4;
    const int AT1_SMEM = (2 * 64 * APAD + 2 * 128 * APAD) * 2 + (64 + 64 + 1024) * 4;
    const int TG0_SMEM = 2 * (128 + 128) * 72 * 2;   // 73728
    const int TG1_SMEM = 2 * (128 + 64) * 72 * 2;    // 55296
    const int TG2_SMEM = 2 * (64 + 128) * 72 * 2;    // 55296
    cudaFuncSetAttribute(at_k<0>, cudaFuncAttributeMaxDynamicSharedMemorySize,
                         AT0_SMEM);
    cudaFuncSetAttribute(at_k<1>, cudaFuncAttributeMaxDynamicSharedMemorySize,
                         AT1_SMEM);
    cudaFuncSetAttribute(tg_k<0>, cudaFuncAttributeMaxDynamicSharedMemorySize,
                         TG0_SMEM);
    cudaFuncSetAttribute(tg_k<1>, cudaFuncAttributeMaxDynamicSharedMemorySize,
                         TG1_SMEM);
    cudaFuncSetAttribute(tg_k<2>, cudaFuncAttributeMaxDynamicSharedMemorySize,
                         TG2_SMEM);

    // ---- ordered so at_k<0> is the 6th launch (ncu -s 5 -c 1) ----
    c2h_k<<<2048, 256>>>(inputs, p_in16, 2097152 / 4);                       // 0
    t2h_k<<<dim3(4, 8, 8), dim3(32, 8)>>>(W_att, p_wattT, 256, 128);         // 1
    tg_k<0><<<dim3(8, 1, 64), 256, TG0_SMEM>>>(p_wattT, p_in16, p_h1T,
                                               a_src, a_dst, p_s1, p_s2);    // 2
    packadj_k<<<1024, 256>>>(adj, p_mask);                                   // 3
    c2h_k<<<128, 256>>>(lin_w, p_linw16, 131072 / 4);                        // 4
    at_k<0><<<dim3(8, 1, 64), 256, AT0_SMEM>>>(p_h1T, p_s1, p_s2, p_mask,
                                               p_x1);                        // 5
    t2h_k<<<dim3(4, 32, 1), dim3(32, 8)>>>(W_out, p_woutT, 1024, 128);       // 6
    transpose_k<<<dim3(4, 4), dim3(32, 8)>>>(ln_w, p_ln_wT, 128, 128);       // 7
    tg_k<1><<<dim3(16, 1, 8), 256, TG1_SMEM>>>(p_woutT, p_x1, p_h2T,
                                               ao_src, ao_dst, p_s1b, p_s2b); // 8
    tg_k<2><<<dim3(128, 1, 1), 256, TG2_SMEM>>>(p_x1, p_linw16, p_linp,
                                                nullptr, nullptr, nullptr,
                                                nullptr);                    // 9
    at_k<1><<<dim3(16, 1, 8), 256, AT1_SMEM>>>(p_h2T, p_s1b, p_s2b, p_mask,
                                               p_att2);                      // 10
    final_k<<<128, 256>>>(p_linp, p_ln_wT, (float*)d_out, p_att2, lin_b, ln_b); // 11
}

// round 11
// speedup vs baseline: 4.6674x; 1.0441x over previous
#include <cuda_runtime.h>
#include <cuda_fp16.h>
#include <math.h>
#include <stdint.h>

#define ALPHA 0.2f
#define LOG2E 1.44269504f
#define EXPSH 11.54156036f   // 8 * log2(e)

static const int Bq = 8, Nq = 1024, Fq = 256, Oq = 128, Hq = 8;

typedef unsigned long long u64;

// ---------------- f32x2 helpers (final fp32 gemm only) -----------------------
__device__ __forceinline__ u64 fma2(u64 a, u64 b, u64 c) {
    u64 d;
    asm("fma.rn.f32x2 %0, %1, %2, %3;" : "=l"(d) : "l"(a), "l"(b), "l"(c));
    return d;
}
__device__ __forceinline__ u64 splat2(float x) {
    u64 d;
    unsigned u = __float_as_uint(x);
    asm("mov.b64 %0, {%1, %1};" : "=l"(d) : "r"(u));
    return d;
}
__device__ __forceinline__ float2 unpack2(u64 v) {
    unsigned lo, hi;
    asm("mov.b64 {%0, %1}, %2;" : "=r"(lo), "=r"(hi) : "l"(v));
    return make_float2(__uint_as_float(lo), __uint_as_float(hi));
}
__device__ __forceinline__ float ex2a(float x) {
    float y;
    asm("ex2.approx.ftz.f32 %0, %1;" : "=f"(y) : "f"(x));
    return y;
}

// ---------------- tensor-core helpers ---------------------------------------
__device__ __forceinline__ void ldsm4(unsigned* r, const void* p) {
    unsigned a = (unsigned)__cvta_generic_to_shared(p);
    asm volatile("ldmatrix.sync.aligned.m8n8.x4.shared.b16 {%0,%1,%2,%3}, [%4];"
                 : "=r"(r[0]), "=r"(r[1]), "=r"(r[2]), "=r"(r[3]) : "r"(a));
}
__device__ __forceinline__ void mma16816(float* d, const unsigned* a,
                                         const unsigned* b, const float* c) {
    asm volatile(
        "mma.sync.aligned.m16n8k16.row.col.f32.f16.f16.f32 "
        "{%0,%1,%2,%3},{%4,%5,%6,%7},{%8,%9},{%10,%11,%12,%13};"
        : "=f"(d[0]), "=f"(d[1]), "=f"(d[2]), "=f"(d[3])
        : "r"(a[0]), "r"(a[1]), "r"(a[2]), "r"(a[3]), "r"(b[0]), "r"(b[1]),
          "f"(c[0]), "f"(c[1]), "f"(c[2]), "f"(c[3]));
}
__device__ __forceinline__ void cpa16(void* smem_dst, const void* gsrc) {
    unsigned a = (unsigned)__cvta_generic_to_shared(smem_dst);
    asm volatile("cp.async.ca.shared.global [%0], [%1], 16;" :: "r"(a), "l"(gsrc));
}
__device__ __forceinline__ void cpa_commit() {
    asm volatile("cp.async.commit_group;" ::: "memory");
}
__device__ __forceinline__ void cpa_wait0() {
    asm volatile("cp.async.wait_group 0;" ::: "memory");
}

// ---------------- scratch ----------------------------------------------------
__device__ __half g_in16[(size_t)8192 * 256];
__device__ __half g_wattT[(size_t)8 * 128 * 256];
__device__ __half g_h1T[(size_t)64 * 128 * 1024];     // [z][o][j]
__device__ __half g_x1[(size_t)8192 * 1024];          // [b*N+n][h*O+o]
__device__ __half g_woutT[(size_t)128 * 1024];
__device__ __half g_linw16[(size_t)128 * 1024];
__device__ __half g_h2T[(size_t)8 * 128 * 1024];
__device__ float g_linp[(size_t)8192 * 128];
__device__ float g_att2[(size_t)8192 * 128];
__device__ float g_s1[(size_t)64 * 1024];
__device__ float g_s2[(size_t)64 * 1024];
__device__ float g_s1b[(size_t)8 * 1024];
__device__ float g_s2b[(size_t)8 * 1024];
__device__ float g_ln_wT[(size_t)128 * 128];
__device__ unsigned g_mask[(size_t)8 * 1024 * 32];    // adj bitmask, 1MB

// ---------------- prep kernels ----------------------------------------------
__global__ void c2h_k(const float* __restrict__ in, __half* __restrict__ out,
                      int n4) {
    int i = blockIdx.x * 256 + threadIdx.x;
    if (i < n4) {
        float4 v = ((const float4*)in)[i];
        half2 a = __floats2half2_rn(v.x, v.y);
        half2 b = __floats2half2_rn(v.z, v.w);
        uint2 o;
        o.x = *(unsigned*)&a;
        o.y = *(unsigned*)&b;
        *(uint2*)(out + (size_t)i * 4) = o;
    }
}

// adj -> bitmask: 16 ints/thread (4x int4), combine 2 lanes via shuffle
__global__ void packadj_k(const int* __restrict__ adj,
                          unsigned* __restrict__ mask) {
    int t = blockIdx.x * 256 + threadIdx.x;
    int lane = threadIdx.x & 31;
    const int4* p = (const int4*)adj + (size_t)t * 4;
    int4 a = p[0], b = p[1], c = p[2], d = p[3];
    unsigned bits = (a.x > 0 ? 1u : 0u) | (a.y > 0 ? 2u : 0u) |
                    (a.z > 0 ? 4u : 0u) | (a.w > 0 ? 8u : 0u) |
                    (b.x > 0 ? 16u : 0u) | (b.y > 0 ? 32u : 0u) |
                    (b.z > 0 ? 64u : 0u) | (b.w > 0 ? 128u : 0u) |
                    (c.x > 0 ? 256u : 0u) | (c.y > 0 ? 512u : 0u) |
                    (c.z > 0 ? 1024u : 0u) | (c.w > 0 ? 2048u : 0u) |
                    (d.x > 0 ? 4096u : 0u) | (d.y > 0 ? 8192u : 0u) |
                    (d.z > 0 ? 16384u : 0u) | (d.w > 0 ? 32768u : 0u);
    unsigned r = bits << ((lane & 1) * 16);
    r |= __shfl_xor_sync(0xffffffffu, r, 1);
    if ((lane & 1) == 0) mask[t >> 1] = r;
}

// ---- merged weight-prep: t2h(W_att), t2h(W_out), transpose(ln_w), c2h(lin_w)
__device__ void t2h_body(const float* in, __half* out, int R, int C,
                         int bx, int by, int tid, float* tbuf /*32*33*/) {
    int c0 = bx * 32, r0 = by * 32;
    int x = tid & 31, y = tid >> 5;
    for (int i = y; i < 32; i += 8)
        tbuf[i * 33 + x] = in[(size_t)(r0 + i) * C + c0 + x];
    __syncthreads();
    for (int i = y; i < 32; i += 8)
        out[(size_t)(c0 + i) * R + r0 + x] = __float2half_rn(tbuf[x * 33 + i]);
}

__global__ __launch_bounds__(256) void prep_k(
    const float* __restrict__ W_att, __half* __restrict__ wattT,
    const float* __restrict__ W_out, __half* __restrict__ woutT,
    const float* __restrict__ ln_w, float* __restrict__ ln_wT,
    const float* __restrict__ lin_w, __half* __restrict__ linw16) {
    __shared__ float tbuf[32 * 33];
    int bid = blockIdx.x, tid = threadIdx.x;
    if (bid < 256) {
        // t2h W_att: [z][256][128] -> [z][128][256]; orig grid (4, 8, 8)
        int z = bid >> 5, rem = bid & 31;
        int bx = rem & 3, by = rem >> 2;
        t2h_body(W_att + (size_t)z * 256 * 128, wattT + (size_t)z * 128 * 256,
                 256, 128, bx, by, tid, tbuf);
    } else if (bid < 384) {
        // t2h W_out: [1024][128] -> [128][1024]; orig grid (4, 32)
        int idx = bid - 256;
        int bx = idx & 3, by = idx >> 2;
        t2h_body(W_out, woutT, 1024, 128, bx, by, tid, tbuf);
    } else if (bid < 400) {
        // transpose ln_w: [128][128] -> [128][128] fp32; orig grid (4, 4)
        int idx = bid - 384;
        int bx = idx & 3, by = idx >> 2;
        int c0 = bx * 32, r0 = by * 32;
        int x = tid & 31, y = tid >> 5;
        for (int i = y; i < 32; i += 8)
            tbuf[i * 33 + x] = ln_w[(size_t)(r0 + i) * 128 + c0 + x];
        __syncthreads();
        for (int i = y; i < 32; i += 8)
            ln_wT[(size_t)(c0 + i) * 128 + r0 + x] = tbuf[x * 33 + i];
    } else {
        // c2h lin_w: 131072 floats = 32768 float4
        int i = (bid - 400) * 256 + tid;
        float4 v = ((const float4*)lin_w)[i];
        half2 a = __floats2half2_rn(v.x, v.y);
        half2 b = __floats2half2_rn(v.z, v.w);
        uint2 o;
        o.x = *(unsigned*)&a;
        o.y = *(unsigned*)&b;
        *(uint2*)(linw16 + (size_t)i * 4) = o;
    }
}

// ---------------- tensor GEMM (mma.sync, cp.async double-buffered) ----------
// C = A @ Bt^T.  MODE 0: h1T (+fused s1/s2); MODE 1: h2T (+fused s1b/s2b);
// MODE 2: linp (fp32 out, no fusion)
template <int MODE>
__global__ __launch_bounds__(256) void tg_k(const __half* __restrict__ Aroot,
                                            const __half* __restrict__ Btroot,
                                            void* __restrict__ Croot,
                                            const float* __restrict__ asrc,
                                            const float* __restrict__ adst,
                                            float* __restrict__ s1g,
                                            float* __restrict__ s2g) {
    const int K = (MODE == 0) ? 256 : 1024;
    const int NIT = K / 64;
    const int TM = (MODE == 2) ? 64 : 128;
    const int TN = (MODE == 1) ? 64 : 128;
    const int MW = TM / 32;
    const int NW = 8 / MW;
    const int NSP = TN / NW;
    const int N8 = NSP / 8;
    const int PAD = 72;
    extern __shared__ __half smh[];
    __half* As = smh;                    // 2 * TM*PAD
    __half* Bs = smh + 2 * TM * PAD;     // 2 * TN*PAD
    int tid = threadIdx.x, bx = blockIdx.x, z = blockIdx.z;

    const __half* A;
    const __half* Bt;
    __half* Ch = nullptr;
    float* Cf = nullptr;
    int lda, ldb, n0 = 0, hsel = 0;
    if (MODE == 0) {
        int b = z >> 3, h = z & 7;
        hsel = h;
        A = Aroot + (size_t)h * 128 * 256;
        lda = 256;
        Bt = Btroot + (size_t)b * 1024 * 256 + (size_t)bx * 128 * 256;
        ldb = 256;
        Ch = (__half*)Croot + (size_t)z * 131072;
        n0 = bx * 128;
    } else if (MODE == 1) {
        A = Aroot;
        lda = 1024;
        Bt = Btroot + (size_t)z * 1048576 + (size_t)bx * 64 * 1024;
        ldb = 1024;
        Ch = (__half*)Croot + (size_t)z * 131072;
        n0 = bx * 64;
    } else {
        A = Aroot + (size_t)bx * 64 * 1024;
        lda = 1024;
        Bt = Btroot;
        ldb = 1024;
        Cf = (float*)Croot + (size_t)bx * 64 * 128;
    }

    int w = tid >> 5, lane = tid & 31;
    int mw = w % MW, nw = w / MW;
    int wm = mw * 32, wn = nw * NSP;
    int ar = (lane & 7) | (((lane >> 3) & 1) << 3);
    int akh = (lane >> 4) << 3;
    int bn = ((lane >> 4) << 3) | (lane & 7);
    int bkh = ((lane >> 3) & 1) << 3;

    auto loadTiles = [&](int buf, int k0) {
        __half* ab = As + buf * TM * PAD;
        __half* bb = Bs + buf * TN * PAD;
#pragma unroll
        for (int q = 0; q < TM / 32; q++) {
            int f = tid + q * 256;
            int row = f >> 3, c8 = f & 7;
            cpa16(&ab[row * PAD + c8 * 8], A + (size_t)row * lda + k0 + c8 * 8);
        }
#pragma unroll
        for (int q = 0; q < TN / 32; q++) {
            int f = tid + q * 256;
            int row = f >> 3, c8 = f & 7;
            cpa16(&bb[row * PAD + c8 * 8], Bt + (size_t)row * ldb + k0 + c8 * 8);
        }
        cpa_commit();
    };

    float acc[2][N8][4];
#pragma unroll
    for (int mt = 0; mt < 2; mt++)
#pragma unroll
        for (int n8 = 0; n8 < N8; n8++)
#pragma unroll
            for (int e = 0; e < 4; e++) acc[mt][n8][e] = 0.f;

    loadTiles(0, 0);
    for (int it = 0; it < NIT; it++) {
        int cb = it & 1;
        cpa_wait0();
        __syncthreads();
        if (it + 1 < NIT) loadTiles(cb ^ 1, (it + 1) * 64);
        const __half* ab = As + cb * TM * PAD;
        const __half* bb = Bs + cb * TN * PAD;
#pragma unroll
        for (int kk = 0; kk < 64; kk += 16) {
            unsigned af[2][4], bf[N8 / 2][4];
            ldsm4(af[0], &ab[(wm + ar) * PAD + kk + akh]);
            ldsm4(af[1], &ab[(wm + 16 + ar) * PAD + kk + akh]);
#pragma unroll
            for (int np = 0; np < N8 / 2; np++)
                ldsm4(bf[np], &bb[(wn + np * 16 + bn) * PAD + kk + bkh]);
#pragma unroll
            for (int mt = 0; mt < 2; mt++)
#pragma unroll
                for (int n8 = 0; n8 < N8; n8++)
                    mma16816(acc[mt][n8], af[mt], &bf[n8 >> 1][(n8 & 1) * 2],
                             acc[mt][n8]);
        }
    }

    __syncthreads();
    int r0 = lane >> 2, cc = (lane & 3) * 2;

    // C stores
#pragma unroll
    for (int mt = 0; mt < 2; mt++)
#pragma unroll
        for (int n8 = 0; n8 < N8; n8++) {
            int row0 = wm + mt * 16 + r0;
            int col = wn + n8 * 8 + cc;
            if (MODE <= 1) {
                half2 lo = __floats2half2_rn(acc[mt][n8][0], acc[mt][n8][1]);
                half2 hi = __floats2half2_rn(acc[mt][n8][2], acc[mt][n8][3]);
                *(half2*)&Ch[(size_t)row0 * 1024 + n0 + col] = lo;
                *(half2*)&Ch[(size_t)(row0 + 8) * 1024 + n0 + col] = hi;
            } else {
                *(float2*)&Cf[(size_t)row0 * 128 + col] =
                    make_float2(acc[mt][n8][0], acc[mt][n8][1]);
                *(float2*)&Cf[(size_t)(row0 + 8) * 128 + col] =
                    make_float2(acc[mt][n8][2], acc[mt][n8][3]);
            }
        }

    // fused s1/s2 (MODE<=1): s[j] = LOG2E * sum_o a[o] * h[o][j]
    if (MODE <= 1) {
        float a1r[4], a2r[4];
        int rws[4] = {wm + r0, wm + r0 + 8, wm + 16 + r0, wm + 24 + r0};
#pragma unroll
        for (int q = 0; q < 4; q++) {
            a1r[q] = asrc[hsel * 128 + rws[q]] * LOG2E;
            a2r[q] = adst[hsel * 128 + rws[q]] * LOG2E;
        }
        float* red = (float*)smh;   // reuse smem
#pragma unroll
        for (int n8 = 0; n8 < N8; n8++) {
            float s1lo = a1r[0] * acc[0][n8][0] + a1r[1] * acc[0][n8][2] +
                         a1r[2] * acc[1][n8][0] + a1r[3] * acc[1][n8][2];
            float s1hi = a1r[0] * acc[0][n8][1] + a1r[1] * acc[0][n8][3] +
                         a1r[2] * acc[1][n8][1] + a1r[3] * acc[1][n8][3];
            float s2lo = a2r[0] * acc[0][n8][0] + a2r[1] * acc[0][n8][2] +
                         a2r[2] * acc[1][n8][0] + a2r[3] * acc[1][n8][2];
            float s2hi = a2r[0] * acc[0][n8][1] + a2r[1] * acc[0][n8][3] +
                         a2r[2] * acc[1][n8][1] + a2r[3] * acc[1][n8][3];
#pragma unroll
            for (int o = 4; o < 32; o <<= 1) {
                s1lo += __shfl_xor_sync(0xffffffffu, s1lo, o);
                s1hi += __shfl_xor_sync(0xffffffffu, s1hi, o);
                s2lo += __shfl_xor_sync(0xffffffffu, s2lo, o);
                s2hi += __shfl_xor_sync(0xffffffffu, s2hi, o);
            }
            if (lane < 4) {
                int col = wn + n8 * 8 + lane * 2;
                red[(mw * TN + col) * 2 + 0] = s1lo;
                red[(mw * TN + col) * 2 + 1] = s2lo;
                red[(mw * TN + col + 1) * 2 + 0] = s1hi;
                red[(mw * TN + col + 1) * 2 + 1] = s2hi;
            }
        }
        __syncthreads();
        if (tid < TN) {
            float s1 = 0.f, s2 = 0.f;
#pragma unroll
            for (int m = 0; m < MW; m++) {
                s1 += red[(m * TN + tid) * 2 + 0];
                s2 += red[(m * TN + tid) * 2 + 1];
            }
            s1g[(size_t)z * 1024 + n0 + tid] = s1;
            s2g[(size_t)z * 1024 + n0 + tid] = s2;
        }
    }
}

// ---------------- pipelined HMMA fused attention ------------------------------
// scores pre-scaled by log2e: p = bit ? ex2(lrelu(s1+s2) - 8*log2e) : 0
#define APAD 72
template <int MODE>
__global__ __launch_bounds__(256) void at_k(const __half* __restrict__ hT,
                                            const float* __restrict__ s1g,
                                            const float* __restrict__ s2g,
                                            const unsigned* __restrict__ mask,
                                            void* __restrict__ outp) {
    const int TM = (MODE == 0) ? 128 : 64;
    const int MW = TM / 32;
    const int NW = 8 / MW;
    const int NSP = 128 / NW;
    const int N8 = NSP / 8;
    const int SC = TM / 8;
    const int LOGSC = (MODE == 0) ? 4 : 3;

    extern __shared__ char smraw[];
    __half* Ps = (__half*)smraw;
    __half* Vs = Ps + 2 * TM * APAD;
    float* s1s = (float*)(Vs + 2 * 128 * APAD);
    float* ds = s1s + TM;
    float* s2s = ds + TM;

    int tid = threadIdx.x, bx = blockIdx.x, z = blockIdx.z;
    int b, h;
    if (MODE == 0) { b = z >> 3; h = z & 7; }
    else { b = z; h = 0; }
    int i0 = bx * TM;
    const __half* hz = hT + (size_t)z * 131072;
    const unsigned* maskb = mask + (size_t)b * 32768;

    ((float4*)s2s)[tid] = ((const float4*)(s2g + (size_t)z * 1024))[tid];
    if (tid < TM) s1s[tid] = s1g[(size_t)z * 1024 + i0 + tid];
    __syncthreads();

    int w = tid >> 5, lane = tid & 31;
    int mw = w % MW, nw = w / MW;
    int wm = mw * 32, wn = nw * NSP;
    int ar = (lane & 7) | (((lane >> 3) & 1) << 3);
    int akh = (lane >> 4) << 3;
    int bn = ((lane >> 4) << 3) | (lane & 7);
    int bkh = ((lane >> 3) & 1) << 3;

    float acc[2][N8][4];
#pragma unroll
    for (int mt = 0; mt < 2; mt++)
#pragma unroll
        for (int n8 = 0; n8 < N8; n8++)
#pragma unroll
            for (int e = 0; e < 4; e++) acc[mt][n8][e] = 0.f;
    float dl[SC];
#pragma unroll
    for (int s = 0; s < SC; s++) dl[s] = 0.f;

    int bitpos = (2 * lane) & 31;

    auto issueV = [&](int buf, int j0) {
        __half* vb = Vs + buf * 128 * APAD;
#pragma unroll
        for (int q = 0; q < 4; q++) {
            int f = tid + q * 256;
            int row = f >> 3, c8 = f & 7;
            cpa16(&vb[row * APAD + c8 * 8],
                  hz + (size_t)row * 1024 + j0 + c8 * 8);
        }
        cpa_commit();
    };
    auto loadMaskW = [&](int j0) -> unsigned {
        int s = lane & (SC - 1);
        int wsel = (lane >> LOGSC) & 1;
        return maskb[((size_t)(i0 + w + s * 8) << 5) + (j0 >> 5) + wsel];
    };
    auto buildP = [&](int buf, int j0, unsigned mpre) {
        __half* pb = Ps + buf * TM * APAD;
        float s2a = s2s[j0 + 2 * lane];
        float s2b = s2s[j0 + 2 * lane + 1];
#pragma unroll
        for (int s = 0; s < SC; s++) {
            int i = w + s * 8;
            unsigned m = __shfl_sync(0xffffffffu, mpre, ((lane >> 4) << LOGSC) | s);
            unsigned two = (m >> bitpos) & 3u;
            float s1v = s1s[i];
            float e1 = s1v + s2a;
            e1 = e1 > 0.f ? e1 : ALPHA * e1;
            float e2 = s1v + s2b;
            e2 = e2 > 0.f ? e2 : ALPHA * e2;
            float p1 = (two & 1u) ? ex2a(e1 - EXPSH) : 0.f;
            float p2 = (two & 2u) ? ex2a(e2 - EXPSH) : 0.f;
            *(half2*)&pb[i * APAD + 2 * lane] = __floats2half2_rn(p1, p2);
            dl[s] += p1 + p2;
        }
    };

    unsigned mpre = loadMaskW(0);
    issueV(0, 0);
    buildP(0, 0, mpre);

    for (int t = 0; t < 16; t++) {
        int cb = t & 1, nb = cb ^ 1;
        cpa_wait0();
        __syncthreads();
        if (t < 15) {
            issueV(nb, (t + 1) * 64);
            mpre = loadMaskW((t + 1) * 64);
        }
        const __half* pb = Ps + cb * TM * APAD;
        const __half* vb = Vs + cb * 128 * APAD;
#pragma unroll
        for (int kk = 0; kk < 64; kk += 16) {
            unsigned af[2][4], bf[N8 / 2][4];
            ldsm4(af[0], &pb[(wm + ar) * APAD + kk + akh]);
            ldsm4(af[1], &pb[(wm + 16 + ar) * APAD + kk + akh]);
#pragma unroll
            for (int np = 0; np < N8 / 2; np++)
                ldsm4(bf[np], &vb[(wn + np * 16 + bn) * APAD + kk + bkh]);
#pragma unroll
            for (int mt = 0; mt < 2; mt++)
#pragma unroll
                for (int n8 = 0; n8 < N8; n8++)
                    mma16816(acc[mt][n8], af[mt], &bf[n8 >> 1][(n8 & 1) * 2],
                             acc[mt][n8]);
        }
        if (t < 15) buildP(nb, (t + 1) * 64, mpre);
    }

#pragma unroll
    for (int s = 0; s < SC; s++) {
        float v = dl[s];
#pragma unroll
        for (int o = 16; o; o >>= 1) v += __shfl_xor_sync(0xffffffffu, v, o);
        if (lane == 0) ds[s * 8 + w] = v;
    }
    __syncthreads();

    int r0 = lane >> 2, cc = (lane & 3) * 2;
#pragma unroll
    for (int mt = 0; mt < 2; mt++)
#pragma unroll
        for (int n8 = 0; n8 < N8; n8++) {
            int row0 = wm + mt * 16 + r0, row1 = row0 + 8;
            int col = wn + n8 * 8 + cc;
            float inv0 = 1.f / ds[row0], inv1 = 1.f / ds[row1];
            float f0 = acc[mt][n8][0] * inv0, f1 = acc[mt][n8][1] * inv0;
            float f2 = acc[mt][n8][2] * inv1, f3 = acc[mt][n8][3] * inv1;
            if (MODE == 0) {
                f0 = f0 > 0.f ? f0 : expm1f(f0);
                f1 = f1 > 0.f ? f1 : expm1f(f1);
                f2 = f2 > 0.f ? f2 : expm1f(f2);
                f3 = f3 > 0.f ? f3 : expm1f(f3);
                __half* x1 = (__half*)outp;
                *(half2*)&x1[((size_t)b * 1024 + i0 + row0) * 1024 + h * 128 + col] =
                    __floats2half2_rn(f0, f1);
                *(half2*)&x1[((size_t)b * 1024 + i0 + row1) * 1024 + h * 128 + col] =
                    __floats2half2_rn(f2, f3);
            } else {
                float* o2 = (float*)outp;
                *(float2*)&o2[((size_t)b * 1024 + i0 + row0) * 128 + col] =
                    make_float2(f0, f1);
                *(float2*)&o2[((size_t)b * 1024 + i0 + row1) * 128 + col] =
                    make_float2(f2, f3);
            }
        }
}

// ---------------- final fp32 gemm: relu((linp+att2+lin_b) @ ln_wT + ln_b) ----
__global__ void __launch_bounds__(256)
final_k(const float* __restrict__ A0, const float* __restrict__ B0,
        float* __restrict__ C0, const float* __restrict__ add,
        const float* __restrict__ biasA, const float* __restrict__ biasC) {
    const int BK = 32, BM = 64, RM = 4;
    __shared__ float As[BK][BM + 4];
    __shared__ float Bs[BK][128 + 4];
    int mblk = blockIdx.x * BM;
    int tid = threadIdx.x;
    int tx = tid % 16, ty = tid / 16;
    u64 acc[RM][4];
#pragma unroll
    for (int r = 0; r < RM; r++)
#pragma unroll
        for (int c = 0; c < 4; c++) acc[r][c] = 0ull;

    for (int k0 = 0; k0 < 128; k0 += BK) {
#pragma unroll
        for (int q = 0; q < BM / 32; q++) {
            int f = tid + q * 256;
            int m = f >> 3;
            int kk = (f & 7) * 4;
            const float* ap = A0 + (size_t)(mblk + m) * 128 + (k0 + kk);
            const float* dp = add + (size_t)(mblk + m) * 128 + (k0 + kk);
            const float* bp = biasA + (k0 + kk);
            float4 v;
            v.x = ap[0] + dp[0] + bp[0];
            v.y = ap[1] + dp[1] + bp[1];
            v.z = ap[2] + dp[2] + bp[2];
            v.w = ap[3] + dp[3] + bp[3];
            As[kk + 0][m] = v.x;
            As[kk + 1][m] = v.y;
            As[kk + 2][m] = v.z;
            As[kk + 3][m] = v.w;
        }
#pragma unroll
        for (int q = 0; q < 4; q++) {
            int f = tid + q * 256;
            int kk = f >> 5;
            int nn = (f & 31) * 4;
            *(float4*)&Bs[kk][nn] = *(const float4*)(B0 + (size_t)(k0 + kk) * 128 + nn);
        }
        __syncthreads();
#pragma unroll 8
        for (int kk = 0; kk < BK; kk++) {
            u64 as_[RM];
            float4 av = *(const float4*)&As[kk][ty * RM];
            as_[0] = splat2(av.x);
            as_[1] = splat2(av.y);
            as_[2] = splat2(av.z);
            as_[3] = splat2(av.w);
            ulonglong2 b0 = *(const ulonglong2*)&Bs[kk][tx * 4];
            ulonglong2 b1 = *(const ulonglong2*)&Bs[kk][64 + tx * 4];
            u64 bs_[4] = {b0.x, b0.y, b1.x, b1.y};
#pragma unroll
            for (int r = 0; r < RM; r++)
#pragma unroll
                for (int c = 0; c < 4; c++) acc[r][c] = fma2(as_[r], bs_[c], acc[r][c]);
        }
        __syncthreads();
    }
#pragma unroll
    for (int r = 0; r < RM; r++) {
        int gm = mblk + ty * RM + r;
        float* crow = C0 + (size_t)gm * 128;
        float2 p0 = unpack2(acc[r][0]);
        float2 p1 = unpack2(acc[r][1]);
        float2 p2 = unpack2(acc[r][2]);
        float2 p3 = unpack2(acc[r][3]);
        float v[8] = {p0.x, p0.y, p1.x, p1.y, p2.x, p2.y, p3.x, p3.y};
#pragma unroll
        for (int c = 0; c < 4; c++) {
            v[c] = v[c] + biasC[tx * 4 + c];
            v[c] = v[c] > 0.f ? v[c] : 0.f;
            v[c + 4] = v[c + 4] + biasC[64 + tx * 4 + c];
            v[c + 4] = v[c + 4] > 0.f ? v[c + 4] : 0.f;
        }
        *(float4*)&crow[tx * 4] = make_float4(v[0], v[1], v[2], v[3]);
        *(float4*)&crow[64 + tx * 4] = make_float4(v[4], v[5], v[6], v[7]);
    }
}

// ---------------- launch ------------------------------------------------------
extern "C" void kernel_launch(void* const* d_in, const int* in_sizes, int n_in,
                              void* d_out, int out_size) {
    (void)in_sizes; (void)n_in; (void)out_size;
    const float* inputs = (const float*)d_in[0];
    const int* adj = (const int*)d_in[1];
    const float* W_att = (const float*)d_in[3];
    const float* a_src = (const float*)d_in[4];
    const float* a_dst = (const float*)d_in[5];
    const float* W_out = (const float*)d_in[6];
    const float* ao_src = (const float*)d_in[7];
    const float* ao_dst = (const float*)d_in[8];
    const float* lin_w = (const float*)d_in[9];
    const float* lin_b = (const float*)d_in[10];
    const float* ln_w = (const float*)d_in[11];
    const float* ln_b = (const float*)d_in[12];

    __half *p_in16, *p_wattT, *p_h1T, *p_x1, *p_woutT, *p_linw16, *p_h2T;
    float *p_linp, *p_att2, *p_s1, *p_s2, *p_s1b, *p_s2b, *p_ln_wT;
    unsigned* p_mask;
    cudaGetSymbolAddress((void**)&p_in16, g_in16);
    cudaGetSymbolAddress((void**)&p_wattT, g_wattT);
    cudaGetSymbolAddress((void**)&p_h1T, g_h1T);
    cudaGetSymbolAddress((void**)&p_x1, g_x1);
    cudaGetSymbolAddress((void**)&p_woutT, g_woutT);
    cudaGetSymbolAddress((void**)&p_linw16, g_linw16);
    cudaGetSymbolAddress((void**)&p_h2T, g_h2T);
    cudaGetSymbolAddress((void**)&p_linp, g_linp);
    cudaGetSymbolAddress((void**)&p_att2, g_att2);
    cudaGetSymbolAddress((void**)&p_s1, g_s1);
    cudaGetSymbolAddress((void**)&p_s2, g_s2);
    cudaGetSymbolAddress((void**)&p_s1b, g_s1b);
    cudaGetSymbolAddress((void**)&p_s2b, g_s2b);
    cudaGetSymbolAddress((void**)&p_ln_wT, g_ln_wT);
    cudaGetSymbolAddress((void**)&p_mask, g_mask);

    const int AT0_SMEM = (2 * 128 * APAD + 2 * 128 * APAD) * 2 + (128 + 128 + 1024) * 4;
    const int AT1_SMEM = (2 * 64 * APAD + 2 * 128 * APAD) * 2 + (64 + 64 + 1024) * 4;
    const int TG0_SMEM = 2 * (128 + 128) * 72 * 2;   // 73728
    const int TG1_SMEM = 2 * (128 + 64) * 72 * 2;    // 55296
    const int TG2_SMEM = 2 * (64 + 128) * 72 * 2;    // 55296
    cudaFuncSetAttribute(at_k<0>, cudaFuncAttributeMaxDynamicSharedMemorySize,
                         AT0_SMEM);
    cudaFuncSetAttribute(at_k<1>, cudaFuncAttributeMaxDynamicSharedMemorySize,
                         AT1_SMEM);
    cudaFuncSetAttribute(tg_k<0>, cudaFuncAttributeMaxDynamicSharedMemorySize,
                         TG0_SMEM);
    cudaFuncSetAttribute(tg_k<1>, cudaFuncAttributeMaxDynamicSharedMemorySize,
                         TG1_SMEM);
    cudaFuncSetAttribute(tg_k<2>, cudaFuncAttributeMaxDynamicSharedMemorySize,
                         TG2_SMEM);

    // ---- ordered so at_k<0> is the 6th launch (ncu -s 5 -c 1) ----
    prep_k<<<528, 256>>>(W_att, p_wattT, W_out, p_woutT, ln_w, p_ln_wT,
                         lin_w, p_linw16);                                   // 0
    c2h_k<<<2048, 256>>>(inputs, p_in16, 2097152 / 4);                       // 1
    tg_k<0><<<dim3(8, 1, 64), 256, TG0_SMEM>>>(p_wattT, p_in16, p_h1T,
                                               a_src, a_dst, p_s1, p_s2);    // 2
    packadj_k<<<2048, 256>>>(adj, p_mask);                                   // 3
    at_k<0><<<dim3(8, 1, 64), 256, AT0_SMEM>>>(p_h1T, p_s1, p_s2, p_mask,
                                               p_x1);                        // 4
    tg_k<1><<<dim3(16, 1, 8), 256, TG1_SMEM>>>(p_woutT, p_x1, p_h2T,
                                               ao_src, ao_dst, p_s1b, p_s2b); // 5
    tg_k<2><<<dim3(128, 1, 1), 256, TG2_SMEM>>>(p_x1, p_linw16, p_linp,
                                                nullptr, nullptr, nullptr,
                                                nullptr);                    // 6
    at_k<1><<<dim3(16, 1, 8), 256, AT1_SMEM>>>(p_h2T, p_s1b, p_s2b, p_mask,
                                               p_att2);                      // 7
    final_k<<<128, 256>>>(p_linp, p_ln_wT, (float*)d_out, p_att2, lin_b, ln_b); // 8
}

// round 13
// speedup vs baseline: 4.7740x; 1.0228x over previous
#include <cuda_runtime.h>
#include <cuda_fp16.h>
#include <math.h>
#include <stdint.h>

#define ALPHA 0.2f
#define LOG2E 1.44269504f
#define EXPSH 11.54156036f   // 8 * log2(e)

static const int Bq = 8, Nq = 1024, Fq = 256, Oq = 128, Hq = 8;

typedef unsigned long long u64;

// ---------------- f32x2 helpers (final fp32 gemm only) -----------------------
__device__ __forceinline__ u64 fma2(u64 a, u64 b, u64 c) {
    u64 d;
    asm("fma.rn.f32x2 %0, %1, %2, %3;" : "=l"(d) : "l"(a), "l"(b), "l"(c));
    return d;
}
__device__ __forceinline__ u64 splat2(float x) {
    u64 d;
    unsigned u = __float_as_uint(x);
    asm("mov.b64 %0, {%1, %1};" : "=l"(d) : "r"(u));
    return d;
}
__device__ __forceinline__ float2 unpack2(u64 v) {
    unsigned lo, hi;
    asm("mov.b64 {%0, %1}, %2;" : "=r"(lo), "=r"(hi) : "l"(v));
    return make_float2(__uint_as_float(lo), __uint_as_float(hi));
}
__device__ __forceinline__ float ex2a(float x) {
    float y;
    asm("ex2.approx.ftz.f32 %0, %1;" : "=f"(y) : "f"(x));
    return y;
}

// ---------------- tensor-core helpers ---------------------------------------
__device__ __forceinline__ void ldsm4(unsigned* r, const void* p) {
    unsigned a = (unsigned)__cvta_generic_to_shared(p);
    asm volatile("ldmatrix.sync.aligned.m8n8.x4.shared.b16 {%0,%1,%2,%3}, [%4];"
                 : "=r"(r[0]), "=r"(r[1]), "=r"(r[2]), "=r"(r[3]) : "r"(a));
}
__device__ __forceinline__ void mma16816(float* d, const unsigned* a,
                                         const unsigned* b, const float* c) {
    asm volatile(
        "mma.sync.aligned.m16n8k16.row.col.f32.f16.f16.f32 "
        "{%0,%1,%2,%3},{%4,%5,%6,%7},{%8,%9},{%10,%11,%12,%13};"
        : "=f"(d[0]), "=f"(d[1]), "=f"(d[2]), "=f"(d[3])
        : "r"(a[0]), "r"(a[1]), "r"(a[2]), "r"(a[3]), "r"(b[0]), "r"(b[1]),
          "f"(c[0]), "f"(c[1]), "f"(c[2]), "f"(c[3]));
}
__device__ __forceinline__ void cpa16(void* smem_dst, const void* gsrc) {
    unsigned a = (unsigned)__cvta_generic_to_shared(smem_dst);
    asm volatile("cp.async.ca.shared.global [%0], [%1], 16;" :: "r"(a), "l"(gsrc));
}
__device__ __forceinline__ void cpa_commit() {
    asm volatile("cp.async.commit_group;" ::: "memory");
}
__device__ __forceinline__ void cpa_wait0() {
    asm volatile("cp.async.wait_group 0;" ::: "memory");
}

// ---------------- scratch ----------------------------------------------------
__device__ __half g_in16[(size_t)8192 * 256];
__device__ __half g_wattT[(size_t)8 * 128 * 256];
__device__ __half g_h1T[(size_t)64 * 128 * 1024];     // [z][o][j]
__device__ __half g_x1[(size_t)8192 * 1024];          // [b*N+n][h*O+o]
__device__ __half g_woutT[(size_t)128 * 1024];
__device__ __half g_linw16[(size_t)128 * 1024];
__device__ __half g_h2T[(size_t)8 * 128 * 1024];
__device__ float g_linp[(size_t)8192 * 128];
__device__ float g_att2[(size_t)8192 * 128];
__device__ float g_s1[(size_t)64 * 1024];
__device__ float g_s2[(size_t)64 * 1024];
__device__ float g_s1b[(size_t)8 * 1024];
__device__ float g_s2b[(size_t)8 * 1024];
__device__ float g_ln_wT[(size_t)128 * 128];
__device__ unsigned g_mask[(size_t)8 * 1024 * 32];    // adj bitmask, 1MB

// ---------------- mega prep: packadj || c2h(inputs) || weight prep -----------
__device__ __forceinline__ void t2h_body(const float* in, __half* out, int R,
                                         int C, int bx, int by, int tid,
                                         float* tbuf /*32*33*/) {
    int c0 = bx * 32, r0 = by * 32;
    int x = tid & 31, y = tid >> 5;
    for (int i = y; i < 32; i += 8)
        tbuf[i * 33 + x] = in[(size_t)(r0 + i) * C + c0 + x];
    __syncthreads();
    for (int i = y; i < 32; i += 8)
        out[(size_t)(c0 + i) * R + r0 + x] = __float2half_rn(tbuf[x * 33 + i]);
}

__global__ __launch_bounds__(256) void mega_prep_k(
    const int* __restrict__ adj, unsigned* __restrict__ mask,
    const float* __restrict__ inputs, __half* __restrict__ in16,
    const float* __restrict__ W_att, __half* __restrict__ wattT,
    const float* __restrict__ W_out, __half* __restrict__ woutT,
    const float* __restrict__ ln_w, float* __restrict__ ln_wT,
    const float* __restrict__ lin_w, __half* __restrict__ linw16) {
    __shared__ float tbuf[32 * 33];
    int bid = blockIdx.x, tid = threadIdx.x;
    if (bid < 2048) {
        // packadj: 16 ints/thread (4x int4), combine 2 lanes via shuffle
        int t = bid * 256 + tid;
        int lane = tid & 31;
        const int4* p = (const int4*)adj + (size_t)t * 4;
        int4 a = p[0], b = p[1], c = p[2], d = p[3];
        unsigned bits = (a.x > 0 ? 1u : 0u) | (a.y > 0 ? 2u : 0u) |
                        (a.z > 0 ? 4u : 0u) | (a.w > 0 ? 8u : 0u) |
                        (b.x > 0 ? 16u : 0u) | (b.y > 0 ? 32u : 0u) |
                        (b.z > 0 ? 64u : 0u) | (b.w > 0 ? 128u : 0u) |
                        (c.x > 0 ? 256u : 0u) | (c.y > 0 ? 512u : 0u) |
                        (c.z > 0 ? 1024u : 0u) | (c.w > 0 ? 2048u : 0u) |
                        (d.x > 0 ? 4096u : 0u) | (d.y > 0 ? 8192u : 0u) |
                        (d.z > 0 ? 16384u : 0u) | (d.w > 0 ? 32768u : 0u);
        unsigned r = bits << ((lane & 1) * 16);
        r |= __shfl_xor_sync(0xffffffffu, r, 1);
        if ((lane & 1) == 0) mask[t >> 1] = r;
    } else if (bid < 4096) {
        // c2h inputs: 2097152 floats = 524288 float4
        int i = (bid - 2048) * 256 + tid;
        float4 v = ((const float4*)inputs)[i];
        half2 a = __floats2half2_rn(v.x, v.y);
        half2 b = __floats2half2_rn(v.z, v.w);
        uint2 o;
        o.x = *(unsigned*)&a;
        o.y = *(unsigned*)&b;
        *(uint2*)(in16 + (size_t)i * 4) = o;
    } else {
        int pb = bid - 4096;   // 0..527
        if (pb < 256) {
            int z = pb >> 5, rem = pb & 31;
            t2h_body(W_att + (size_t)z * 256 * 128,
                     wattT + (size_t)z * 128 * 256, 256, 128, rem & 3,
                     rem >> 2, tid, tbuf);
        } else if (pb < 384) {
            int idx = pb - 256;
            t2h_body(W_out, woutT, 1024, 128, idx & 3, idx >> 2, tid, tbuf);
        } else if (pb < 400) {
            int idx = pb - 384;
            int bx = idx & 3, by = idx >> 2;
            int c0 = bx * 32, r0 = by * 32;
            int x = tid & 31, y = tid >> 5;
            for (int i = y; i < 32; i += 8)
                tbuf[i * 33 + x] = ln_w[(size_t)(r0 + i) * 128 + c0 + x];
            __syncthreads();
            for (int i = y; i < 32; i += 8)
                ln_wT[(size_t)(c0 + i) * 128 + r0 + x] = tbuf[x * 33 + i];
        } else {
            int i = (pb - 400) * 256 + tid;
            float4 v = ((const float4*)lin_w)[i];
            half2 a = __floats2half2_rn(v.x, v.y);
            half2 b = __floats2half2_rn(v.z, v.w);
            uint2 o;
            o.x = *(unsigned*)&a;
            o.y = *(unsigned*)&b;
            *(uint2*)(linw16 + (size_t)i * 4) = o;
        }
    }
}

// ---------------- tensor GEMM (mma.sync, cp.async double-buffered) ----------
// C = A @ Bt^T.  MODE 0: h1T (+fused s1/s2); MODE 1: h2T (+fused s1b/s2b);
// MODE 2: linp (fp32 out, no fusion)
template <int MODE>
__global__ __launch_bounds__(256) void tg_k(const __half* __restrict__ Aroot,
                                            const __half* __restrict__ Btroot,
                                            void* __restrict__ Croot,
                                            const float* __restrict__ asrc,
                                            const float* __restrict__ adst,
                                            float* __restrict__ s1g,
                                            float* __restrict__ s2g) {
    const int K = (MODE == 0) ? 256 : 1024;
    const int NIT = K / 64;
    const int TM = (MODE == 2) ? 64 : 128;
    const int TN = (MODE == 1) ? 64 : 128;
    const int MW = TM / 32;
    const int NW = 8 / MW;
    const int NSP = TN / NW;
    const int N8 = NSP / 8;
    const int PAD = 72;
    extern __shared__ __half smh[];
    __half* As = smh;                    // 2 * TM*PAD
    __half* Bs = smh + 2 * TM * PAD;     // 2 * TN*PAD
    int tid = threadIdx.x, bx = blockIdx.x, z = blockIdx.z;

    const __half* A;
    const __half* Bt;
    __half* Ch = nullptr;
    float* Cf = nullptr;
    int lda, ldb, n0 = 0, hsel = 0;
    if (MODE == 0) {
        int b = z >> 3, h = z & 7;
        hsel = h;
        A = Aroot + (size_t)h * 128 * 256;
        lda = 256;
        Bt = Btroot + (size_t)b * 1024 * 256 + (size_t)bx * 128 * 256;
        ldb = 256;
        Ch = (__half*)Croot + (size_t)z * 131072;
        n0 = bx * 128;
    } else if (MODE == 1) {
        A = Aroot;
        lda = 1024;
        Bt = Btroot + (size_t)z * 1048576 + (size_t)bx * 64 * 1024;
        ldb = 1024;
        Ch = (__half*)Croot + (size_t)z * 131072;
        n0 = bx * 64;
    } else {
        A = Aroot + (size_t)bx * 64 * 1024;
        lda = 1024;
        Bt = Btroot;
        ldb = 1024;
        Cf = (float*)Croot + (size_t)bx * 64 * 128;
    }

    int w = tid >> 5, lane = tid & 31;
    int mw = w % MW, nw = w / MW;
    int wm = mw * 32, wn = nw * NSP;
    int ar = (lane & 7) | (((lane >> 3) & 1) << 3);
    int akh = (lane >> 4) << 3;
    int bn = ((lane >> 4) << 3) | (lane & 7);
    int bkh = ((lane >> 3) & 1) << 3;

    auto loadTiles = [&](int buf, int k0) {
        __half* ab = As + buf * TM * PAD;
        __half* bb = Bs + buf * TN * PAD;
#pragma unroll
        for (int q = 0; q < TM / 32; q++) {
            int f = tid + q * 256;
            int row = f >> 3, c8 = f & 7;
            cpa16(&ab[row * PAD + c8 * 8], A + (size_t)row * lda + k0 + c8 * 8);
        }
#pragma unroll
        for (int q = 0; q < TN / 32; q++) {
            int f = tid + q * 256;
            int row = f >> 3, c8 = f & 7;
            cpa16(&bb[row * PAD + c8 * 8], Bt + (size_t)row * ldb + k0 + c8 * 8);
        }
        cpa_commit();
    };

    float acc[2][N8][4];
#pragma unroll
    for (int mt = 0; mt < 2; mt++)
#pragma unroll
        for (int n8 = 0; n8 < N8; n8++)
#pragma unroll
            for (int e = 0; e < 4; e++) acc[mt][n8][e] = 0.f;

    loadTiles(0, 0);
    for (int it = 0; it < NIT; it++) {
        int cb = it & 1;
        cpa_wait0();
        __syncthreads();
        if (it + 1 < NIT) loadTiles(cb ^ 1, (it + 1) * 64);
        const __half* ab = As + cb * TM * PAD;
        const __half* bb = Bs + cb * TN * PAD;
#pragma unroll
        for (int kk = 0; kk < 64; kk += 16) {
            unsigned af[2][4], bf[N8 / 2][4];
            ldsm4(af[0], &ab[(wm + ar) * PAD + kk + akh]);
            ldsm4(af[1], &ab[(wm + 16 + ar) * PAD + kk + akh]);
#pragma unroll
            for (int np = 0; np < N8 / 2; np++)
                ldsm4(bf[np], &bb[(wn + np * 16 + bn) * PAD + kk + bkh]);
#pragma unroll
            for (int mt = 0; mt < 2; mt++)
#pragma unroll
                for (int n8 = 0; n8 < N8; n8++)
                    mma16816(acc[mt][n8], af[mt], &bf[n8 >> 1][(n8 & 1) * 2],
                             acc[mt][n8]);
        }
    }

    __syncthreads();
    int r0 = lane >> 2, cc = (lane & 3) * 2;

    // C stores
#pragma unroll
    for (int mt = 0; mt < 2; mt++)
#pragma unroll
        for (int n8 = 0; n8 < N8; n8++) {
            int row0 = wm + mt * 16 + r0;
            int col = wn + n8 * 8 + cc;
            if (MODE <= 1) {
                half2 lo = __floats2half2_rn(acc[mt][n8][0], acc[mt][n8][1]);
                half2 hi = __floats2half2_rn(acc[mt][n8][2], acc[mt][n8][3]);
                *(half2*)&Ch[(size_t)row0 * 1024 + n0 + col] = lo;
                *(half2*)&Ch[(size_t)(row0 + 8) * 1024 + n0 + col] = hi;
            } else {
                *(float2*)&Cf[(size_t)row0 * 128 + col] =
                    make_float2(acc[mt][n8][0], acc[mt][n8][1]);
                *(float2*)&Cf[(size_t)(row0 + 8) * 128 + col] =
                    make_float2(acc[mt][n8][2], acc[mt][n8][3]);
            }
        }

    // fused s1/s2 (MODE<=1): s[j] = LOG2E * sum_o a[o] * h[o][j]
    if (MODE <= 1) {
        float a1r[4], a2r[4];
        int rws[4] = {wm + r0, wm + r0 + 8, wm + 16 + r0, wm + 24 + r0};
#pragma unroll
        for (int q = 0; q < 4; q++) {
            a1r[q] = asrc[hsel * 128 + rws[q]] * LOG2E;
            a2r[q] = adst[hsel * 128 + rws[q]] * LOG2E;
        }
        float* red = (float*)smh;   // reuse smem
#pragma unroll
        for (int n8 = 0; n8 < N8; n8++) {
            float s1lo = a1r[0] * acc[0][n8][0] + a1r[1] * acc[0][n8][2] +
                         a1r[2] * acc[1][n8][0] + a1r[3] * acc[1][n8][2];
            float s1hi = a1r[0] * acc[0][n8][1] + a1r[1] * acc[0][n8][3] +
                         a1r[2] * acc[1][n8][1] + a1r[3] * acc[1][n8][3];
            float s2lo = a2r[0] * acc[0][n8][0] + a2r[1] * acc[0][n8][2] +
                         a2r[2] * acc[1][n8][0] + a2r[3] * acc[1][n8][2];
            float s2hi = a2r[0] * acc[0][n8][1] + a2r[1] * acc[0][n8][3] +
                         a2r[2] * acc[1][n8][1] + a2r[3] * acc[1][n8][3];
#pragma unroll
            for (int o = 4; o < 32; o <<= 1) {
                s1lo += __shfl_xor_sync(0xffffffffu, s1lo, o);
                s1hi += __shfl_xor_sync(0xffffffffu, s1hi, o);
                s2lo += __shfl_xor_sync(0xffffffffu, s2lo, o);
                s2hi += __shfl_xor_sync(0xffffffffu, s2hi, o);
            }
            if (lane < 4) {
                int col = wn + n8 * 8 + lane * 2;
                red[(mw * TN + col) * 2 + 0] = s1lo;
                red[(mw * TN + col) * 2 + 1] = s2lo;
                red[(mw * TN + col + 1) * 2 + 0] = s1hi;
                red[(mw * TN + col + 1) * 2 + 1] = s2hi;
            }
        }
        __syncthreads();
        if (tid < TN) {
            float s1 = 0.f, s2 = 0.f;
#pragma unroll
            for (int m = 0; m < MW; m++) {
                s1 += red[(m * TN + tid) * 2 + 0];
                s2 += red[(m * TN + tid) * 2 + 1];
            }
            s1g[(size_t)z * 1024 + n0 + tid] = s1;
            s2g[(size_t)z * 1024 + n0 + tid] = s2;
        }
    }
}

// ---------------- pipelined HMMA fused attention ------------------------------
// scores pre-scaled by log2e: p = bit ? ex2(lrelu(s1+s2) - 8*log2e) : 0
#define APAD 72
template <int MODE>
__global__ __launch_bounds__(256) void at_k(const __half* __restrict__ hT,
                                            const float* __restrict__ s1g,
                                            const float* __restrict__ s2g,
                                            const unsigned* __restrict__ mask,
                                            void* __restrict__ outp) {
    const int TM = (MODE == 0) ? 128 : 64;
    const int MW = TM / 32;
    const int NW = 8 / MW;
    const int NSP = 128 / NW;
    const int N8 = NSP / 8;
    const int SC = TM / 8;
    const int LOGSC = (MODE == 0) ? 4 : 3;

    extern __shared__ char smraw[];
    __half* Ps = (__half*)smraw;
    __half* Vs = Ps + 2 * TM * APAD;
    float* s1s = (float*)(Vs + 2 * 128 * APAD);
    float* ds = s1s + TM;
    float* s2s = ds + TM;

    int tid = threadIdx.x, bx = blockIdx.x, z = blockIdx.z;
    int b, h;
    if (MODE == 0) { b = z >> 3; h = z & 7; }
    else { b = z; h = 0; }
    int i0 = bx * TM;
    const __half* hz = hT + (size_t)z * 131072;
    const unsigned* maskb = mask + (size_t)b * 32768;

    ((float4*)s2s)[tid] = ((const float4*)(s2g + (size_t)z * 1024))[tid];
    if (tid < TM) s1s[tid] = s1g[(size_t)z * 1024 + i0 + tid];
    __syncthreads();

    int w = tid >> 5, lane = tid & 31;
    int mw = w % MW, nw = w / MW;
    int wm = mw * 32, wn = nw * NSP;
    int ar = (lane & 7) | (((lane >> 3) & 1) << 3);
    int akh = (lane >> 4) << 3;
    int bn = ((lane >> 4) << 3) | (lane & 7);
    int bkh = ((lane >> 3) & 1) << 3;

    float acc[2][N8][4];
#pragma unroll
    for (int mt = 0; mt < 2; mt++)
#pragma unroll
        for (int n8 = 0; n8 < N8; n8++)
#pragma unroll
            for (int e = 0; e < 4; e++) acc[mt][n8][e] = 0.f;
    float dl[SC];
#pragma unroll
    for (int s = 0; s < SC; s++) dl[s] = 0.f;

    int bitpos = (2 * lane) & 31;

    auto issueV = [&](int buf, int j0) {
        __half* vb = Vs + buf * 128 * APAD;
#pragma unroll
        for (int q = 0; q < 4; q++) {
            int f = tid + q * 256;
            int row = f >> 3, c8 = f & 7;
            cpa16(&vb[row * APAD + c8 * 8],
                  hz + (size_t)row * 1024 + j0 + c8 * 8);
        }
        cpa_commit();
    };
    auto loadMaskW = [&](int j0) -> unsigned {
        int s = lane & (SC - 1);
        int wsel = (lane >> LOGSC) & 1;
        return maskb[((size_t)(i0 + w + s * 8) << 5) + (j0 >> 5) + wsel];
    };
    auto buildP = [&](int buf, int j0, unsigned mpre) {
        __half* pb = Ps + buf * TM * APAD;
        float s2a = s2s[j0 + 2 * lane];
        float s2b = s2s[j0 + 2 * lane + 1];
#pragma unroll
        for (int s = 0; s < SC; s++) {
            int i = w + s * 8;
            unsigned m = __shfl_sync(0xffffffffu, mpre, ((lane >> 4) << LOGSC) | s);
            unsigned two = (m >> bitpos) & 3u;
            float s1v = s1s[i];
            float e1 = s1v + s2a;
            e1 = e1 > 0.f ? e1 : ALPHA * e1;
            float e2 = s1v + s2b;
            e2 = e2 > 0.f ? e2 : ALPHA * e2;
            float p1 = (two & 1u) ? ex2a(e1 - EXPSH) : 0.f;
            float p2 = (two & 2u) ? ex2a(e2 - EXPSH) : 0.f;
            *(half2*)&pb[i * APAD + 2 * lane] = __floats2half2_rn(p1, p2);
            dl[s] += p1 + p2;
        }
    };

    unsigned mpre = loadMaskW(0);
    issueV(0, 0);
    buildP(0, 0, mpre);

    for (int t = 0; t < 16; t++) {
        int cb = t & 1, nb = cb ^ 1;
        cpa_wait0();
        __syncthreads();
        if (t < 15) {
            issueV(nb, (t + 1) * 64);
            mpre = loadMaskW((t + 1) * 64);
        }
        const __half* pb = Ps + cb * TM * APAD;
        const __half* vb = Vs + cb * 128 * APAD;
#pragma unroll
        for (int kk = 0; kk < 64; kk += 16) {
            unsigned af[2][4], bf[N8 / 2][4];
            ldsm4(af[0], &pb[(wm + ar) * APAD + kk + akh]);
            ldsm4(af[1], &pb[(wm + 16 + ar) * APAD + kk + akh]);
#pragma unroll
            for (int np = 0; np < N8 / 2; np++)
                ldsm4(bf[np], &vb[(wn + np * 16 + bn) * APAD + kk + bkh]);
#pragma unroll
            for (int mt = 0; mt < 2; mt++)
#pragma unroll
                for (int n8 = 0; n8 < N8; n8++)
                    mma16816(acc[mt][n8], af[mt], &bf[n8 >> 1][(n8 & 1) * 2],
                             acc[mt][n8]);
        }
        if (t < 15) buildP(nb, (t + 1) * 64, mpre);
    }

#pragma unroll
    for (int s = 0; s < SC; s++) {
        float v = dl[s];
#pragma unroll
        for (int o = 16; o; o >>= 1) v += __shfl_xor_sync(0xffffffffu, v, o);
        if (lane == 0) ds[s * 8 + w] = v;
    }
    __syncthreads();

    int r0 = lane >> 2, cc = (lane & 3) * 2;
#pragma unroll
    for (int mt = 0; mt < 2; mt++)
#pragma unroll
        for (int n8 = 0; n8 < N8; n8++) {
            int row0 = wm + mt * 16 + r0, row1 = row0 + 8;
            int col = wn + n8 * 8 + cc;
            float inv0 = 1.f / ds[row0], inv1 = 1.f / ds[row1];
            float f0 = acc[mt][n8][0] * inv0, f1 = acc[mt][n8][1] * inv0;
            float f2 = acc[mt][n8][2] * inv1, f3 = acc[mt][n8][3] * inv1;
            if (MODE == 0) {
                f0 = f0 > 0.f ? f0 : expm1f(f0);
                f1 = f1 > 0.f ? f1 : expm1f(f1);
                f2 = f2 > 0.f ? f2 : expm1f(f2);
                f3 = f3 > 0.f ? f3 : expm1f(f3);
                __half* x1 = (__half*)outp;
                *(half2*)&x1[((size_t)b * 1024 + i0 + row0) * 1024 + h * 128 + col] =
                    __floats2half2_rn(f0, f1);
                *(half2*)&x1[((size_t)b * 1024 + i0 + row1) * 1024 + h * 128 + col] =
                    __floats2half2_rn(f2, f3);
            } else {
                float* o2 = (float*)outp;
                *(float2*)&o2[((size_t)b * 1024 + i0 + row0) * 128 + col] =
                    make_float2(f0, f1);
                *(float2*)&o2[((size_t)b * 1024 + i0 + row1) * 128 + col] =
                    make_float2(f2, f3);
            }
        }
}

// ---------------- final fp32 gemm: relu((linp+att2+lin_b) @ ln_wT + ln_b) ----
__global__ void __launch_bounds__(256)
final_k(const float* __restrict__ A0, const float* __restrict__ B0,
        float* __restrict__ C0, const float* __restrict__ add,
        const float* __restrict__ biasA, const float* __restrict__ biasC) {
    const int BK = 32, BM = 64, RM = 4;
    __shared__ float As[BK][BM + 4];
    __shared__ float Bs[BK][128 + 4];
    int mblk = blockIdx.x * BM;
    int tid = threadIdx.x;
    int tx = tid % 16, ty = tid / 16;
    u64 acc[RM][4];
#pragma unroll
    for (int r = 0; r < RM; r++)
#pragma unroll
        for (int c = 0; c < 4; c++) acc[r][c] = 0ull;

    for (int k0 = 0; k0 < 128; k0 += BK) {
#pragma unroll
        for (int q = 0; q < BM / 32; q++) {
            int f = tid + q * 256;
            int m = f >> 3;
            int kk = (f & 7) * 4;
            const float* ap = A0 + (size_t)(mblk + m) * 128 + (k0 + kk);
            const float* dp = add + (size_t)(mblk + m) * 128 + (k0 + kk);
            const float* bp = biasA + (k0 + kk);
            float4 v;
            v.x = ap[0] + dp[0] + bp[0];
            v.y = ap[1] + dp[1] + bp[1];
            v.z = ap[2] + dp[2] + bp[2];
            v.w = ap[3] + dp[3] + bp[3];
            As[kk + 0][m] = v.x;
            As[kk + 1][m] = v.y;
            As[kk + 2][m] = v.z;
            As[kk + 3][m] = v.w;
        }
#pragma unroll
        for (int q = 0; q < 4; q++) {
            int f = tid + q * 256;
            int kk = f >> 5;
            int nn = (f & 31) * 4;
            *(float4*)&Bs[kk][nn] = *(const float4*)(B0 + (size_t)(k0 + kk) * 128 + nn);
        }
        __syncthreads();
#pragma unroll 8
        for (int kk = 0; kk < BK; kk++) {
            u64 as_[RM];
            float4 av = *(const float4*)&As[kk][ty * RM];
            as_[0] = splat2(av.x);
            as_[1] = splat2(av.y);
            as_[2] = splat2(av.z);
            as_[3] = splat2(av.w);
            ulonglong2 b0 = *(const ulonglong2*)&Bs[kk][tx * 4];
            ulonglong2 b1 = *(const ulonglong2*)&Bs[kk][64 + tx * 4];
            u64 bs_[4] = {b0.x, b0.y, b1.x, b1.y};
#pragma unroll
            for (int r = 0; r < RM; r++)
#pragma unroll
                for (int c = 0; c < 4; c++) acc[r][c] = fma2(as_[r], bs_[c], acc[r][c]);
        }
        __syncthreads();
    }
#pragma unroll
    for (int r = 0; r < RM; r++) {
        int gm = mblk + ty * RM + r;
        float* crow = C0 + (size_t)gm * 128;
        float2 p0 = unpack2(acc[r][0]);
        float2 p1 = unpack2(acc[r][1]);
        float2 p2 = unpack2(acc[r][2]);
        float2 p3 = unpack2(acc[r][3]);
        float v[8] = {p0.x, p0.y, p1.x, p1.y, p2.x, p2.y, p3.x, p3.y};
#pragma unroll
        for (int c = 0; c < 4; c++) {
            v[c] = v[c] + biasC[tx * 4 + c];
            v[c] = v[c] > 0.f ? v[c] : 0.f;
            v[c + 4] = v[c + 4] + biasC[64 + tx * 4 + c];
            v[c + 4] = v[c + 4] > 0.f ? v[c + 4] : 0.f;
        }
        *(float4*)&crow[tx * 4] = make_float4(v[0], v[1], v[2], v[3]);
        *(float4*)&crow[64 + tx * 4] = make_float4(v[4], v[5], v[6], v[7]);
    }
}

// ---------------- launch ------------------------------------------------------
extern "C" void kernel_launch(void* const* d_in, const int* in_sizes, int n_in,
                              void* d_out, int out_size) {
    (void)in_sizes; (void)n_in; (void)out_size;
    const float* inputs = (const float*)d_in[0];
    const int* adj = (const int*)d_in[1];
    const float* W_att = (const float*)d_in[3];
    const float* a_src = (const float*)d_in[4];
    const float* a_dst = (const float*)d_in[5];
    const float* W_out = (const float*)d_in[6];
    const float* ao_src = (const float*)d_in[7];
    const float* ao_dst = (const float*)d_in[8];
    const float* lin_w = (const float*)d_in[9];
    const float* lin_b = (const float*)d_in[10];
    const float* ln_w = (const float*)d_in[11];
    const float* ln_b = (const float*)d_in[12];

    __half *p_in16, *p_wattT, *p_h1T, *p_x1, *p_woutT, *p_linw16, *p_h2T;
    float *p_linp, *p_att2, *p_s1, *p_s2, *p_s1b, *p_s2b, *p_ln_wT;
    unsigned* p_mask;
    cudaGetSymbolAddress((void**)&p_in16, g_in16);
    cudaGetSymbolAddress((void**)&p_wattT, g_wattT);
    cudaGetSymbolAddress((void**)&p_h1T, g_h1T);
    cudaGetSymbolAddress((void**)&p_x1, g_x1);
    cudaGetSymbolAddress((void**)&p_woutT, g_woutT);
    cudaGetSymbolAddress((void**)&p_linw16, g_linw16);
    cudaGetSymbolAddress((void**)&p_h2T, g_h2T);
    cudaGetSymbolAddress((void**)&p_linp, g_linp);
    cudaGetSymbolAddress((void**)&p_att2, g_att2);
    cudaGetSymbolAddress((void**)&p_s1, g_s1);
    cudaGetSymbolAddress((void**)&p_s2, g_s2);
    cudaGetSymbolAddress((void**)&p_s1b, g_s1b);
    cudaGetSymbolAddress((void**)&p_s2b, g_s2b);
    cudaGetSymbolAddress((void**)&p_ln_wT, g_ln_wT);
    cudaGetSymbolAddress((void**)&p_mask, g_mask);

    const int AT0_SMEM = (2 * 128 * APAD + 2 * 128 * APAD) * 2 + (128 + 128 + 1024) * 4;
    const int AT1_SMEM = (2 * 64 * APAD + 2 * 128 * APAD) * 2 + (64 + 64 + 1024) * 4;
    const int TG0_SMEM = 2 * (128 + 128) * 72 * 2;   // 73728
    const int TG1_SMEM = 2 * (128 + 64) * 72 * 2;    // 55296
    const int TG2_SMEM = 2 * (64 + 128) * 72 * 2;    // 55296
    cudaFuncSetAttribute(at_k<0>, cudaFuncAttributeMaxDynamicSharedMemorySize,
                         AT0_SMEM);
    cudaFuncSetAttribute(at_k<1>, cudaFuncAttributeMaxDynamicSharedMemorySize,
                         AT1_SMEM);
    cudaFuncSetAttribute(tg_k<0>, cudaFuncAttributeMaxDynamicSharedMemorySize,
                         TG0_SMEM);
    cudaFuncSetAttribute(tg_k<1>, cudaFuncAttributeMaxDynamicSharedMemorySize,
                         TG1_SMEM);
    cudaFuncSetAttribute(tg_k<2>, cudaFuncAttributeMaxDynamicSharedMemorySize,
                         TG2_SMEM);

    mega_prep_k<<<4624, 256>>>(adj, p_mask, inputs, p_in16, W_att, p_wattT,
                               W_out, p_woutT, ln_w, p_ln_wT, lin_w,
                               p_linw16);                                    // 0
    tg_k<0><<<dim3(8, 1, 64), 256, TG0_SMEM>>>(p_wattT, p_in16, p_h1T,
                                               a_src, a_dst, p_s1, p_s2);    // 1
    at_k<0><<<dim3(8, 1, 64), 256, AT0_SMEM>>>(p_h1T, p_s1, p_s2, p_mask,
                                               p_x1);                        // 2
    tg_k<1><<<dim3(16, 1, 8), 256, TG1_SMEM>>>(p_woutT, p_x1, p_h2T,
                                               ao_src, ao_dst, p_s1b, p_s2b); // 3
    tg_k<2><<<dim3(128, 1, 1), 256, TG2_SMEM>>>(p_x1, p_linw16, p_linp,
                                                nullptr, nullptr, nullptr,
                                                nullptr);                    // 4
    at_k<1><<<dim3(16, 1, 8), 256, AT1_SMEM>>>(p_h2T, p_s1b, p_s2b, p_mask,
                                               p_att2);                      // 5
    final_k<<<128, 256>>>(p_linp, p_ln_wT, (float*)d_out, p_att2, lin_b, ln_b); // 6
}